// round 2
// baseline (speedup 1.0000x reference)
#include <cuda_runtime.h>
#include <cstring>
#include <cstdint>

typedef unsigned long long ull;

// ---------------- f32x2 packed helpers ----------------
static __device__ __forceinline__ ull pack2(float lo, float hi) {
    float2 t = make_float2(lo, hi);
    ull r; memcpy(&r, &t, 8); return r;
}
static __device__ __forceinline__ float2 unpack2(ull v) {
    float2 t; memcpy(&t, &v, 8); return t;
}
static __device__ __forceinline__ void fma2(ull& d, ull a, ull b, ull c) {
    asm("fma.rn.f32x2 %0, %1, %2, %3;" : "=l"(d) : "l"(a), "l"(b), "l"(c));
}

// ---------------- problem constants ----------------
#define NB 8
#define HH 64
#define WW 64
#define NN (HH*WW)          // 4096
#define VAIN 256
#define VBIN 128
#define VCIN 64
#define VOUT 128

// ---------------- scratch (device globals; no allocs) ----------------
__device__ float g_ha   [(size_t)NB*NN*128];          // relu(W_a1 @ xa), channel-last
__device__ float g_emba [(size_t)NB*NN*128];
__device__ float g_gateb[(size_t)NB*NN*128];
__device__ float g_gatec[(size_t)NB*NN*128];
__device__ float g_hb   [(size_t)NB*16384*128];
__device__ float g_embb [(size_t)NB*16384*128];
__device__ float g_hc   [(size_t)NB*65536*128];
__device__ float g_embc [(size_t)NB*65536*128];
__device__ float g_agg  [(size_t)NB*NN*384];
__device__ float g_y    [(size_t)NB*NN*256];

// ---------------- generic tiled GEMM ----------------
// out[b][m][o] = act( sum_k X[...] * W[o][k] )
// XL==0: X is [B][K][M] (channel-major, e.g. vert_* inputs)
// XL==1: X is [B][M][K] (channel-last intermediates)
// ACT: 0=none, 1=relu, 2=(1-sigmoid)
// OUTCM: write out as [B][O][M] (channel-major) via smem transpose
constexpr int MT = 128, OT = 64, KT = 32;

template<int XL, int ACT, bool OUTCM>
__global__ __launch_bounds__(256)
void gemm_k(const float* __restrict__ X, const float* __restrict__ W,
            float* __restrict__ out, int M, int K, int O)
{
    constexpr int XROW = MT + 4;   // 132 floats/row (16B aligned rows)
    constexpr int WROW = OT + 4;   // 68
    constexpr int SM_MAIN = KT*XROW + KT*WROW;              // 6400 floats
    constexpr int SM_T    = OUTCM ? MT*(OT+1) : 0;          // 8320 floats
    constexpr int SMS     = (SM_T > SM_MAIN) ? SM_T : SM_MAIN;
    __shared__ __align__(16) float sm[SMS];
    float (*Xt)[XROW] = (float(*)[XROW])sm;
    float (*Wt)[WROW] = (float(*)[WROW])(sm + KT*XROW);

    const int tid = threadIdx.x;
    const int tx  = tid & 15;    // o dimension (4 cols each)
    const int ty  = tid >> 4;    // m dimension (8 rows each)
    const int b   = blockIdx.z;
    const int m0  = blockIdx.x * MT;
    const int o0  = blockIdx.y * OT;

    const float* Xb = X + (size_t)b * (size_t)M * (size_t)K;

    ull acc[8][2];
    #pragma unroll
    for (int i = 0; i < 8; i++) { acc[i][0] = 0ull; acc[i][1] = 0ull; }

    for (int k0 = 0; k0 < K; k0 += KT) {
        // ---- load X tile -> Xt[kk][mm] ----
        if (XL == 0) {
            int kk = tid >> 3;            // 0..31
            int mm = (tid & 7) << 4;      // 0,16,..,112
            const float4* src = (const float4*)(Xb + (size_t)(k0 + kk) * M + (m0 + mm));
            float4 v0 = src[0], v1 = src[1], v2 = src[2], v3 = src[3];
            *(float4*)&Xt[kk][mm+ 0] = v0;
            *(float4*)&Xt[kk][mm+ 4] = v1;
            *(float4*)&Xt[kk][mm+ 8] = v2;
            *(float4*)&Xt[kk][mm+12] = v3;
        } else {
            int mm  = tid >> 1;           // 0..127
            int kk0 = (tid & 1) << 4;     // 0 or 16
            const float4* src = (const float4*)(Xb + (size_t)(m0 + mm) * K + (k0 + kk0));
            #pragma unroll
            for (int q = 0; q < 4; q++) {
                float4 v = src[q];
                Xt[kk0 + q*4 + 0][mm] = v.x;
                Xt[kk0 + q*4 + 1][mm] = v.y;
                Xt[kk0 + q*4 + 2][mm] = v.z;
                Xt[kk0 + q*4 + 3][mm] = v.w;
            }
        }
        // ---- load W tile (W is [O][K] row-major) -> Wt[kk][oo] ----
        {
            int oo  = tid >> 2;           // 0..63
            int kk0 = (tid & 3) << 3;     // 0,8,16,24
            const float4* src = (const float4*)(W + (size_t)(o0 + oo) * K + (k0 + kk0));
            #pragma unroll
            for (int q = 0; q < 2; q++) {
                float4 v = src[q];
                Wt[kk0 + q*4 + 0][oo] = v.x;
                Wt[kk0 + q*4 + 1][oo] = v.y;
                Wt[kk0 + q*4 + 2][oo] = v.z;
                Wt[kk0 + q*4 + 3][oo] = v.w;
            }
        }
        __syncthreads();

        #pragma unroll
        for (int kk = 0; kk < KT; kk++) {
            const float4 a0 = *(const float4*)&Xt[kk][ty*8];
            const float4 a1 = *(const float4*)&Xt[kk][ty*8 + 4];
            const ull bp0 = *(const ull*)&Wt[kk][tx*4];
            const ull bp1 = *(const ull*)&Wt[kk][tx*4 + 2];
            ull ad;
            ad = pack2(a0.x, a0.x); fma2(acc[0][0], ad, bp0, acc[0][0]); fma2(acc[0][1], ad, bp1, acc[0][1]);
            ad = pack2(a0.y, a0.y); fma2(acc[1][0], ad, bp0, acc[1][0]); fma2(acc[1][1], ad, bp1, acc[1][1]);
            ad = pack2(a0.z, a0.z); fma2(acc[2][0], ad, bp0, acc[2][0]); fma2(acc[2][1], ad, bp1, acc[2][1]);
            ad = pack2(a0.w, a0.w); fma2(acc[3][0], ad, bp0, acc[3][0]); fma2(acc[3][1], ad, bp1, acc[3][1]);
            ad = pack2(a1.x, a1.x); fma2(acc[4][0], ad, bp0, acc[4][0]); fma2(acc[4][1], ad, bp1, acc[4][1]);
            ad = pack2(a1.y, a1.y); fma2(acc[5][0], ad, bp0, acc[5][0]); fma2(acc[5][1], ad, bp1, acc[5][1]);
            ad = pack2(a1.z, a1.z); fma2(acc[6][0], ad, bp0, acc[6][0]); fma2(acc[6][1], ad, bp1, acc[6][1]);
            ad = pack2(a1.w, a1.w); fma2(acc[7][0], ad, bp0, acc[7][0]); fma2(acc[7][1], ad, bp1, acc[7][1]);
        }
        __syncthreads();
    }

    // ---- epilogue ----
    float c[8][4];
    #pragma unroll
    for (int i = 0; i < 8; i++) {
        float2 lo = unpack2(acc[i][0]);
        float2 hi = unpack2(acc[i][1]);
        c[i][0] = lo.x; c[i][1] = lo.y; c[i][2] = hi.x; c[i][3] = hi.y;
    }
    #pragma unroll
    for (int i = 0; i < 8; i++)
        #pragma unroll
        for (int j = 0; j < 4; j++) {
            if (ACT == 1) c[i][j] = fmaxf(c[i][j], 0.0f);
            else if (ACT == 2) c[i][j] = 1.0f / (1.0f + __expf(c[i][j]));   // 1 - sigmoid(v)
        }

    if (!OUTCM) {
        #pragma unroll
        for (int i = 0; i < 8; i++) {
            float4 v = make_float4(c[i][0], c[i][1], c[i][2], c[i][3]);
            *(float4*)(out + ((size_t)b * M + (m0 + ty*8 + i)) * (size_t)O + o0 + tx*4) = v;
        }
    } else {
        float (*T)[OT + 1] = (float(*)[OT + 1])sm;
        #pragma unroll
        for (int i = 0; i < 8; i++)
            #pragma unroll
            for (int j = 0; j < 4; j++)
                T[ty*8 + i][tx*4 + j] = c[i][j];
        __syncthreads();
        int ol = tid >> 2;              // 0..63
        int mb = (tid & 3) << 5;        // 0,32,64,96
        float* ob = out + ((size_t)b * O + o0 + ol) * (size_t)M + m0 + mb;
        #pragma unroll
        for (int q = 0; q < 8; q++) {
            float4 v = make_float4(T[mb + q*4 + 0][ol], T[mb + q*4 + 1][ol],
                                   T[mb + q*4 + 2][ol], T[mb + q*4 + 3][ol]);
            *(float4*)(ob + q*4) = v;
        }
    }
}

// ---------------- attention (warp per pixel) ----------------
static __device__ __forceinline__ float wsum(float v) {
    #pragma unroll
    for (int o = 16; o > 0; o >>= 1) v += __shfl_xor_sync(0xffffffffu, v, o);
    return v;
}
static __device__ __forceinline__ float sigm(float x) {
    return 1.0f / (1.0f + __expf(-x));
}

__global__ __launch_bounds__(128)
void attend_k(const float* __restrict__ emba, const float* __restrict__ gateb,
              const float* __restrict__ gatec, const float* __restrict__ embb,
              const float* __restrict__ embc, const float* __restrict__ Wab,
              const float* __restrict__ Wac, float* __restrict__ agg)
{
    int gw   = (blockIdx.x * 128 + threadIdx.x) >> 5;   // 0..32767
    int lane = threadIdx.x & 31;
    int b = gw >> 12, n = gw & 4095;
    int h = n >> 6, w = n & 63;
    size_t nb = (size_t)b * NN + n;

    const float* eap = emba + nb * 128;
    float ea[4], gb[4], gc[4];
    float pab = 0.f, pac = 0.f;
    #pragma unroll
    for (int j = 0; j < 4; j++) {
        int cc = lane + 32*j;
        ea[j] = eap[cc];
        gb[j] = gateb[nb*128 + cc];
        gc[j] = gatec[nb*128 + cc];
        pab += Wab[cc] * ea[j];
        pac += Wac[cc] * ea[j];
    }
    float dab = wsum(pab);
    float dac = wsum(pac);

    float* ag = agg + nb * 384;

    // ---- B branch: 4 patches ----
    {
        float eb[4][4], lb[4];
        #pragma unroll
        for (int p = 0; p < 4; p++) {
            int kh = p >> 1, kw = p & 1;
            const float* ep = embb + ((size_t)b*16384 + (size_t)(2*h + kh)*128 + (2*w + kw)) * 128;
            float s = 0.f;
            #pragma unroll
            for (int j = 0; j < 4; j++) {
                int cc = lane + 32*j;
                eb[p][j] = ep[cc];
                s += Wab[128 + cc] * eb[p][j];
            }
            lb[p] = fmaxf(dab + wsum(s), 0.0f);
        }
        float mx = fmaxf(fmaxf(lb[0], lb[1]), fmaxf(lb[2], lb[3]));
        float ssum = 0.f;
        #pragma unroll
        for (int p = 0; p < 4; p++) { lb[p] = __expf(lb[p] - mx); ssum += lb[p]; }
        float inv = 1.0f / ssum;
        #pragma unroll
        for (int j = 0; j < 4; j++) {
            float a = 0.f;
            #pragma unroll
            for (int p = 0; p < 4; p++) a += eb[p][j] * lb[p];
            a *= inv * gb[j];
            ag[lane + 32*j] = sigm(a);
        }
    }

    // ---- C branch: 16 patches ----
    {
        float ec[16][4], lc[16];
        #pragma unroll
        for (int p = 0; p < 16; p++) {
            int kh = p >> 2, kw = p & 3;
            const float* ep = embc + ((size_t)b*65536 + (size_t)(4*h + kh)*256 + (4*w + kw)) * 128;
            float s = 0.f;
            #pragma unroll
            for (int j = 0; j < 4; j++) {
                int cc = lane + 32*j;
                ec[p][j] = ep[cc];
                s += Wac[128 + cc] * ec[p][j];
            }
            lc[p] = fmaxf(dac + wsum(s), 0.0f);
        }
        float mx = lc[0];
        #pragma unroll
        for (int p = 1; p < 16; p++) mx = fmaxf(mx, lc[p]);
        float ssum = 0.f;
        #pragma unroll
        for (int p = 0; p < 16; p++) { lc[p] = __expf(lc[p] - mx); ssum += lc[p]; }
        float inv = 1.0f / ssum;
        #pragma unroll
        for (int j = 0; j < 4; j++) {
            float a = 0.f;
            #pragma unroll
            for (int p = 0; p < 16; p++) a += ec[p][j] * lc[p];
            a *= inv * gc[j];
            ag[128 + lane + 32*j] = sigm(a);
        }
    }

    // ---- emb_a passthrough (sigmoid) ----
    #pragma unroll
    for (int j = 0; j < 4; j++)
        ag[256 + lane + 32*j] = sigm(ea[j]);
}

// ---------------- launch ----------------
extern "C" void kernel_launch(void* const* d_in, const int* in_sizes, int n_in,
                              void* d_out, int out_size)
{
    const float* va   = (const float*)d_in[0];
    const float* vb   = (const float*)d_in[1];
    const float* vc   = (const float*)d_in[2];
    const float* Wa1  = (const float*)d_in[3];
    const float* Wa2  = (const float*)d_in[4];
    const float* Wgb  = (const float*)d_in[5];
    const float* Wgc  = (const float*)d_in[6];
    const float* Wb1  = (const float*)d_in[7];
    const float* Wb2  = (const float*)d_in[8];
    const float* Wc1  = (const float*)d_in[9];
    const float* Wc2  = (const float*)d_in[10];
    const float* Wab  = (const float*)d_in[11];
    const float* Wac  = (const float*)d_in[12];
    const float* Wr1  = (const float*)d_in[13];
    const float* Wr2  = (const float*)d_in[14];
    float* out = (float*)d_out;

    float *ha, *emba, *gateb, *gatec, *hb, *embb, *hc, *embc, *agg, *yb;
    cudaGetSymbolAddress((void**)&ha,    g_ha);
    cudaGetSymbolAddress((void**)&emba,  g_emba);
    cudaGetSymbolAddress((void**)&gateb, g_gateb);
    cudaGetSymbolAddress((void**)&gatec, g_gatec);
    cudaGetSymbolAddress((void**)&hb,    g_hb);
    cudaGetSymbolAddress((void**)&embb,  g_embb);
    cudaGetSymbolAddress((void**)&hc,    g_hc);
    cudaGetSymbolAddress((void**)&embc,  g_embc);
    cudaGetSymbolAddress((void**)&agg,   g_agg);
    cudaGetSymbolAddress((void**)&yb,    g_y);

    dim3 blk(256);
    // emb_a stage
    gemm_k<0,1,false><<<dim3(4096/MT, 128/OT, NB), blk>>>(va, Wa1, ha,    4096, 256, 128);
    gemm_k<0,2,false><<<dim3(4096/MT, 128/OT, NB), blk>>>(va, Wgb, gateb, 4096, 256, 128);
    gemm_k<0,2,false><<<dim3(4096/MT, 128/OT, NB), blk>>>(va, Wgc, gatec, 4096, 256, 128);
    gemm_k<1,0,false><<<dim3(4096/MT, 128/OT, NB), blk>>>(ha, Wa2, emba,  4096, 128, 128);
    // emb_b stage
    gemm_k<0,1,false><<<dim3(16384/MT, 128/OT, NB), blk>>>(vb, Wb1, hb,   16384, 128, 128);
    gemm_k<1,0,false><<<dim3(16384/MT, 128/OT, NB), blk>>>(hb, Wb2, embb, 16384, 128, 128);
    // emb_c stage
    gemm_k<0,1,false><<<dim3(65536/MT, 128/OT, NB), blk>>>(vc, Wc1, hc,   65536,  64, 128);
    gemm_k<1,0,false><<<dim3(65536/MT, 128/OT, NB), blk>>>(hc, Wc2, embc, 65536, 128, 128);
    // attention + gather + sigmoid -> agg [B][N][384]
    attend_k<<<8192, 128>>>(emba, gateb, gatec, embb, embc, Wab, Wac, agg);
    // readout
    gemm_k<1,1,false><<<dim3(4096/MT, 256/OT, NB), blk>>>(agg, Wr1, yb, 4096, 384, 256);
    gemm_k<1,0,true ><<<dim3(4096/MT, 256/OT, NB), blk>>>(yb, Wr2, out, 4096, 256, 256);
}

// round 4
// speedup vs baseline: 1.2133x; 1.2133x over previous
#include <cuda_runtime.h>
#include <cuda_bf16.h>
#include <cstdint>

using bf16 = __nv_bfloat16;
#define DIB __device__ __forceinline__

#define NB 8

// ================= scratch (device globals) =================
__device__ __align__(16) bf16 g_XAh[(size_t)NB*4096*256],  g_XAl[(size_t)NB*4096*256];
__device__ __align__(16) bf16 g_XBh[(size_t)NB*16384*128], g_XBl[(size_t)NB*16384*128];
__device__ __align__(16) bf16 g_XCh[(size_t)NB*65536*64],  g_XCl[(size_t)NB*65536*64];
__device__ __align__(16) bf16 g_hah[(size_t)NB*4096*128],  g_hal[(size_t)NB*4096*128];
__device__ __align__(16) bf16 g_eah[(size_t)NB*4096*128],  g_eal[(size_t)NB*4096*128];
__device__ __align__(16) float g_gb[(size_t)NB*4096*128],  g_gc[(size_t)NB*4096*128];
__device__ __align__(16) bf16 g_hbh[(size_t)NB*16384*128], g_hbl[(size_t)NB*16384*128];
__device__ __align__(16) bf16 g_ebh[(size_t)NB*16384*128], g_ebl[(size_t)NB*16384*128];
__device__ __align__(16) bf16 g_hch[(size_t)NB*65536*128], g_hcl[(size_t)NB*65536*128];
__device__ __align__(16) bf16 g_ech[(size_t)NB*65536*128], g_ecl[(size_t)NB*65536*128];
__device__ __align__(16) bf16 g_agh[(size_t)NB*4096*384],  g_agl[(size_t)NB*4096*384];
__device__ __align__(16) bf16 g_yh [(size_t)NB*4096*256],  g_yl [(size_t)NB*4096*256];
__device__ __align__(16) bf16 g_Wa1h[128*256], g_Wa1l[128*256];
__device__ __align__(16) bf16 g_Wgbh[128*256], g_Wgbl[128*256];
__device__ __align__(16) bf16 g_Wgch[128*256], g_Wgcl[128*256];
__device__ __align__(16) bf16 g_Wa2h[128*128], g_Wa2l[128*128];
__device__ __align__(16) bf16 g_Wb1h[128*128], g_Wb1l[128*128];
__device__ __align__(16) bf16 g_Wb2h[128*128], g_Wb2l[128*128];
__device__ __align__(16) bf16 g_Wc1h[128*64],  g_Wc1l[128*64];
__device__ __align__(16) bf16 g_Wc2h[128*128], g_Wc2l[128*128];
__device__ __align__(16) bf16 g_Wr1h[256*384], g_Wr1l[256*384];
__device__ __align__(16) bf16 g_Wr2h[256*256], g_Wr2l[256*256];

// ================= prep kernels =================
__global__ void wsplit_k(const float* __restrict__ w, bf16* __restrict__ h,
                         bf16* __restrict__ l, int n) {
    int i = blockIdx.x * 256 + threadIdx.x;
    if (i < n) {
        float v = w[i];
        bf16 hv = __float2bfloat16(v);
        h[i] = hv;
        l[i] = __float2bfloat16(v - __bfloat162float(hv));
    }
}

// src [B][C][M] fp32 -> dst hi/lo [B][M][C] bf16
__global__ __launch_bounds__(256)
void prep_x(const float* __restrict__ src, bf16* __restrict__ dh, bf16* __restrict__ dl,
            int C, int M) {
    __shared__ float s[32][33];
    int p0 = blockIdx.x * 32, c0 = blockIdx.y * 32, b = blockIdx.z;
    int tx = threadIdx.x & 31, ty = threadIdx.x >> 5;
    const float* sb = src + (size_t)b * C * M;
    #pragma unroll
    for (int i = 0; i < 4; i++)
        s[ty + 8*i][tx] = sb[(size_t)(c0 + ty + 8*i) * M + p0 + tx];
    __syncthreads();
    #pragma unroll
    for (int i = 0; i < 4; i++) {
        float v = s[tx][ty + 8*i];
        size_t o = ((size_t)b * M + p0 + ty + 8*i) * C + c0 + tx;
        bf16 hv = __float2bfloat16(v);
        dh[o] = hv;
        dl[o] = __float2bfloat16(v - __bfloat162float(hv));
    }
}

// ================= HMMA helpers =================
static DIB void mma16816(float* d, const uint32_t* a, const uint32_t* b) {
    asm volatile(
        "mma.sync.aligned.m16n8k16.row.col.f32.bf16.bf16.f32 "
        "{%0,%1,%2,%3}, {%4,%5,%6,%7}, {%8,%9}, {%0,%1,%2,%3};"
        : "+f"(d[0]), "+f"(d[1]), "+f"(d[2]), "+f"(d[3])
        : "r"(a[0]), "r"(a[1]), "r"(a[2]), "r"(a[3]), "r"(b[0]), "r"(b[1]));
}
static DIB uint32_t pk(bf16 lo, bf16 hi) {
    return (uint32_t)__bfloat16_as_ushort(lo) | ((uint32_t)__bfloat16_as_ushort(hi) << 16);
}

// ================= split-bf16 GEMM =================
// out[b][m][o] = act( sum_k X[m][k] * W[o][k] ), X/W given as hi/lo bf16 planes.
// ACT: 0 none, 1 relu, 2 (1-sigmoid)
// OUTM: 0 -> bf16 hi/lo planes [B][M][O]; 1 -> fp32 [B][M][O]; 2 -> fp32 [B][O][M]
template<int ACT, int OUTM>
__global__ __launch_bounds__(256)
void mmag_k(const bf16* __restrict__ Xh, const bf16* __restrict__ Xl,
            const bf16* __restrict__ Wh, const bf16* __restrict__ Wl,
            bf16* __restrict__ Oh, bf16* __restrict__ Ol, float* __restrict__ Of,
            int M, int K, int O)
{
    __shared__ __align__(16) bf16 Xsh[128][40], Xsl[128][40];
    __shared__ __align__(16) bf16 Wsh[128][40], Wsl[128][40];

    const int tid = threadIdx.x;
    const int warp = tid >> 5, lane = tid & 31;
    const int gid = lane >> 2, tq = (lane & 3) * 2;
    const int wm = (warp >> 1) * 32, wn = (warp & 1) * 64;
    const int b = blockIdx.z;
    const int m0 = blockIdx.x * 128, o0 = blockIdx.y * 128;

    float acc[2][8][4];
    #pragma unroll
    for (int mt = 0; mt < 2; mt++)
        #pragma unroll
        for (int nt = 0; nt < 8; nt++)
            #pragma unroll
            for (int q = 0; q < 4; q++) acc[mt][nt][q] = 0.f;

    const int r = tid >> 1, half = (tid & 1) * 16;
    const size_t xrow = ((size_t)b * M + m0 + r) * K;
    const size_t wrow = (size_t)(o0 + r) * K;

    for (int kc = 0; kc < K; kc += 32) {
        *(uint4*)&Xsh[r][half]     = *(const uint4*)(Xh + xrow + kc + half);
        *(uint4*)&Xsh[r][half + 8] = *(const uint4*)(Xh + xrow + kc + half + 8);
        *(uint4*)&Xsl[r][half]     = *(const uint4*)(Xl + xrow + kc + half);
        *(uint4*)&Xsl[r][half + 8] = *(const uint4*)(Xl + xrow + kc + half + 8);
        *(uint4*)&Wsh[r][half]     = *(const uint4*)(Wh + wrow + kc + half);
        *(uint4*)&Wsh[r][half + 8] = *(const uint4*)(Wh + wrow + kc + half + 8);
        *(uint4*)&Wsl[r][half]     = *(const uint4*)(Wl + wrow + kc + half);
        *(uint4*)&Wsl[r][half + 8] = *(const uint4*)(Wl + wrow + kc + half + 8);
        __syncthreads();

        #pragma unroll
        for (int ks = 0; ks < 32; ks += 16) {
            uint32_t Ah[2][4], Al[2][4];
            #pragma unroll
            for (int mt = 0; mt < 2; mt++) {
                int mr = wm + mt * 16;
                Ah[mt][0] = *(const uint32_t*)&Xsh[mr + gid    ][ks + tq];
                Ah[mt][1] = *(const uint32_t*)&Xsh[mr + gid + 8][ks + tq];
                Ah[mt][2] = *(const uint32_t*)&Xsh[mr + gid    ][ks + tq + 8];
                Ah[mt][3] = *(const uint32_t*)&Xsh[mr + gid + 8][ks + tq + 8];
                Al[mt][0] = *(const uint32_t*)&Xsl[mr + gid    ][ks + tq];
                Al[mt][1] = *(const uint32_t*)&Xsl[mr + gid + 8][ks + tq];
                Al[mt][2] = *(const uint32_t*)&Xsl[mr + gid    ][ks + tq + 8];
                Al[mt][3] = *(const uint32_t*)&Xsl[mr + gid + 8][ks + tq + 8];
            }
            #pragma unroll
            for (int nt = 0; nt < 8; nt++) {
                uint32_t Bh[2], Bl[2];
                int nr = wn + nt * 8 + gid;
                Bh[0] = *(const uint32_t*)&Wsh[nr][ks + tq];
                Bh[1] = *(const uint32_t*)&Wsh[nr][ks + tq + 8];
                Bl[0] = *(const uint32_t*)&Wsl[nr][ks + tq];
                Bl[1] = *(const uint32_t*)&Wsl[nr][ks + tq + 8];
                #pragma unroll
                for (int mt = 0; mt < 2; mt++) {
                    mma16816(acc[mt][nt], Ah[mt], Bh);
                    mma16816(acc[mt][nt], Ah[mt], Bl);
                    mma16816(acc[mt][nt], Al[mt], Bh);
                }
            }
        }
        __syncthreads();
    }

    // epilogue
    #pragma unroll
    for (int mt = 0; mt < 2; mt++) {
        #pragma unroll
        for (int h2 = 0; h2 < 2; h2++) {
            int m = m0 + wm + mt * 16 + gid + h2 * 8;
            #pragma unroll
            for (int nt = 0; nt < 8; nt++) {
                int oc = o0 + wn + nt * 8 + tq;
                float v0 = acc[mt][nt][h2 * 2], v1 = acc[mt][nt][h2 * 2 + 1];
                if (ACT == 1) { v0 = fmaxf(v0, 0.f); v1 = fmaxf(v1, 0.f); }
                else if (ACT == 2) {
                    v0 = 1.0f / (1.0f + __expf(v0));
                    v1 = 1.0f / (1.0f + __expf(v1));
                }
                if (OUTM == 0) {
                    bf16 h0 = __float2bfloat16(v0), h1 = __float2bfloat16(v1);
                    bf16 l0 = __float2bfloat16(v0 - __bfloat162float(h0));
                    bf16 l1 = __float2bfloat16(v1 - __bfloat162float(h1));
                    size_t go = ((size_t)b * M + m) * O + oc;
                    *(uint32_t*)(Oh + go) = pk(h0, h1);
                    *(uint32_t*)(Ol + go) = pk(l0, l1);
                } else if (OUTM == 1) {
                    *(float2*)(Of + ((size_t)b * M + m) * O + oc) = make_float2(v0, v1);
                } else {
                    Of[((size_t)b * O + oc)     * M + m] = v0;
                    Of[((size_t)b * O + oc + 1) * M + m] = v1;
                }
            }
        }
    }
}

// ================= attention =================
static DIB float wsum(float v) {
    #pragma unroll
    for (int o = 16; o > 0; o >>= 1) v += __shfl_xor_sync(0xffffffffu, v, o);
    return v;
}
static DIB float sigm(float x) { return 1.0f / (1.0f + __expf(-x)); }
static DIB float rd2(const bf16* h, const bf16* l, size_t i) {
    return __bfloat162float(h[i]) + __bfloat162float(l[i]);
}
static DIB void wr2(bf16* h, bf16* l, size_t i, float v) {
    bf16 x = __float2bfloat16(v);
    h[i] = x;
    l[i] = __float2bfloat16(v - __bfloat162float(x));
}

__global__ __launch_bounds__(128)
void attend_k(const bf16* __restrict__ eah, const bf16* __restrict__ eal,
              const float* __restrict__ gateb, const float* __restrict__ gatec,
              const bf16* __restrict__ ebh, const bf16* __restrict__ ebl,
              const bf16* __restrict__ ech, const bf16* __restrict__ ecl,
              const float* __restrict__ Wab, const float* __restrict__ Wac,
              bf16* __restrict__ agh, bf16* __restrict__ agl)
{
    int gw = (blockIdx.x * 128 + threadIdx.x) >> 5;
    int lane = threadIdx.x & 31;
    int b = gw >> 12, n = gw & 4095;
    int h = n >> 6, w = n & 63;
    size_t nb = (size_t)b * 4096 + n;

    float ea[4], gb[4], gc[4];
    float pab = 0.f, pac = 0.f;
    #pragma unroll
    for (int j = 0; j < 4; j++) {
        int cc = lane + 32 * j;
        ea[j] = rd2(eah, eal, nb * 128 + cc);
        gb[j] = gateb[nb * 128 + cc];
        gc[j] = gatec[nb * 128 + cc];
        pab += Wab[cc] * ea[j];
        pac += Wac[cc] * ea[j];
    }
    float dab = wsum(pab), dac = wsum(pac);

    { // B branch: 4 patches
        float eb[4][4], lb[4];
        #pragma unroll
        for (int p = 0; p < 4; p++) {
            int kh = p >> 1, kw = p & 1;
            size_t base = ((size_t)b * 16384 + (size_t)(2*h + kh) * 128 + (2*w + kw)) * 128;
            float s = 0.f;
            #pragma unroll
            for (int j = 0; j < 4; j++) {
                int cc = lane + 32 * j;
                eb[p][j] = rd2(ebh, ebl, base + cc);
                s += Wab[128 + cc] * eb[p][j];
            }
            lb[p] = fmaxf(dab + wsum(s), 0.0f);
        }
        float mx = fmaxf(fmaxf(lb[0], lb[1]), fmaxf(lb[2], lb[3]));
        float ss = 0.f;
        #pragma unroll
        for (int p = 0; p < 4; p++) { lb[p] = __expf(lb[p] - mx); ss += lb[p]; }
        float inv = 1.0f / ss;
        #pragma unroll
        for (int j = 0; j < 4; j++) {
            float a = 0.f;
            #pragma unroll
            for (int p = 0; p < 4; p++) a += eb[p][j] * lb[p];
            wr2(agh, agl, nb * 384 + lane + 32 * j, sigm(a * inv * gb[j]));
        }
    }
    { // C branch: 16 patches
        float ec[16][4], lc[16];
        #pragma unroll
        for (int p = 0; p < 16; p++) {
            int kh = p >> 2, kw = p & 3;
            size_t base = ((size_t)b * 65536 + (size_t)(4*h + kh) * 256 + (4*w + kw)) * 128;
            float s = 0.f;
            #pragma unroll
            for (int j = 0; j < 4; j++) {
                int cc = lane + 32 * j;
                ec[p][j] = rd2(ech, ecl, base + cc);
                s += Wac[128 + cc] * ec[p][j];
            }
            lc[p] = fmaxf(dac + wsum(s), 0.0f);
        }
        float mx = lc[0];
        #pragma unroll
        for (int p = 1; p < 16; p++) mx = fmaxf(mx, lc[p]);
        float ss = 0.f;
        #pragma unroll
        for (int p = 0; p < 16; p++) { lc[p] = __expf(lc[p] - mx); ss += lc[p]; }
        float inv = 1.0f / ss;
        #pragma unroll
        for (int j = 0; j < 4; j++) {
            float a = 0.f;
            #pragma unroll
            for (int p = 0; p < 16; p++) a += ec[p][j] * lc[p];
            wr2(agh, agl, nb * 384 + 128 + lane + 32 * j, sigm(a * inv * gc[j]));
        }
    }
    #pragma unroll
    for (int j = 0; j < 4; j++)
        wr2(agh, agl, nb * 384 + 256 + lane + 32 * j, sigm(ea[j]));
}

// ================= launch =================
extern "C" void kernel_launch(void* const* d_in, const int* in_sizes, int n_in,
                              void* d_out, int out_size)
{
    const float* va  = (const float*)d_in[0];
    const float* vb  = (const float*)d_in[1];
    const float* vc  = (const float*)d_in[2];
    const float* Wa1 = (const float*)d_in[3];
    const float* Wa2 = (const float*)d_in[4];
    const float* Wgb = (const float*)d_in[5];
    const float* Wgc = (const float*)d_in[6];
    const float* Wb1 = (const float*)d_in[7];
    const float* Wb2 = (const float*)d_in[8];
    const float* Wc1 = (const float*)d_in[9];
    const float* Wc2 = (const float*)d_in[10];
    const float* Wab = (const float*)d_in[11];
    const float* Wac = (const float*)d_in[12];
    const float* Wr1 = (const float*)d_in[13];
    const float* Wr2 = (const float*)d_in[14];
    float* out = (float*)d_out;

    bf16 *XAh,*XAl,*XBh,*XBl,*XCh,*XCl,*hah,*hal,*eah,*eal,*hbh,*hbl,*ebh,*ebl,
         *hch,*hcl,*ech,*ecl,*agh,*agl,*yh,*yl;
    float *gb,*gc;
    bf16 *Wa1h,*Wa1l,*Wgbh,*Wgbl,*Wgch,*Wgcl,*Wa2h,*Wa2l,*Wb1h,*Wb1l,*Wb2h,*Wb2l,
         *Wc1h,*Wc1l,*Wc2h,*Wc2l,*Wr1h,*Wr1l,*Wr2h,*Wr2l;
    cudaGetSymbolAddress((void**)&XAh,g_XAh); cudaGetSymbolAddress((void**)&XAl,g_XAl);
    cudaGetSymbolAddress((void**)&XBh,g_XBh); cudaGetSymbolAddress((void**)&XBl,g_XBl);
    cudaGetSymbolAddress((void**)&XCh,g_XCh); cudaGetSymbolAddress((void**)&XCl,g_XCl);
    cudaGetSymbolAddress((void**)&hah,g_hah); cudaGetSymbolAddress((void**)&hal,g_hal);
    cudaGetSymbolAddress((void**)&eah,g_eah); cudaGetSymbolAddress((void**)&eal,g_eal);
    cudaGetSymbolAddress((void**)&gb,g_gb);   cudaGetSymbolAddress((void**)&gc,g_gc);
    cudaGetSymbolAddress((void**)&hbh,g_hbh); cudaGetSymbolAddress((void**)&hbl,g_hbl);
    cudaGetSymbolAddress((void**)&ebh,g_ebh); cudaGetSymbolAddress((void**)&ebl,g_ebl);
    cudaGetSymbolAddress((void**)&hch,g_hch); cudaGetSymbolAddress((void**)&hcl,g_hcl);
    cudaGetSymbolAddress((void**)&ech,g_ech); cudaGetSymbolAddress((void**)&ecl,g_ecl);
    cudaGetSymbolAddress((void**)&agh,g_agh); cudaGetSymbolAddress((void**)&agl,g_agl);
    cudaGetSymbolAddress((void**)&yh,g_yh);   cudaGetSymbolAddress((void**)&yl,g_yl);
    cudaGetSymbolAddress((void**)&Wa1h,g_Wa1h); cudaGetSymbolAddress((void**)&Wa1l,g_Wa1l);
    cudaGetSymbolAddress((void**)&Wgbh,g_Wgbh); cudaGetSymbolAddress((void**)&Wgbl,g_Wgbl);
    cudaGetSymbolAddress((void**)&Wgch,g_Wgch); cudaGetSymbolAddress((void**)&Wgcl,g_Wgcl);
    cudaGetSymbolAddress((void**)&Wa2h,g_Wa2h); cudaGetSymbolAddress((void**)&Wa2l,g_Wa2l);
    cudaGetSymbolAddress((void**)&Wb1h,g_Wb1h); cudaGetSymbolAddress((void**)&Wb1l,g_Wb1l);
    cudaGetSymbolAddress((void**)&Wb2h,g_Wb2h); cudaGetSymbolAddress((void**)&Wb2l,g_Wb2l);
    cudaGetSymbolAddress((void**)&Wc1h,g_Wc1h); cudaGetSymbolAddress((void**)&Wc1l,g_Wc1l);
    cudaGetSymbolAddress((void**)&Wc2h,g_Wc2h); cudaGetSymbolAddress((void**)&Wc2l,g_Wc2l);
    cudaGetSymbolAddress((void**)&Wr1h,g_Wr1h); cudaGetSymbolAddress((void**)&Wr1l,g_Wr1l);
    cudaGetSymbolAddress((void**)&Wr2h,g_Wr2h); cudaGetSymbolAddress((void**)&Wr2l,g_Wr2l);

    auto ws = [&](const float* w, bf16* h, bf16* l, int n) {
        wsplit_k<<<(n + 255) / 256, 256>>>(w, h, l, n);
    };
    ws(Wa1, Wa1h, Wa1l, 128*256);
    ws(Wgb, Wgbh, Wgbl, 128*256);
    ws(Wgc, Wgch, Wgcl, 128*256);
    ws(Wa2, Wa2h, Wa2l, 128*128);
    ws(Wb1, Wb1h, Wb1l, 128*128);
    ws(Wb2, Wb2h, Wb2l, 128*128);
    ws(Wc1, Wc1h, Wc1l, 128*64);
    ws(Wc2, Wc2h, Wc2l, 128*128);
    ws(Wr1, Wr1h, Wr1l, 256*384);
    ws(Wr2, Wr2h, Wr2l, 256*256);

    prep_x<<<dim3(128, 8, NB), 256>>>(va, XAh, XAl, 256, 4096);
    prep_x<<<dim3(512, 4, NB), 256>>>(vb, XBh, XBl, 128, 16384);
    prep_x<<<dim3(2048, 2, NB), 256>>>(vc, XCh, XCl, 64, 65536);

    // a-stage
    mmag_k<1,0><<<dim3(32, 1, NB), 256>>>(XAh, XAl, Wa1h, Wa1l, hah, hal, nullptr, 4096, 256, 128);
    mmag_k<2,1><<<dim3(32, 1, NB), 256>>>(XAh, XAl, Wgbh, Wgbl, nullptr, nullptr, gb, 4096, 256, 128);
    mmag_k<2,1><<<dim3(32, 1, NB), 256>>>(XAh, XAl, Wgch, Wgcl, nullptr, nullptr, gc, 4096, 256, 128);
    mmag_k<0,0><<<dim3(32, 1, NB), 256>>>(hah, hal, Wa2h, Wa2l, eah, eal, nullptr, 4096, 128, 128);
    // b-stage
    mmag_k<1,0><<<dim3(128, 1, NB), 256>>>(XBh, XBl, Wb1h, Wb1l, hbh, hbl, nullptr, 16384, 128, 128);
    mmag_k<0,0><<<dim3(128, 1, NB), 256>>>(hbh, hbl, Wb2h, Wb2l, ebh, ebl, nullptr, 16384, 128, 128);
    // c-stage
    mmag_k<1,0><<<dim3(512, 1, NB), 256>>>(XCh, XCl, Wc1h, Wc1l, hch, hcl, nullptr, 65536, 64, 128);
    mmag_k<0,0><<<dim3(512, 1, NB), 256>>>(hch, hcl, Wc2h, Wc2l, ech, ecl, nullptr, 65536, 128, 128);
    // attention
    attend_k<<<8192, 128>>>(eah, eal, gb, gc, ebh, ebl, ech, ecl, Wab, Wac, agh, agl);
    // readout
    mmag_k<1,0><<<dim3(32, 2, NB), 256>>>(agh, agl, Wr1h, Wr1l, yh, yl, nullptr, 4096, 384, 256);
    mmag_k<0,2><<<dim3(32, 2, NB), 256>>>(yh, yl, Wr2h, Wr2l, nullptr, nullptr, out, 4096, 256, 256);
}

// round 5
// speedup vs baseline: 1.6206x; 1.3357x over previous
#include <cuda_runtime.h>
#include <cuda_bf16.h>
#include <cstdint>

using bf16 = __nv_bfloat16;
#define DIB __device__ __forceinline__
#define NB 8

// ================= scratch (device globals) =================
__device__ __align__(16) bf16 g_XAh[(size_t)NB*4096*256],  g_XAl[(size_t)NB*4096*256];
__device__ __align__(16) bf16 g_XBh[(size_t)NB*16384*128], g_XBl[(size_t)NB*16384*128];
__device__ __align__(16) bf16 g_XCh[(size_t)NB*65536*64],  g_XCl[(size_t)NB*65536*64];
__device__ __align__(16) bf16 g_hah[(size_t)NB*4096*128],  g_hal[(size_t)NB*4096*128];
__device__ __align__(16) bf16 g_eah[(size_t)NB*4096*128],  g_eal[(size_t)NB*4096*128];
__device__ __align__(16) float g_gb[(size_t)NB*4096*128],  g_gc[(size_t)NB*4096*128];
__device__ __align__(16) bf16 g_ebh[(size_t)NB*16384*128], g_ebl[(size_t)NB*16384*128];
__device__ __align__(16) bf16 g_ech[(size_t)NB*65536*128], g_ecl[(size_t)NB*65536*128];
__device__ __align__(16) bf16 g_agh[(size_t)NB*4096*384],  g_agl[(size_t)NB*4096*384];
__device__ __align__(16) bf16 g_Wa1h[128*256], g_Wa1l[128*256];
__device__ __align__(16) bf16 g_Wgbh[128*256], g_Wgbl[128*256];
__device__ __align__(16) bf16 g_Wgch[128*256], g_Wgcl[128*256];
__device__ __align__(16) bf16 g_Wa2h[128*128], g_Wa2l[128*128];
__device__ __align__(16) bf16 g_Wb1h[128*128], g_Wb1l[128*128];
__device__ __align__(16) bf16 g_Wb2h[128*128], g_Wb2l[128*128];
__device__ __align__(16) bf16 g_Wc1h[128*64],  g_Wc1l[128*64];
__device__ __align__(16) bf16 g_Wc2h[128*128], g_Wc2l[128*128];
__device__ __align__(16) bf16 g_Wr1h[256*384], g_Wr1l[256*384];
__device__ __align__(16) bf16 g_Wr2h[256*256], g_Wr2l[256*256];

// ================= small helpers =================
static DIB uint32_t smem_u32(const void* p) {
    uint32_t a;
    asm("{ .reg .u64 t; cvta.to.shared.u64 t, %1; cvt.u32.u64 %0, t; }" : "=r"(a) : "l"(p));
    return a;
}
static DIB void cpa16(uint32_t s, const void* g) {
    asm volatile("cp.async.ca.shared.global [%0],[%1],16;" :: "r"(s), "l"(g) : "memory");
}
#define CPA_COMMIT() asm volatile("cp.async.commit_group;" ::: "memory")
#define CPA_WAIT(N)  asm volatile("cp.async.wait_group " #N ";" ::: "memory")
static DIB void ldsm4(uint32_t* r, uint32_t a) {
    asm volatile("ldmatrix.sync.aligned.m8n8.x4.shared.b16 {%0,%1,%2,%3},[%4];"
        : "=r"(r[0]), "=r"(r[1]), "=r"(r[2]), "=r"(r[3]) : "r"(a));
}
static DIB void mma16816(float* d, const uint32_t* a, const uint32_t* b) {
    asm volatile(
        "mma.sync.aligned.m16n8k16.row.col.f32.bf16.bf16.f32 "
        "{%0,%1,%2,%3}, {%4,%5,%6,%7}, {%8,%9}, {%0,%1,%2,%3};"
        : "+f"(d[0]), "+f"(d[1]), "+f"(d[2]), "+f"(d[3])
        : "r"(a[0]), "r"(a[1]), "r"(a[2]), "r"(a[3]), "r"(b[0]), "r"(b[1]));
}
static DIB uint32_t pk(bf16 lo, bf16 hi) {
    return (uint32_t)__bfloat16_as_ushort(lo) | ((uint32_t)__bfloat16_as_ushort(hi) << 16);
}

// split-MMA chunk: acc += Ah*(Bh+Bl) + Al*Bh over CH_ k-elems
template<int STA, int STW, int CH_>
DIB void mma_block(float acc[2][8][4], uint32_t aH, uint32_t aL,
                   uint32_t bH, uint32_t bL, int aoff, int boff)
{
    #pragma unroll
    for (int ks = 0; ks < CH_; ks += 16) {
        uint32_t Ah[2][4], Al[2][4], Bh[4][4], Bl[4][4];
        #pragma unroll
        for (int mt = 0; mt < 2; mt++) {
            ldsm4(Ah[mt], aH + (uint32_t)(aoff + mt*16*STA + ks) * 2);
            ldsm4(Al[mt], aL + (uint32_t)(aoff + mt*16*STA + ks) * 2);
        }
        #pragma unroll
        for (int nb = 0; nb < 4; nb++) {
            ldsm4(Bh[nb], bH + (uint32_t)(boff + nb*16*STW + ks) * 2);
            ldsm4(Bl[nb], bL + (uint32_t)(boff + nb*16*STW + ks) * 2);
        }
        #pragma unroll
        for (int nt = 0; nt < 8; nt++) {
            uint32_t bh[2] = {Bh[nt>>1][(nt&1)*2], Bh[nt>>1][(nt&1)*2+1]};
            uint32_t bl[2] = {Bl[nt>>1][(nt&1)*2], Bl[nt>>1][(nt&1)*2+1]};
            #pragma unroll
            for (int mt = 0; mt < 2; mt++) {
                mma16816(acc[mt][nt], Ah[mt], bh);
                mma16816(acc[mt][nt], Ah[mt], bl);
                mma16816(acc[mt][nt], Al[mt], bh);
            }
        }
    }
}

// ================= fused 2-layer GEMM =================
// X[B][M][K1] (hi/lo bf16) -> relu(X.W1^T) -> h (smem, split) -> h.W2^T -> out
// OUTM 0: bf16 hi/lo planes [B][M][O2];  OUTM 2: fp32 [B][O2][M]
template<int K1, int O1, int O2, int BM, int CH, int OUTM>
__global__ __launch_bounds__(256, 1)
void fused2_k(const bf16* __restrict__ Xh, const bf16* __restrict__ Xl,
              const bf16* __restrict__ W1h, const bf16* __restrict__ W1l,
              const bf16* __restrict__ W2h, const bf16* __restrict__ W2l,
              bf16* __restrict__ Oh, bf16* __restrict__ Ol, float* __restrict__ Of,
              int Mtot)
{
    constexpr int XST = CH + 8, HST = O1 + 8;
    constexpr int WR  = (O1 > O2) ? O1 : O2;
    constexpr int XPL = BM * XST, WPL = WR * XST;
    constexpr int STAGE = 2 * (XPL + WPL);
    constexpr int HOFF = 2 * STAGE;
    constexpr int ROPS = CH / 8;
    constexpr int NC1 = K1 / CH, NC2 = O1 / CH;
    constexpr int WARPS_M = BM / 32, WARPS_N = 8 / WARPS_M;

    extern __shared__ bf16 smm[];
    const int tid = threadIdx.x, lane = tid & 31, warp = tid >> 5;
    const int gid = lane >> 2, tq = (lane & 3) * 2;
    const int wmi = warp / WARPS_N, wni = warp % WARPS_N;
    const int wm = wmi * 32, wn = wni * 64;
    const int b = blockIdx.z, m0 = blockIdx.x * BM;
    const uint32_t su = smem_u32(smm);

    const int aoffX = (wm + (lane & 7) + ((lane >> 3) & 1) * 8) * XST + (lane >> 4) * 8;
    const int aoffH = (wm + (lane & 7) + ((lane >> 3) & 1) * 8) * HST + (lane >> 4) * 8;
    const int boffX = (wn + (lane & 7) + (lane >> 4) * 8) * XST + ((lane >> 3) & 1) * 8;

    const bf16* Xhb = Xh + ((size_t)b * Mtot + m0) * K1;
    const bf16* Xlb = Xl + ((size_t)b * Mtot + m0) * K1;

    float acc[2][8][4];
    #pragma unroll
    for (int mt = 0; mt < 2; mt++)
        #pragma unroll
        for (int nt = 0; nt < 8; nt++)
            #pragma unroll
            for (int q = 0; q < 4; q++) acc[mt][nt][q] = 0.f;

    auto load1 = [&](int kc, int s) {
        uint32_t base = su + (uint32_t)(s * STAGE) * 2;
        #pragma unroll
        for (int i = tid; i < BM * ROPS; i += 256) {
            int r = i / ROPS, c = (i % ROPS) * 8;
            cpa16(base + (uint32_t)(r * XST + c) * 2,         Xhb + (size_t)r * K1 + kc + c);
            cpa16(base + (uint32_t)(XPL + r * XST + c) * 2,   Xlb + (size_t)r * K1 + kc + c);
        }
        #pragma unroll
        for (int i = tid; i < O1 * ROPS; i += 256) {
            int r = i / ROPS, c = (i % ROPS) * 8;
            cpa16(base + (uint32_t)(2*XPL + r * XST + c) * 2,       W1h + (size_t)r * K1 + kc + c);
            cpa16(base + (uint32_t)(2*XPL + WPL + r * XST + c) * 2, W1l + (size_t)r * K1 + kc + c);
        }
        CPA_COMMIT();
    };
    auto load2 = [&](int kc, int s) {
        uint32_t base = su + (uint32_t)(s * STAGE) * 2;
        #pragma unroll
        for (int i = tid; i < O2 * ROPS; i += 256) {
            int r = i / ROPS, c = (i % ROPS) * 8;
            cpa16(base + (uint32_t)(2*XPL + r * XST + c) * 2,       W2h + (size_t)r * O1 + kc + c);
            cpa16(base + (uint32_t)(2*XPL + WPL + r * XST + c) * 2, W2l + (size_t)r * O1 + kc + c);
        }
        CPA_COMMIT();
    };

    // ---------- GEMM1 ----------
    load1(0, 0);
    for (int ki = 0; ki < NC1; ki++) {
        if (ki + 1 < NC1) { load1((ki + 1) * CH, (ki + 1) & 1); CPA_WAIT(1); }
        else               { CPA_WAIT(0); }
        __syncthreads();
        uint32_t base = su + (uint32_t)((ki & 1) * STAGE) * 2;
        mma_block<XST, XST, CH>(acc, base, base + XPL * 2,
                                base + 2*XPL * 2, base + (2*XPL + WPL) * 2, aoffX, boffX);
        __syncthreads();
    }

    // prefetch first W2 chunk while we drain accumulators
    load2(0, 0);

    // ---------- relu + split -> h smem ----------
    #pragma unroll
    for (int mt = 0; mt < 2; mt++)
        #pragma unroll
        for (int h2 = 0; h2 < 2; h2++) {
            int ml = wm + mt * 16 + gid + h2 * 8;
            #pragma unroll
            for (int nt = 0; nt < 8; nt++) {
                int oc = wn + nt * 8 + tq;
                float v0 = fmaxf(acc[mt][nt][h2 * 2],     0.f);
                float v1 = fmaxf(acc[mt][nt][h2 * 2 + 1], 0.f);
                bf16 h0 = __float2bfloat16(v0), h1 = __float2bfloat16(v1);
                bf16 l0 = __float2bfloat16(v0 - __bfloat162float(h0));
                bf16 l1 = __float2bfloat16(v1 - __bfloat162float(h1));
                *(uint32_t*)&smm[HOFF + ml * HST + oc]            = pk(h0, h1);
                *(uint32_t*)&smm[HOFF + BM * HST + ml * HST + oc] = pk(l0, l1);
            }
        }
    __syncthreads();

    #pragma unroll
    for (int mt = 0; mt < 2; mt++)
        #pragma unroll
        for (int nt = 0; nt < 8; nt++)
            #pragma unroll
            for (int q = 0; q < 4; q++) acc[mt][nt][q] = 0.f;

    // ---------- GEMM2 ----------
    for (int ki = 0; ki < NC2; ki++) {
        if (ki + 1 < NC2) { load2((ki + 1) * CH, (ki + 1) & 1); CPA_WAIT(1); }
        else               { CPA_WAIT(0); }
        __syncthreads();
        uint32_t base = su + (uint32_t)((ki & 1) * STAGE) * 2;
        uint32_t ha = su + (uint32_t)HOFF * 2 + (uint32_t)(ki * CH) * 2;
        mma_block<HST, XST, CH>(acc, ha, ha + (uint32_t)(BM * HST) * 2,
                                base + 2*XPL * 2, base + (2*XPL + WPL) * 2, aoffH, boffX);
        __syncthreads();
    }

    // ---------- epilogue ----------
    #pragma unroll
    for (int mt = 0; mt < 2; mt++)
        #pragma unroll
        for (int h2 = 0; h2 < 2; h2++) {
            int m = m0 + wm + mt * 16 + gid + h2 * 8;
            #pragma unroll
            for (int nt = 0; nt < 8; nt++) {
                int oc = wn + nt * 8 + tq;
                float v0 = acc[mt][nt][h2 * 2], v1 = acc[mt][nt][h2 * 2 + 1];
                if (OUTM == 0) {
                    bf16 h0 = __float2bfloat16(v0), h1 = __float2bfloat16(v1);
                    bf16 l0 = __float2bfloat16(v0 - __bfloat162float(h0));
                    bf16 l1 = __float2bfloat16(v1 - __bfloat162float(h1));
                    size_t go = ((size_t)b * Mtot + m) * O2 + oc;
                    *(uint32_t*)(Oh + go) = pk(h0, h1);
                    *(uint32_t*)(Ol + go) = pk(l0, l1);
                } else {
                    Of[((size_t)b * O2 + oc)     * Mtot + m] = v0;
                    Of[((size_t)b * O2 + oc + 1) * Mtot + m] = v1;
                }
            }
        }
}

// ================= unfused GEMM (a-stage; proven R4 path) =================
template<int ACT, int OUTM>
__global__ __launch_bounds__(256)
void mmag_k(const bf16* __restrict__ Xh, const bf16* __restrict__ Xl,
            const bf16* __restrict__ Wh, const bf16* __restrict__ Wl,
            bf16* __restrict__ Oh, bf16* __restrict__ Ol, float* __restrict__ Of,
            int M, int K, int O)
{
    __shared__ __align__(16) bf16 Xsh[128][40], Xsl[128][40];
    __shared__ __align__(16) bf16 Wsh[128][40], Wsl[128][40];

    const int tid = threadIdx.x;
    const int warp = tid >> 5, lane = tid & 31;
    const int gid = lane >> 2, tq = (lane & 3) * 2;
    const int wm = (warp >> 1) * 32, wn = (warp & 1) * 64;
    const int b = blockIdx.z;
    const int m0 = blockIdx.x * 128, o0 = blockIdx.y * 128;

    float acc[2][8][4];
    #pragma unroll
    for (int mt = 0; mt < 2; mt++)
        #pragma unroll
        for (int nt = 0; nt < 8; nt++)
            #pragma unroll
            for (int q = 0; q < 4; q++) acc[mt][nt][q] = 0.f;

    const int r = tid >> 1, half = (tid & 1) * 16;
    const size_t xrow = ((size_t)b * M + m0 + r) * K;
    const size_t wrow = (size_t)(o0 + r) * K;

    for (int kc = 0; kc < K; kc += 32) {
        *(uint4*)&Xsh[r][half]     = *(const uint4*)(Xh + xrow + kc + half);
        *(uint4*)&Xsh[r][half + 8] = *(const uint4*)(Xh + xrow + kc + half + 8);
        *(uint4*)&Xsl[r][half]     = *(const uint4*)(Xl + xrow + kc + half);
        *(uint4*)&Xsl[r][half + 8] = *(const uint4*)(Xl + xrow + kc + half + 8);
        *(uint4*)&Wsh[r][half]     = *(const uint4*)(Wh + wrow + kc + half);
        *(uint4*)&Wsh[r][half + 8] = *(const uint4*)(Wh + wrow + kc + half + 8);
        *(uint4*)&Wsl[r][half]     = *(const uint4*)(Wl + wrow + kc + half);
        *(uint4*)&Wsl[r][half + 8] = *(const uint4*)(Wl + wrow + kc + half + 8);
        __syncthreads();

        #pragma unroll
        for (int ks = 0; ks < 32; ks += 16) {
            uint32_t Ah[2][4], Al[2][4];
            #pragma unroll
            for (int mt = 0; mt < 2; mt++) {
                int mr = wm + mt * 16;
                Ah[mt][0] = *(const uint32_t*)&Xsh[mr + gid    ][ks + tq];
                Ah[mt][1] = *(const uint32_t*)&Xsh[mr + gid + 8][ks + tq];
                Ah[mt][2] = *(const uint32_t*)&Xsh[mr + gid    ][ks + tq + 8];
                Ah[mt][3] = *(const uint32_t*)&Xsh[mr + gid + 8][ks + tq + 8];
                Al[mt][0] = *(const uint32_t*)&Xsl[mr + gid    ][ks + tq];
                Al[mt][1] = *(const uint32_t*)&Xsl[mr + gid + 8][ks + tq];
                Al[mt][2] = *(const uint32_t*)&Xsl[mr + gid    ][ks + tq + 8];
                Al[mt][3] = *(const uint32_t*)&Xsl[mr + gid + 8][ks + tq + 8];
            }
            #pragma unroll
            for (int nt = 0; nt < 8; nt++) {
                uint32_t Bh[2], Bl[2];
                int nr = wn + nt * 8 + gid;
                Bh[0] = *(const uint32_t*)&Wsh[nr][ks + tq];
                Bh[1] = *(const uint32_t*)&Wsh[nr][ks + tq + 8];
                Bl[0] = *(const uint32_t*)&Wsl[nr][ks + tq];
                Bl[1] = *(const uint32_t*)&Wsl[nr][ks + tq + 8];
                #pragma unroll
                for (int mt = 0; mt < 2; mt++) {
                    mma16816(acc[mt][nt], Ah[mt], Bh);
                    mma16816(acc[mt][nt], Ah[mt], Bl);
                    mma16816(acc[mt][nt], Al[mt], Bh);
                }
            }
        }
        __syncthreads();
    }

    #pragma unroll
    for (int mt = 0; mt < 2; mt++) {
        #pragma unroll
        for (int h2 = 0; h2 < 2; h2++) {
            int m = m0 + wm + mt * 16 + gid + h2 * 8;
            #pragma unroll
            for (int nt = 0; nt < 8; nt++) {
                int oc = o0 + wn + nt * 8 + tq;
                float v0 = acc[mt][nt][h2 * 2], v1 = acc[mt][nt][h2 * 2 + 1];
                if (ACT == 1) { v0 = fmaxf(v0, 0.f); v1 = fmaxf(v1, 0.f); }
                else if (ACT == 2) {
                    v0 = 1.0f / (1.0f + __expf(v0));
                    v1 = 1.0f / (1.0f + __expf(v1));
                }
                if (OUTM == 0) {
                    bf16 h0 = __float2bfloat16(v0), h1 = __float2bfloat16(v1);
                    bf16 l0 = __float2bfloat16(v0 - __bfloat162float(h0));
                    bf16 l1 = __float2bfloat16(v1 - __bfloat162float(h1));
                    size_t go = ((size_t)b * M + m) * O + oc;
                    *(uint32_t*)(Oh + go) = pk(h0, h1);
                    *(uint32_t*)(Ol + go) = pk(l0, l1);
                } else {
                    *(float2*)(Of + ((size_t)b * M + m) * O + oc) = make_float2(v0, v1);
                }
            }
        }
    }
}

// ================= prep kernels =================
__global__ void wsplit_k(const float* __restrict__ w, bf16* __restrict__ h,
                         bf16* __restrict__ l, int n) {
    int i = blockIdx.x * 256 + threadIdx.x;
    if (i < n) {
        float v = w[i];
        bf16 hv = __float2bfloat16(v);
        h[i] = hv;
        l[i] = __float2bfloat16(v - __bfloat162float(hv));
    }
}

__global__ __launch_bounds__(256)
void prep_x(const float* __restrict__ src, bf16* __restrict__ dh, bf16* __restrict__ dl,
            int C, int M) {
    __shared__ float s[32][33];
    int p0 = blockIdx.x * 32, c0 = blockIdx.y * 32, b = blockIdx.z;
    int tx = threadIdx.x & 31, ty = threadIdx.x >> 5;
    const float* sb = src + (size_t)b * C * M;
    #pragma unroll
    for (int i = 0; i < 4; i++)
        s[ty + 8*i][tx] = sb[(size_t)(c0 + ty + 8*i) * M + p0 + tx];
    __syncthreads();
    #pragma unroll
    for (int i = 0; i < 4; i++) {
        float v = s[tx][ty + 8*i];
        size_t o = ((size_t)b * M + p0 + ty + 8*i) * C + c0 + tx;
        bf16 hv = __float2bfloat16(v);
        dh[o] = hv;
        dl[o] = __float2bfloat16(v - __bfloat162float(hv));
    }
}

// ================= attention =================
static DIB float wsum(float v) {
    #pragma unroll
    for (int o = 16; o > 0; o >>= 1) v += __shfl_xor_sync(0xffffffffu, v, o);
    return v;
}
static DIB float sigm(float x) { return 1.0f / (1.0f + __expf(-x)); }
static DIB float rd2(const bf16* h, const bf16* l, size_t i) {
    return __bfloat162float(h[i]) + __bfloat162float(l[i]);
}
static DIB void wr2(bf16* h, bf16* l, size_t i, float v) {
    bf16 x = __float2bfloat16(v);
    h[i] = x;
    l[i] = __float2bfloat16(v - __bfloat162float(x));
}

__global__ __launch_bounds__(128)
void attend_k(const bf16* __restrict__ eah, const bf16* __restrict__ eal,
              const float* __restrict__ gateb, const float* __restrict__ gatec,
              const bf16* __restrict__ ebh, const bf16* __restrict__ ebl,
              const bf16* __restrict__ ech, const bf16* __restrict__ ecl,
              const float* __restrict__ Wab, const float* __restrict__ Wac,
              bf16* __restrict__ agh, bf16* __restrict__ agl)
{
    int gw = (blockIdx.x * 128 + threadIdx.x) >> 5;
    int lane = threadIdx.x & 31;
    int b = gw >> 12, n = gw & 4095;
    int h = n >> 6, w = n & 63;
    size_t nb = (size_t)b * 4096 + n;

    float ea[4], gb[4], gc[4];
    float pab = 0.f, pac = 0.f;
    #pragma unroll
    for (int j = 0; j < 4; j++) {
        int cc = lane + 32 * j;
        ea[j] = rd2(eah, eal, nb * 128 + cc);
        gb[j] = gateb[nb * 128 + cc];
        gc[j] = gatec[nb * 128 + cc];
        pab += Wab[cc] * ea[j];
        pac += Wac[cc] * ea[j];
    }
    float dab = wsum(pab), dac = wsum(pac);

    { // B branch
        float eb[4][4], lb[4];
        #pragma unroll
        for (int p = 0; p < 4; p++) {
            int kh = p >> 1, kw = p & 1;
            size_t base = ((size_t)b * 16384 + (size_t)(2*h + kh) * 128 + (2*w + kw)) * 128;
            float s = 0.f;
            #pragma unroll
            for (int j = 0; j < 4; j++) {
                int cc = lane + 32 * j;
                eb[p][j] = rd2(ebh, ebl, base + cc);
                s += Wab[128 + cc] * eb[p][j];
            }
            lb[p] = fmaxf(dab + wsum(s), 0.0f);
        }
        float mx = fmaxf(fmaxf(lb[0], lb[1]), fmaxf(lb[2], lb[3]));
        float ss = 0.f;
        #pragma unroll
        for (int p = 0; p < 4; p++) { lb[p] = __expf(lb[p] - mx); ss += lb[p]; }
        float inv = 1.0f / ss;
        #pragma unroll
        for (int j = 0; j < 4; j++) {
            float a = 0.f;
            #pragma unroll
            for (int p = 0; p < 4; p++) a += eb[p][j] * lb[p];
            wr2(agh, agl, nb * 384 + lane + 32 * j, sigm(a * inv * gb[j]));
        }
    }
    { // C branch
        float ec[16][4], lc[16];
        #pragma unroll
        for (int p = 0; p < 16; p++) {
            int kh = p >> 2, kw = p & 3;
            size_t base = ((size_t)b * 65536 + (size_t)(4*h + kh) * 256 + (4*w + kw)) * 128;
            float s = 0.f;
            #pragma unroll
            for (int j = 0; j < 4; j++) {
                int cc = lane + 32 * j;
                ec[p][j] = rd2(ech, ecl, base + cc);
                s += Wac[128 + cc] * ec[p][j];
            }
            lc[p] = fmaxf(dac + wsum(s), 0.0f);
        }
        float mx = lc[0];
        #pragma unroll
        for (int p = 1; p < 16; p++) mx = fmaxf(mx, lc[p]);
        float ss = 0.f;
        #pragma unroll
        for (int p = 0; p < 16; p++) { lc[p] = __expf(lc[p] - mx); ss += lc[p]; }
        float inv = 1.0f / ss;
        #pragma unroll
        for (int j = 0; j < 4; j++) {
            float a = 0.f;
            #pragma unroll
            for (int p = 0; p < 16; p++) a += ec[p][j] * lc[p];
            wr2(agh, agl, nb * 384 + 128 + lane + 32 * j, sigm(a * inv * gc[j]));
        }
    }
    #pragma unroll
    for (int j = 0; j < 4; j++)
        wr2(agh, agl, nb * 384 + 256 + lane + 32 * j, sigm(ea[j]));
}

// ================= launch =================
static inline int fsz(int O1, int O2, int BM, int CH) {
    int XST = CH + 8, WR = (O1 > O2) ? O1 : O2;
    int XPL = BM * XST, WPL = WR * XST;
    int STAGE = 2 * (XPL + WPL);
    return (2 * STAGE + 2 * BM * (O1 + 8)) * 2;   // bytes
}

extern "C" void kernel_launch(void* const* d_in, const int* in_sizes, int n_in,
                              void* d_out, int out_size)
{
    const float* va  = (const float*)d_in[0];
    const float* vb  = (const float*)d_in[1];
    const float* vc  = (const float*)d_in[2];
    const float* Wa1 = (const float*)d_in[3];
    const float* Wa2 = (const float*)d_in[4];
    const float* Wgb = (const float*)d_in[5];
    const float* Wgc = (const float*)d_in[6];
    const float* Wb1 = (const float*)d_in[7];
    const float* Wb2 = (const float*)d_in[8];
    const float* Wc1 = (const float*)d_in[9];
    const float* Wc2 = (const float*)d_in[10];
    const float* Wab = (const float*)d_in[11];
    const float* Wac = (const float*)d_in[12];
    const float* Wr1 = (const float*)d_in[13];
    const float* Wr2 = (const float*)d_in[14];
    float* out = (float*)d_out;

    bf16 *XAh,*XAl,*XBh,*XBl,*XCh,*XCl,*hah,*hal,*eah,*eal,*ebh,*ebl,*ech,*ecl,*agh,*agl;
    float *gb,*gc;
    bf16 *Wa1h,*Wa1l,*Wgbh,*Wgbl,*Wgch,*Wgcl,*Wa2h,*Wa2l,*Wb1h,*Wb1l,*Wb2h,*Wb2l,
         *Wc1h,*Wc1l,*Wc2h,*Wc2l,*Wr1h,*Wr1l,*Wr2h,*Wr2l;
    cudaGetSymbolAddress((void**)&XAh,g_XAh); cudaGetSymbolAddress((void**)&XAl,g_XAl);
    cudaGetSymbolAddress((void**)&XBh,g_XBh); cudaGetSymbolAddress((void**)&XBl,g_XBl);
    cudaGetSymbolAddress((void**)&XCh,g_XCh); cudaGetSymbolAddress((void**)&XCl,g_XCl);
    cudaGetSymbolAddress((void**)&hah,g_hah); cudaGetSymbolAddress((void**)&hal,g_hal);
    cudaGetSymbolAddress((void**)&eah,g_eah); cudaGetSymbolAddress((void**)&eal,g_eal);
    cudaGetSymbolAddress((void**)&gb,g_gb);   cudaGetSymbolAddress((void**)&gc,g_gc);
    cudaGetSymbolAddress((void**)&ebh,g_ebh); cudaGetSymbolAddress((void**)&ebl,g_ebl);
    cudaGetSymbolAddress((void**)&ech,g_ech); cudaGetSymbolAddress((void**)&ecl,g_ecl);
    cudaGetSymbolAddress((void**)&agh,g_agh); cudaGetSymbolAddress((void**)&agl,g_agl);
    cudaGetSymbolAddress((void**)&Wa1h,g_Wa1h); cudaGetSymbolAddress((void**)&Wa1l,g_Wa1l);
    cudaGetSymbolAddress((void**)&Wgbh,g_Wgbh); cudaGetSymbolAddress((void**)&Wgbl,g_Wgbl);
    cudaGetSymbolAddress((void**)&Wgch,g_Wgch); cudaGetSymbolAddress((void**)&Wgcl,g_Wgcl);
    cudaGetSymbolAddress((void**)&Wa2h,g_Wa2h); cudaGetSymbolAddress((void**)&Wa2l,g_Wa2l);
    cudaGetSymbolAddress((void**)&Wb1h,g_Wb1h); cudaGetSymbolAddress((void**)&Wb1l,g_Wb1l);
    cudaGetSymbolAddress((void**)&Wb2h,g_Wb2h); cudaGetSymbolAddress((void**)&Wb2l,g_Wb2l);
    cudaGetSymbolAddress((void**)&Wc1h,g_Wc1h); cudaGetSymbolAddress((void**)&Wc1l,g_Wc1l);
    cudaGetSymbolAddress((void**)&Wc2h,g_Wc2h); cudaGetSymbolAddress((void**)&Wc2l,g_Wc2l);
    cudaGetSymbolAddress((void**)&Wr1h,g_Wr1h); cudaGetSymbolAddress((void**)&Wr1l,g_Wr1l);
    cudaGetSymbolAddress((void**)&Wr2h,g_Wr2h); cudaGetSymbolAddress((void**)&Wr2l,g_Wr2l);

    auto ws = [&](const float* w, bf16* h, bf16* l, int n) {
        wsplit_k<<<(n + 255) / 256, 256>>>(w, h, l, n);
    };
    ws(Wa1, Wa1h, Wa1l, 128*256);
    ws(Wgb, Wgbh, Wgbl, 128*256);
    ws(Wgc, Wgch, Wgcl, 128*256);
    ws(Wa2, Wa2h, Wa2l, 128*128);
    ws(Wb1, Wb1h, Wb1l, 128*128);
    ws(Wb2, Wb2h, Wb2l, 128*128);
    ws(Wc1, Wc1h, Wc1l, 128*64);
    ws(Wc2, Wc2h, Wc2l, 128*128);
    ws(Wr1, Wr1h, Wr1l, 256*384);
    ws(Wr2, Wr2h, Wr2l, 256*256);

    prep_x<<<dim3(128, 8, NB), 256>>>(va, XAh, XAl, 256, 4096);
    prep_x<<<dim3(512, 4, NB), 256>>>(vb, XBh, XBl, 128, 16384);
    prep_x<<<dim3(2048, 2, NB), 256>>>(vc, XCh, XCl, 64, 65536);

    // a-stage (unfused, proven)
    mmag_k<1,0><<<dim3(32, 1, NB), 256>>>(XAh, XAl, Wa1h, Wa1l, hah, hal, nullptr, 4096, 256, 128);
    mmag_k<2,1><<<dim3(32, 1, NB), 256>>>(XAh, XAl, Wgbh, Wgbl, nullptr, nullptr, gb, 4096, 256, 128);
    mmag_k<2,1><<<dim3(32, 1, NB), 256>>>(XAh, XAl, Wgch, Wgcl, nullptr, nullptr, gc, 4096, 256, 128);
    mmag_k<0,0><<<dim3(32, 1, NB), 256>>>(hah, hal, Wa2h, Wa2l, eah, eal, nullptr, 4096, 128, 128);

    // fused b-, c-stage and readout
    int sB = fsz(128, 128, 128, 64);
    int sC = sB;
    int sR = fsz(256, 256, 64, 32);
    cudaFuncSetAttribute(fused2_k<128,128,128,128,64,0>, cudaFuncAttributeMaxDynamicSharedMemorySize, sB);
    cudaFuncSetAttribute(fused2_k< 64,128,128,128,64,0>, cudaFuncAttributeMaxDynamicSharedMemorySize, sC);
    cudaFuncSetAttribute(fused2_k<384,256,256, 64,32,2>, cudaFuncAttributeMaxDynamicSharedMemorySize, sR);

    fused2_k<128,128,128,128,64,0><<<dim3(128, 1, NB), 256, sB>>>(
        XBh, XBl, Wb1h, Wb1l, Wb2h, Wb2l, ebh, ebl, nullptr, 16384);
    fused2_k< 64,128,128,128,64,0><<<dim3(512, 1, NB), 256, sC>>>(
        XCh, XCl, Wc1h, Wc1l, Wc2h, Wc2l, ech, ecl, nullptr, 65536);

    attend_k<<<8192, 128>>>(eah, eal, gb, gc, ebh, ebl, ech, ecl, Wab, Wac, agh, agl);

    fused2_k<384,256,256,64,32,2><<<dim3(64, 1, NB), 256, sR>>>(
        agh, agl, Wr1h, Wr1l, Wr2h, Wr2l, nullptr, nullptr, out, 4096);
}

// round 6
// speedup vs baseline: 1.7264x; 1.0653x over previous
#include <cuda_runtime.h>
#include <cuda_bf16.h>
#include <cstdint>

using bf16 = __nv_bfloat16;
#define DIB __device__ __forceinline__
#define NB 8

// ================= scratch (device globals) =================
__device__ __align__(16) bf16 g_XAh[(size_t)NB*4096*256],  g_XAl[(size_t)NB*4096*256];
__device__ __align__(16) bf16 g_XBh[(size_t)NB*16384*128], g_XBl[(size_t)NB*16384*128];
__device__ __align__(16) bf16 g_XCh[(size_t)NB*65536*64],  g_XCl[(size_t)NB*65536*64];
__device__ __align__(16) bf16 g_eah[(size_t)NB*4096*128],  g_eal[(size_t)NB*4096*128];
__device__ __align__(16) float g_gb[(size_t)NB*4096*128],  g_gc[(size_t)NB*4096*128];
__device__ __align__(16) bf16 g_ebh[(size_t)NB*16384*128], g_ebl[(size_t)NB*16384*128];
__device__ __align__(16) bf16 g_ech[(size_t)NB*65536*128], g_ecl[(size_t)NB*65536*128];
__device__ __align__(16) bf16 g_agh[(size_t)NB*4096*384],  g_agl[(size_t)NB*4096*384];
__device__ __align__(16) bf16 g_WAh[384*256],  g_WAl[384*256];   // Wa1|Wgb|Wgc stacked
__device__ __align__(16) bf16 g_Wa2h[128*128], g_Wa2l[128*128];
__device__ __align__(16) bf16 g_Wb1h[128*128], g_Wb1l[128*128];
__device__ __align__(16) bf16 g_Wb2h[128*128], g_Wb2l[128*128];
__device__ __align__(16) bf16 g_Wc1h[128*64],  g_Wc1l[128*64];
__device__ __align__(16) bf16 g_Wc2h[128*128], g_Wc2l[128*128];
__device__ __align__(16) bf16 g_Wr1h[256*384], g_Wr1l[256*384];
__device__ __align__(16) bf16 g_Wr2h[256*256], g_Wr2l[256*256];

// ================= helpers =================
static DIB uint32_t smem_u32(const void* p) {
    uint32_t a;
    asm("{ .reg .u64 t; cvta.to.shared.u64 t, %1; cvt.u32.u64 %0, t; }" : "=r"(a) : "l"(p));
    return a;
}
static DIB void cpa16(uint32_t s, const void* g) {
    asm volatile("cp.async.ca.shared.global [%0],[%1],16;" :: "r"(s), "l"(g) : "memory");
}
#define CPA_COMMIT() asm volatile("cp.async.commit_group;" ::: "memory")
#define CPA_WAIT(N)  asm volatile("cp.async.wait_group " #N ";" ::: "memory")
static DIB void ldsm4(uint32_t* r, uint32_t a) {
    asm volatile("ldmatrix.sync.aligned.m8n8.x4.shared.b16 {%0,%1,%2,%3},[%4];"
        : "=r"(r[0]), "=r"(r[1]), "=r"(r[2]), "=r"(r[3]) : "r"(a));
}
static DIB void mma16816(float* d, const uint32_t* a, const uint32_t* b) {
    asm volatile(
        "mma.sync.aligned.m16n8k16.row.col.f32.bf16.bf16.f32 "
        "{%0,%1,%2,%3}, {%4,%5,%6,%7}, {%8,%9}, {%0,%1,%2,%3};"
        : "+f"(d[0]), "+f"(d[1]), "+f"(d[2]), "+f"(d[3])
        : "r"(a[0]), "r"(a[1]), "r"(a[2]), "r"(a[3]), "r"(b[0]), "r"(b[1]));
}
static DIB uint32_t pk(bf16 lo, bf16 hi) {
    return (uint32_t)__bfloat16_as_ushort(lo) | ((uint32_t)__bfloat16_as_ushort(hi) << 16);
}

// acc += Ah*(Bh+Bl) + Al*Bh over 32 k-elems. addresses are byte addrs at warp frag base.
template<int STA, int STB, int NT>
static DIB void mma_blk(float (&acc)[2][NT][4], uint32_t aH, uint32_t aL,
                        uint32_t bH, uint32_t bL)
{
    #pragma unroll
    for (int ks = 0; ks < 32; ks += 16) {
        uint32_t Ah[2][4], Al[2][4], Bh[NT/2][4], Bl[NT/2][4];
        #pragma unroll
        for (int mt = 0; mt < 2; mt++) {
            ldsm4(Ah[mt], aH + (uint32_t)(mt*16*STA + ks) * 2);
            ldsm4(Al[mt], aL + (uint32_t)(mt*16*STA + ks) * 2);
        }
        #pragma unroll
        for (int g = 0; g < NT/2; g++) {
            ldsm4(Bh[g], bH + (uint32_t)(g*16*STB + ks) * 2);
            ldsm4(Bl[g], bL + (uint32_t)(g*16*STB + ks) * 2);
        }
        #pragma unroll
        for (int nt = 0; nt < NT; nt++) {
            uint32_t bh[2] = {Bh[nt>>1][(nt&1)*2], Bh[nt>>1][(nt&1)*2+1]};
            uint32_t bl[2] = {Bl[nt>>1][(nt&1)*2], Bl[nt>>1][(nt&1)*2+1]};
            #pragma unroll
            for (int mt = 0; mt < 2; mt++) {
                mma16816(acc[mt][nt], Ah[mt], bh);
                mma16816(acc[mt][nt], Ah[mt], bl);
                mma16816(acc[mt][nt], Al[mt], bh);
            }
        }
    }
}

// ================= unified fused 2-layer GEMM =================
// GEMM1: D1[m][0..O1T) = X . W1^T;  cols < O1M -> relu -> split -> h(smem);
//        gate block g (128 cols)    -> 1-sigmoid -> gate{0,1} fp32 [B][M][128]
// GEMM2: D2 = h . W2^T -> OUTM 0: bf16 hi/lo [B][M][O2]; OUTM 2: fp32 [B][O2][M]
template<int K1, int O1M, int NG, int O2, int OCC, int OUTM>
__global__ __launch_bounds__(256, OCC)
void fuse_k(const bf16* __restrict__ Xh, const bf16* __restrict__ Xl,
            const bf16* __restrict__ W1h, const bf16* __restrict__ W1l,
            const bf16* __restrict__ W2h, const bf16* __restrict__ W2l,
            float* __restrict__ gate0, float* __restrict__ gate1,
            bf16* __restrict__ Oh, bf16* __restrict__ Ol, float* __restrict__ Of,
            int Mtot)
{
    constexpr int BM = 64, CH = 32, XST = 40;
    constexpr int O1T = O1M + NG * 128;
    constexpr int WR  = (O1T > O2) ? O1T : O2;
    constexpr int HST = O1M + 8;
    constexpr int XPL = BM * XST, WPL = WR * XST;
    constexpr int STAGE = 2 * XPL + 2 * WPL;
    constexpr int HOFF  = 2 * STAGE;
    constexpr int NC1 = K1 / CH, NC2 = O1M / CH;
    constexpr int NT1 = O1T / 32, NT2 = O2 / 32;

    extern __shared__ bf16 smm[];
    const int tid = threadIdx.x, lane = tid & 31, warp = tid >> 5;
    const int gid = lane >> 2, tq = (lane & 3) * 2;
    const int wm  = (warp >> 2) * 32;
    const int wn1 = (warp & 3) * (NT1 * 8);
    const int wn2 = (warp & 3) * (NT2 * 8);
    const int b = blockIdx.z, m0 = blockIdx.x * BM;
    const uint32_t su = smem_u32(smm);

    const int arow = (lane & 7) + ((lane >> 3) & 1) * 8;
    const int acol = (lane >> 4) * 8;
    const int brow = (lane & 7) + (lane >> 4) * 8;
    const int bcol = ((lane >> 3) & 1) * 8;

    const bf16* Xhb = Xh + ((size_t)b * Mtot + m0) * K1;
    const bf16* Xlb = Xl + ((size_t)b * Mtot + m0) * K1;

    auto load1 = [&](int kc, int s) {
        uint32_t base = su + (uint32_t)(s * STAGE) * 2;
        #pragma unroll
        for (int i = tid; i < BM * 4; i += 256) {
            int r = i >> 2, c = (i & 3) * 8;
            cpa16(base + (uint32_t)(r * XST + c) * 2,       Xhb + (size_t)r * K1 + kc + c);
            cpa16(base + (uint32_t)(XPL + r * XST + c) * 2, Xlb + (size_t)r * K1 + kc + c);
        }
        #pragma unroll
        for (int i = tid; i < O1T * 4; i += 256) {
            int r = i >> 2, c = (i & 3) * 8;
            cpa16(base + (uint32_t)(2*XPL + r * XST + c) * 2,       W1h + (size_t)r * K1 + kc + c);
            cpa16(base + (uint32_t)(2*XPL + WPL + r * XST + c) * 2, W1l + (size_t)r * K1 + kc + c);
        }
        CPA_COMMIT();
    };
    auto load2 = [&](int kc, int s) {
        uint32_t base = su + (uint32_t)(s * STAGE) * 2;
        #pragma unroll
        for (int i = tid; i < O2 * 4; i += 256) {
            int r = i >> 2, c = (i & 3) * 8;
            cpa16(base + (uint32_t)(2*XPL + r * XST + c) * 2,       W2h + (size_t)r * O1M + kc + c);
            cpa16(base + (uint32_t)(2*XPL + WPL + r * XST + c) * 2, W2l + (size_t)r * O1M + kc + c);
        }
        CPA_COMMIT();
    };

    // ---------------- GEMM1 ----------------
    float acc1[2][NT1][4];
    #pragma unroll
    for (int mt = 0; mt < 2; mt++)
        #pragma unroll
        for (int nt = 0; nt < NT1; nt++)
            #pragma unroll
            for (int q = 0; q < 4; q++) acc1[mt][nt][q] = 0.f;

    load1(0, 0);
    for (int ki = 0; ki < NC1; ki++) {
        if (ki + 1 < NC1) { load1((ki + 1) * CH, (ki + 1) & 1); CPA_WAIT(1); }
        else              { CPA_WAIT(0); }
        __syncthreads();
        uint32_t base = su + (uint32_t)((ki & 1) * STAGE) * 2;
        uint32_t aH = base + (uint32_t)((wm + arow) * XST + acol) * 2;
        uint32_t aL = aH + (uint32_t)XPL * 2;
        uint32_t bH = base + (uint32_t)(2*XPL + (wn1 + brow) * XST + bcol) * 2;
        uint32_t bL = bH + (uint32_t)WPL * 2;
        mma_blk<XST, XST, NT1>(acc1, aH, aL, bH, bL);
        __syncthreads();
    }

    load2(0, 0);   // prefetch first W2 chunk under the epilogue

    // ---------------- relu+split -> h smem; gates -> global ----------------
    #pragma unroll
    for (int mt = 0; mt < 2; mt++)
        #pragma unroll
        for (int h2 = 0; h2 < 2; h2++) {
            int ml = wm + mt * 16 + gid + h2 * 8;
            #pragma unroll
            for (int nt = 0; nt < NT1; nt++) {
                int oc = wn1 + nt * 8 + tq;
                float v0 = acc1[mt][nt][h2 * 2], v1 = acc1[mt][nt][h2 * 2 + 1];
                if (NG == 0 || oc < O1M) {
                    v0 = fmaxf(v0, 0.f); v1 = fmaxf(v1, 0.f);
                    bf16 h0 = __float2bfloat16(v0), h1 = __float2bfloat16(v1);
                    bf16 l0 = __float2bfloat16(v0 - __bfloat162float(h0));
                    bf16 l1 = __float2bfloat16(v1 - __bfloat162float(h1));
                    *(uint32_t*)&smm[HOFF + ml * HST + oc]            = pk(h0, h1);
                    *(uint32_t*)&smm[HOFF + BM * HST + ml * HST + oc] = pk(l0, l1);
                } else {
                    int g = (oc - O1M) >> 7;
                    float* gp = (g ? gate1 : gate0) + ((size_t)b * Mtot + m0 + ml) * 128 + (oc & 127);
                    *(float2*)gp = make_float2(1.0f / (1.0f + __expf(v0)),
                                               1.0f / (1.0f + __expf(v1)));
                }
            }
        }
    __syncthreads();

    // ---------------- GEMM2 ----------------
    float acc2[2][NT2][4];
    #pragma unroll
    for (int mt = 0; mt < 2; mt++)
        #pragma unroll
        for (int nt = 0; nt < NT2; nt++)
            #pragma unroll
            for (int q = 0; q < 4; q++) acc2[mt][nt][q] = 0.f;

    for (int ki = 0; ki < NC2; ki++) {
        if (ki + 1 < NC2) { load2((ki + 1) * CH, (ki + 1) & 1); CPA_WAIT(1); }
        else              { CPA_WAIT(0); }
        __syncthreads();
        uint32_t base = su + (uint32_t)((ki & 1) * STAGE) * 2;
        uint32_t aH = su + (uint32_t)(HOFF + (wm + arow) * HST + acol + ki * CH) * 2;
        uint32_t aL = aH + (uint32_t)(BM * HST) * 2;
        uint32_t bH = base + (uint32_t)(2*XPL + (wn2 + brow) * XST + bcol) * 2;
        uint32_t bL = bH + (uint32_t)WPL * 2;
        mma_blk<HST, XST, NT2>(acc2, aH, aL, bH, bL);
        __syncthreads();
    }

    // ---------------- output ----------------
    #pragma unroll
    for (int mt = 0; mt < 2; mt++)
        #pragma unroll
        for (int h2 = 0; h2 < 2; h2++) {
            int m = m0 + wm + mt * 16 + gid + h2 * 8;
            #pragma unroll
            for (int nt = 0; nt < NT2; nt++) {
                int oc = wn2 + nt * 8 + tq;
                float v0 = acc2[mt][nt][h2 * 2], v1 = acc2[mt][nt][h2 * 2 + 1];
                if (OUTM == 0) {
                    bf16 h0 = __float2bfloat16(v0), h1 = __float2bfloat16(v1);
                    bf16 l0 = __float2bfloat16(v0 - __bfloat162float(h0));
                    bf16 l1 = __float2bfloat16(v1 - __bfloat162float(h1));
                    size_t go = ((size_t)b * Mtot + m) * O2 + oc;
                    *(uint32_t*)(Oh + go) = pk(h0, h1);
                    *(uint32_t*)(Ol + go) = pk(l0, l1);
                } else {
                    Of[((size_t)b * O2 + oc)     * Mtot + m] = v0;
                    Of[((size_t)b * O2 + oc + 1) * Mtot + m] = v1;
                }
            }
        }
}

// ================= prep kernels =================
__global__ void wsplit_k(const float* __restrict__ w, bf16* __restrict__ h,
                         bf16* __restrict__ l, int n) {
    int i = blockIdx.x * 256 + threadIdx.x;
    if (i < n) {
        float v = w[i];
        bf16 hv = __float2bfloat16(v);
        h[i] = hv;
        l[i] = __float2bfloat16(v - __bfloat162float(hv));
    }
}

__global__ __launch_bounds__(256)
void prep_x(const float* __restrict__ src, bf16* __restrict__ dh, bf16* __restrict__ dl,
            int C, int M) {
    __shared__ float s[32][33];
    int p0 = blockIdx.x * 32, c0 = blockIdx.y * 32, b = blockIdx.z;
    int tx = threadIdx.x & 31, ty = threadIdx.x >> 5;
    const float* sb = src + (size_t)b * C * M;
    #pragma unroll
    for (int i = 0; i < 4; i++)
        s[ty + 8*i][tx] = sb[(size_t)(c0 + ty + 8*i) * M + p0 + tx];
    __syncthreads();
    #pragma unroll
    for (int i = 0; i < 4; i++) {
        float v = s[tx][ty + 8*i];
        size_t o = ((size_t)b * M + p0 + ty + 8*i) * C + c0 + tx;
        bf16 hv = __float2bfloat16(v);
        dh[o] = hv;
        dl[o] = __float2bfloat16(v - __bfloat162float(hv));
    }
}

// ================= attention =================
static DIB float wsum(float v) {
    #pragma unroll
    for (int o = 16; o > 0; o >>= 1) v += __shfl_xor_sync(0xffffffffu, v, o);
    return v;
}
static DIB float sigm(float x) { return 1.0f / (1.0f + __expf(-x)); }
static DIB float rd2(const bf16* h, const bf16* l, size_t i) {
    return __bfloat162float(h[i]) + __bfloat162float(l[i]);
}
static DIB void wr2(bf16* h, bf16* l, size_t i, float v) {
    bf16 x = __float2bfloat16(v);
    h[i] = x;
    l[i] = __float2bfloat16(v - __bfloat162float(x));
}

__global__ __launch_bounds__(128)
void attend_k(const bf16* __restrict__ eah, const bf16* __restrict__ eal,
              const float* __restrict__ gateb, const float* __restrict__ gatec,
              const bf16* __restrict__ ebh, const bf16* __restrict__ ebl,
              const bf16* __restrict__ ech, const bf16* __restrict__ ecl,
              const float* __restrict__ Wab, const float* __restrict__ Wac,
              bf16* __restrict__ agh, bf16* __restrict__ agl)
{
    int gw = (blockIdx.x * 128 + threadIdx.x) >> 5;
    int lane = threadIdx.x & 31;
    int b = gw >> 12, n = gw & 4095;
    int h = n >> 6, w = n & 63;
    size_t nb = (size_t)b * 4096 + n;

    float ea[4], gb[4], gc[4];
    float pab = 0.f, pac = 0.f;
    #pragma unroll
    for (int j = 0; j < 4; j++) {
        int cc = lane + 32 * j;
        ea[j] = rd2(eah, eal, nb * 128 + cc);
        gb[j] = gateb[nb * 128 + cc];
        gc[j] = gatec[nb * 128 + cc];
        pab += Wab[cc] * ea[j];
        pac += Wac[cc] * ea[j];
    }
    float dab = wsum(pab), dac = wsum(pac);

    { // B branch
        float eb[4][4], lb[4];
        #pragma unroll
        for (int p = 0; p < 4; p++) {
            int kh = p >> 1, kw = p & 1;
            size_t base = ((size_t)b * 16384 + (size_t)(2*h + kh) * 128 + (2*w + kw)) * 128;
            float s = 0.f;
            #pragma unroll
            for (int j = 0; j < 4; j++) {
                int cc = lane + 32 * j;
                eb[p][j] = rd2(ebh, ebl, base + cc);
                s += Wab[128 + cc] * eb[p][j];
            }
            lb[p] = fmaxf(dab + wsum(s), 0.0f);
        }
        float mx = fmaxf(fmaxf(lb[0], lb[1]), fmaxf(lb[2], lb[3]));
        float ss = 0.f;
        #pragma unroll
        for (int p = 0; p < 4; p++) { lb[p] = __expf(lb[p] - mx); ss += lb[p]; }
        float inv = 1.0f / ss;
        #pragma unroll
        for (int j = 0; j < 4; j++) {
            float a = 0.f;
            #pragma unroll
            for (int p = 0; p < 4; p++) a += eb[p][j] * lb[p];
            wr2(agh, agl, nb * 384 + lane + 32 * j, sigm(a * inv * gb[j]));
        }
    }
    { // C branch
        float ec[16][4], lc[16];
        #pragma unroll
        for (int p = 0; p < 16; p++) {
            int kh = p >> 2, kw = p & 3;
            size_t base = ((size_t)b * 65536 + (size_t)(4*h + kh) * 256 + (4*w + kw)) * 128;
            float s = 0.f;
            #pragma unroll
            for (int j = 0; j < 4; j++) {
                int cc = lane + 32 * j;
                ec[p][j] = rd2(ech, ecl, base + cc);
                s += Wac[128 + cc] * ec[p][j];
            }
            lc[p] = fmaxf(dac + wsum(s), 0.0f);
        }
        float mx = lc[0];
        #pragma unroll
        for (int p = 1; p < 16; p++) mx = fmaxf(mx, lc[p]);
        float ss = 0.f;
        #pragma unroll
        for (int p = 0; p < 16; p++) { lc[p] = __expf(lc[p] - mx); ss += lc[p]; }
        float inv = 1.0f / ss;
        #pragma unroll
        for (int j = 0; j < 4; j++) {
            float a = 0.f;
            #pragma unroll
            for (int p = 0; p < 16; p++) a += ec[p][j] * lc[p];
            wr2(agh, agl, nb * 384 + 128 + lane + 32 * j, sigm(a * inv * gc[j]));
        }
    }
    #pragma unroll
    for (int j = 0; j < 4; j++)
        wr2(agh, agl, nb * 384 + 256 + lane + 32 * j, sigm(ea[j]));
}

// ================= launch =================
static inline int fsz(int O1M, int NG, int O2) {
    int O1T = O1M + NG * 128;
    int WR = (O1T > O2) ? O1T : O2;
    int XPL = 64 * 40, WPL = WR * 40;
    int STAGE = 2 * XPL + 2 * WPL;
    return (2 * STAGE + 2 * 64 * (O1M + 8)) * 2;   // bytes
}

extern "C" void kernel_launch(void* const* d_in, const int* in_sizes, int n_in,
                              void* d_out, int out_size)
{
    const float* va  = (const float*)d_in[0];
    const float* vb  = (const float*)d_in[1];
    const float* vc  = (const float*)d_in[2];
    const float* Wa1 = (const float*)d_in[3];
    const float* Wa2 = (const float*)d_in[4];
    const float* Wgb = (const float*)d_in[5];
    const float* Wgc = (const float*)d_in[6];
    const float* Wb1 = (const float*)d_in[7];
    const float* Wb2 = (const float*)d_in[8];
    const float* Wc1 = (const float*)d_in[9];
    const float* Wc2 = (const float*)d_in[10];
    const float* Wab = (const float*)d_in[11];
    const float* Wac = (const float*)d_in[12];
    const float* Wr1 = (const float*)d_in[13];
    const float* Wr2 = (const float*)d_in[14];
    float* out = (float*)d_out;

    bf16 *XAh,*XAl,*XBh,*XBl,*XCh,*XCl,*eah,*eal,*ebh,*ebl,*ech,*ecl,*agh,*agl;
    float *gb,*gc;
    bf16 *WAh,*WAl,*Wa2h,*Wa2l,*Wb1h,*Wb1l,*Wb2h,*Wb2l,*Wc1h,*Wc1l,*Wc2h,*Wc2l,
         *Wr1h,*Wr1l,*Wr2h,*Wr2l;
    cudaGetSymbolAddress((void**)&XAh,g_XAh); cudaGetSymbolAddress((void**)&XAl,g_XAl);
    cudaGetSymbolAddress((void**)&XBh,g_XBh); cudaGetSymbolAddress((void**)&XBl,g_XBl);
    cudaGetSymbolAddress((void**)&XCh,g_XCh); cudaGetSymbolAddress((void**)&XCl,g_XCl);
    cudaGetSymbolAddress((void**)&eah,g_eah); cudaGetSymbolAddress((void**)&eal,g_eal);
    cudaGetSymbolAddress((void**)&gb,g_gb);   cudaGetSymbolAddress((void**)&gc,g_gc);
    cudaGetSymbolAddress((void**)&ebh,g_ebh); cudaGetSymbolAddress((void**)&ebl,g_ebl);
    cudaGetSymbolAddress((void**)&ech,g_ech); cudaGetSymbolAddress((void**)&ecl,g_ecl);
    cudaGetSymbolAddress((void**)&agh,g_agh); cudaGetSymbolAddress((void**)&agl,g_agl);
    cudaGetSymbolAddress((void**)&WAh,g_WAh); cudaGetSymbolAddress((void**)&WAl,g_WAl);
    cudaGetSymbolAddress((void**)&Wa2h,g_Wa2h); cudaGetSymbolAddress((void**)&Wa2l,g_Wa2l);
    cudaGetSymbolAddress((void**)&Wb1h,g_Wb1h); cudaGetSymbolAddress((void**)&Wb1l,g_Wb1l);
    cudaGetSymbolAddress((void**)&Wb2h,g_Wb2h); cudaGetSymbolAddress((void**)&Wb2l,g_Wb2l);
    cudaGetSymbolAddress((void**)&Wc1h,g_Wc1h); cudaGetSymbolAddress((void**)&Wc1l,g_Wc1l);
    cudaGetSymbolAddress((void**)&Wc2h,g_Wc2h); cudaGetSymbolAddress((void**)&Wc2l,g_Wc2l);
    cudaGetSymbolAddress((void**)&Wr1h,g_Wr1h); cudaGetSymbolAddress((void**)&Wr1l,g_Wr1l);
    cudaGetSymbolAddress((void**)&Wr2h,g_Wr2h); cudaGetSymbolAddress((void**)&Wr2l,g_Wr2l);

    auto ws = [&](const float* w, bf16* h, bf16* l, int n) {
        wsplit_k<<<(n + 255) / 256, 256>>>(w, h, l, n);
    };
    ws(Wa1, WAh,            WAl,            128*256);
    ws(Wgb, WAh + 128*256,  WAl + 128*256,  128*256);
    ws(Wgc, WAh + 256*256,  WAl + 256*256,  128*256);
    ws(Wa2, Wa2h, Wa2l, 128*128);
    ws(Wb1, Wb1h, Wb1l, 128*128);
    ws(Wb2, Wb2h, Wb2l, 128*128);
    ws(Wc1, Wc1h, Wc1l, 128*64);
    ws(Wc2, Wc2h, Wc2l, 128*128);
    ws(Wr1, Wr1h, Wr1l, 256*384);
    ws(Wr2, Wr2h, Wr2l, 256*256);

    prep_x<<<dim3(128, 8, NB), 256>>>(va, XAh, XAl, 256, 4096);
    prep_x<<<dim3(512, 4, NB), 256>>>(vb, XBh, XBl, 128, 16384);
    prep_x<<<dim3(2048, 2, NB), 256>>>(vc, XCh, XCl, 64, 65536);

    int sA = fsz(128, 2, 128);
    int sB = fsz(128, 0, 128);
    int sR = fsz(256, 0, 256);
    cudaFuncSetAttribute(fuse_k<256,128,2,128,1,0>, cudaFuncAttributeMaxDynamicSharedMemorySize, sA);
    cudaFuncSetAttribute(fuse_k<128,128,0,128,2,0>, cudaFuncAttributeMaxDynamicSharedMemorySize, sB);
    cudaFuncSetAttribute(fuse_k< 64,128,0,128,2,0>, cudaFuncAttributeMaxDynamicSharedMemorySize, sB);
    cudaFuncSetAttribute(fuse_k<384,256,0,256,1,2>, cudaFuncAttributeMaxDynamicSharedMemorySize, sR);

    // a-stage (fused: a1 + gates + a2)
    fuse_k<256,128,2,128,1,0><<<dim3(64, 1, NB), 256, sA>>>(
        XAh, XAl, WAh, WAl, Wa2h, Wa2l, gb, gc, eah, eal, nullptr, 4096);
    // b-stage
    fuse_k<128,128,0,128,2,0><<<dim3(256, 1, NB), 256, sB>>>(
        XBh, XBl, Wb1h, Wb1l, Wb2h, Wb2l, nullptr, nullptr, ebh, ebl, nullptr, 16384);
    // c-stage
    fuse_k< 64,128,0,128,2,0><<<dim3(1024, 1, NB), 256, sB>>>(
        XCh, XCl, Wc1h, Wc1l, Wc2h, Wc2l, nullptr, nullptr, ech, ecl, nullptr, 65536);

    attend_k<<<8192, 128>>>(eah, eal, gb, gc, ebh, ebl, ech, ecl, Wab, Wac, agh, agl);

    // readout
    fuse_k<384,256,0,256,1,2><<<dim3(64, 1, NB), 256, sR>>>(
        agh, agl, Wr1h, Wr1l, Wr2h, Wr2l, nullptr, nullptr, nullptr, nullptr, out, 4096);
}

// round 10
// speedup vs baseline: 1.7571x; 1.0178x over previous
#include <cuda_runtime.h>
#include <cuda_bf16.h>
#include <cstdint>

using bf16 = __nv_bfloat16;
#define DIB __device__ __forceinline__
#define NB 8

// ================= scratch (device globals) =================
__device__ __align__(16) bf16 g_XAh[(size_t)NB*4096*256],  g_XAl[(size_t)NB*4096*256];
__device__ __align__(16) bf16 g_XBh[(size_t)NB*16384*128], g_XBl[(size_t)NB*16384*128];
__device__ __align__(16) bf16 g_XCh[(size_t)NB*65536*64],  g_XCl[(size_t)NB*65536*64];
__device__ __align__(16) bf16 g_eah[(size_t)NB*4096*128],  g_eal[(size_t)NB*4096*128];
__device__ __align__(16) float g_gb[(size_t)NB*4096*128],  g_gc[(size_t)NB*4096*128];
__device__ __align__(16) bf16 g_ebh[(size_t)NB*16384*128], g_ebl[(size_t)NB*16384*128];
__device__ __align__(16) bf16 g_ech[(size_t)NB*65536*128], g_ecl[(size_t)NB*65536*128];
__device__ __align__(16) bf16 g_agh[(size_t)NB*4096*384],  g_agl[(size_t)NB*4096*384];
__device__ __align__(16) bf16 g_WAh[384*256],  g_WAl[384*256];   // Wa1|Wgb|Wgc stacked
__device__ __align__(16) bf16 g_Wa2h[128*128], g_Wa2l[128*128];
__device__ __align__(16) bf16 g_Wb1h[128*128], g_Wb1l[128*128];
__device__ __align__(16) bf16 g_Wb2h[128*128], g_Wb2l[128*128];
__device__ __align__(16) bf16 g_Wc1h[128*64],  g_Wc1l[128*64];
__device__ __align__(16) bf16 g_Wc2h[128*128], g_Wc2l[128*128];
__device__ __align__(16) bf16 g_Wr1h[256*384], g_Wr1l[256*384];
__device__ __align__(16) bf16 g_Wr2h[256*256], g_Wr2l[256*256];

// ================= helpers =================
static DIB uint32_t smem_u32(const void* p) {
    uint32_t a;
    asm("{ .reg .u64 t; cvta.to.shared.u64 t, %1; cvt.u32.u64 %0, t; }" : "=r"(a) : "l"(p));
    return a;
}
static DIB void cpa16(uint32_t s, const void* g) {
    asm volatile("cp.async.ca.shared.global [%0],[%1],16;" :: "r"(s), "l"(g) : "memory");
}
#define CPA_COMMIT() asm volatile("cp.async.commit_group;" ::: "memory")
#define CPA_WAIT(N)  asm volatile("cp.async.wait_group " #N ";" ::: "memory")
static DIB void ldsm4(uint32_t* r, uint32_t a) {
    asm volatile("ldmatrix.sync.aligned.m8n8.x4.shared.b16 {%0,%1,%2,%3},[%4];"
        : "=r"(r[0]), "=r"(r[1]), "=r"(r[2]), "=r"(r[3]) : "r"(a));
}
static DIB void mma16816(float* d, const uint32_t* a, const uint32_t* b) {
    asm volatile(
        "mma.sync.aligned.m16n8k16.row.col.f32.bf16.bf16.f32 "
        "{%0,%1,%2,%3}, {%4,%5,%6,%7}, {%8,%9}, {%0,%1,%2,%3};"
        : "+f"(d[0]), "+f"(d[1]), "+f"(d[2]), "+f"(d[3])
        : "r"(a[0]), "r"(a[1]), "r"(a[2]), "r"(a[3]), "r"(b[0]), "r"(b[1]));
}
static DIB uint32_t pk(bf16 lo, bf16 hi) {
    return (uint32_t)__bfloat16_as_ushort(lo) | ((uint32_t)__bfloat16_as_ushort(hi) << 16);
}

// acc += Ah*(Bh+Bl) + Al*Bh over 32 k-elems
template<int STA, int STB, int NT>
static DIB void mma_blk(float (&acc)[2][NT][4], uint32_t aH, uint32_t aL,
                        uint32_t bH, uint32_t bL)
{
    #pragma unroll
    for (int ks = 0; ks < 32; ks += 16) {
        uint32_t Ah[2][4], Al[2][4], Bh[NT/2][4], Bl[NT/2][4];
        #pragma unroll
        for (int mt = 0; mt < 2; mt++) {
            ldsm4(Ah[mt], aH + (uint32_t)(mt*16*STA + ks) * 2);
            ldsm4(Al[mt], aL + (uint32_t)(mt*16*STA + ks) * 2);
        }
        #pragma unroll
        for (int g = 0; g < NT/2; g++) {
            ldsm4(Bh[g], bH + (uint32_t)(g*16*STB + ks) * 2);
            ldsm4(Bl[g], bL + (uint32_t)(g*16*STB + ks) * 2);
        }
        #pragma unroll
        for (int nt = 0; nt < NT; nt++) {
            uint32_t bh[2] = {Bh[nt>>1][(nt&1)*2], Bh[nt>>1][(nt&1)*2+1]};
            uint32_t bl[2] = {Bl[nt>>1][(nt&1)*2], Bl[nt>>1][(nt&1)*2+1]};
            #pragma unroll
            for (int mt = 0; mt < 2; mt++) {
                mma16816(acc[mt][nt], Ah[mt], bh);
                mma16816(acc[mt][nt], Ah[mt], bl);
                mma16816(acc[mt][nt], Al[mt], bh);
            }
        }
    }
}

// ================= unified fused 2-layer GEMM (proven R6 version) =================
template<int K1, int O1M, int NG, int O2, int OCC, int OUTM>
__global__ __launch_bounds__(256, OCC)
void fuse_k(const bf16* __restrict__ Xh, const bf16* __restrict__ Xl,
            const bf16* __restrict__ W1h, const bf16* __restrict__ W1l,
            const bf16* __restrict__ W2h, const bf16* __restrict__ W2l,
            float* __restrict__ gate0, float* __restrict__ gate1,
            bf16* __restrict__ Oh, bf16* __restrict__ Ol, float* __restrict__ Of,
            int Mtot)
{
    constexpr int BM = 64, CH = 32, XST = 40;
    constexpr int O1T = O1M + NG * 128;
    constexpr int WR  = (O1T > O2) ? O1T : O2;
    constexpr int HST = O1M + 8;
    constexpr int XPL = BM * XST, WPL = WR * XST;
    constexpr int STAGE = 2 * XPL + 2 * WPL;
    constexpr int HOFF  = 2 * STAGE;
    constexpr int NC1 = K1 / CH, NC2 = O1M / CH;
    constexpr int NT1 = O1T / 32, NT2 = O2 / 32;

    extern __shared__ bf16 smm[];
    const int tid = threadIdx.x, lane = tid & 31, warp = tid >> 5;
    const int gid = lane >> 2, tq = (lane & 3) * 2;
    const int wm  = (warp >> 2) * 32;
    const int wn1 = (warp & 3) * (NT1 * 8);
    const int wn2 = (warp & 3) * (NT2 * 8);
    const int b = blockIdx.z, m0 = blockIdx.x * BM;
    const uint32_t su = smem_u32(smm);

    const int arow = (lane & 7) + ((lane >> 3) & 1) * 8;
    const int acol = (lane >> 4) * 8;
    const int brow = (lane & 7) + (lane >> 4) * 8;
    const int bcol = ((lane >> 3) & 1) * 8;

    const bf16* Xhb = Xh + ((size_t)b * Mtot + m0) * K1;
    const bf16* Xlb = Xl + ((size_t)b * Mtot + m0) * K1;

    auto load1 = [&](int kc, int s) {
        uint32_t base = su + (uint32_t)(s * STAGE) * 2;
        #pragma unroll
        for (int i = tid; i < BM * 4; i += 256) {
            int r = i >> 2, c = (i & 3) * 8;
            cpa16(base + (uint32_t)(r * XST + c) * 2,       Xhb + (size_t)r * K1 + kc + c);
            cpa16(base + (uint32_t)(XPL + r * XST + c) * 2, Xlb + (size_t)r * K1 + kc + c);
        }
        #pragma unroll
        for (int i = tid; i < O1T * 4; i += 256) {
            int r = i >> 2, c = (i & 3) * 8;
            cpa16(base + (uint32_t)(2*XPL + r * XST + c) * 2,       W1h + (size_t)r * K1 + kc + c);
            cpa16(base + (uint32_t)(2*XPL + WPL + r * XST + c) * 2, W1l + (size_t)r * K1 + kc + c);
        }
        CPA_COMMIT();
    };
    auto load2 = [&](int kc, int s) {
        uint32_t base = su + (uint32_t)(s * STAGE) * 2;
        #pragma unroll
        for (int i = tid; i < O2 * 4; i += 256) {
            int r = i >> 2, c = (i & 3) * 8;
            cpa16(base + (uint32_t)(2*XPL + r * XST + c) * 2,       W2h + (size_t)r * O1M + kc + c);
            cpa16(base + (uint32_t)(2*XPL + WPL + r * XST + c) * 2, W2l + (size_t)r * O1M + kc + c);
        }
        CPA_COMMIT();
    };

    // ---------------- GEMM1 ----------------
    float acc1[2][NT1][4];
    #pragma unroll
    for (int mt = 0; mt < 2; mt++)
        #pragma unroll
        for (int nt = 0; nt < NT1; nt++)
            #pragma unroll
            for (int q = 0; q < 4; q++) acc1[mt][nt][q] = 0.f;

    load1(0, 0);
    for (int ki = 0; ki < NC1; ki++) {
        if (ki + 1 < NC1) { load1((ki + 1) * CH, (ki + 1) & 1); CPA_WAIT(1); }
        else              { CPA_WAIT(0); }
        __syncthreads();
        uint32_t base = su + (uint32_t)((ki & 1) * STAGE) * 2;
        uint32_t aH = base + (uint32_t)((wm + arow) * XST + acol) * 2;
        uint32_t aL = aH + (uint32_t)XPL * 2;
        uint32_t bH = base + (uint32_t)(2*XPL + (wn1 + brow) * XST + bcol) * 2;
        uint32_t bL = bH + (uint32_t)WPL * 2;
        mma_blk<XST, XST, NT1>(acc1, aH, aL, bH, bL);
        __syncthreads();
    }

    load2(0, 0);   // prefetch first W2 chunk under the epilogue

    // ---------------- relu+split -> h smem; gates -> global ----------------
    #pragma unroll
    for (int mt = 0; mt < 2; mt++)
        #pragma unroll
        for (int h2 = 0; h2 < 2; h2++) {
            int ml = wm + mt * 16 + gid + h2 * 8;
            #pragma unroll
            for (int nt = 0; nt < NT1; nt++) {
                int oc = wn1 + nt * 8 + tq;
                float v0 = acc1[mt][nt][h2 * 2], v1 = acc1[mt][nt][h2 * 2 + 1];
                if (NG == 0 || oc < O1M) {
                    v0 = fmaxf(v0, 0.f); v1 = fmaxf(v1, 0.f);
                    bf16 h0 = __float2bfloat16(v0), h1 = __float2bfloat16(v1);
                    bf16 l0 = __float2bfloat16(v0 - __bfloat162float(h0));
                    bf16 l1 = __float2bfloat16(v1 - __bfloat162float(h1));
                    *(uint32_t*)&smm[HOFF + ml * HST + oc]            = pk(h0, h1);
                    *(uint32_t*)&smm[HOFF + BM * HST + ml * HST + oc] = pk(l0, l1);
                } else {
                    int g = (oc - O1M) >> 7;
                    float* gp = (g ? gate1 : gate0) + ((size_t)b * Mtot + m0 + ml) * 128 + (oc & 127);
                    *(float2*)gp = make_float2(1.0f / (1.0f + __expf(v0)),
                                               1.0f / (1.0f + __expf(v1)));
                }
            }
        }
    __syncthreads();

    // ---------------- GEMM2 ----------------
    float acc2[2][NT2][4];
    #pragma unroll
    for (int mt = 0; mt < 2; mt++)
        #pragma unroll
        for (int nt = 0; nt < NT2; nt++)
            #pragma unroll
            for (int q = 0; q < 4; q++) acc2[mt][nt][q] = 0.f;

    for (int ki = 0; ki < NC2; ki++) {
        if (ki + 1 < NC2) { load2((ki + 1) * CH, (ki + 1) & 1); CPA_WAIT(1); }
        else              { CPA_WAIT(0); }
        __syncthreads();
        uint32_t base = su + (uint32_t)((ki & 1) * STAGE) * 2;
        uint32_t aH = su + (uint32_t)(HOFF + (wm + arow) * HST + acol + ki * CH) * 2;
        uint32_t aL = aH + (uint32_t)(BM * HST) * 2;
        uint32_t bH = base + (uint32_t)(2*XPL + (wn2 + brow) * XST + bcol) * 2;
        uint32_t bL = bH + (uint32_t)WPL * 2;
        mma_blk<HST, XST, NT2>(acc2, aH, aL, bH, bL);
        __syncthreads();
    }

    // ---------------- output ----------------
    #pragma unroll
    for (int mt = 0; mt < 2; mt++)
        #pragma unroll
        for (int h2 = 0; h2 < 2; h2++) {
            int m = m0 + wm + mt * 16 + gid + h2 * 8;
            #pragma unroll
            for (int nt = 0; nt < NT2; nt++) {
                int oc = wn2 + nt * 8 + tq;
                float v0 = acc2[mt][nt][h2 * 2], v1 = acc2[mt][nt][h2 * 2 + 1];
                if (OUTM == 0) {
                    bf16 h0 = __float2bfloat16(v0), h1 = __float2bfloat16(v1);
                    bf16 l0 = __float2bfloat16(v0 - __bfloat162float(h0));
                    bf16 l1 = __float2bfloat16(v1 - __bfloat162float(h1));
                    size_t go = ((size_t)b * Mtot + m) * O2 + oc;
                    *(uint32_t*)(Oh + go) = pk(h0, h1);
                    *(uint32_t*)(Ol + go) = pk(l0, l1);
                } else {
                    Of[((size_t)b * O2 + oc)     * Mtot + m] = v0;
                    Of[((size_t)b * O2 + oc + 1) * Mtot + m] = v1;
                }
            }
        }
}

// ================= prep kernels =================
struct WSeg { const float* s; bf16* h; bf16* l; int n; };
struct WParams { WSeg w[10]; };

__global__ __launch_bounds__(256)
void wsplit_all(WParams p) {
    int gi = blockIdx.x * 256 + threadIdx.x;
    #pragma unroll
    for (int s = 0; s < 10; s++) {
        int n = p.w[s].n;
        if (gi < n) {
            float v = p.w[s].s[gi];
            bf16 hv = __float2bfloat16(v);
            p.w[s].h[gi] = hv;
            p.w[s].l[gi] = __float2bfloat16(v - __bfloat162float(hv));
            return;
        }
        gi -= n;
    }
}

__global__ __launch_bounds__(256)
void prep_x(const float* __restrict__ src, bf16* __restrict__ dh, bf16* __restrict__ dl,
            int C, int M) {
    __shared__ float s[32][33];
    int p0 = blockIdx.x * 32, c0 = blockIdx.y * 32, b = blockIdx.z;
    int tx = threadIdx.x & 31, ty = threadIdx.x >> 5;
    const float* sb = src + (size_t)b * C * M;
    #pragma unroll
    for (int i = 0; i < 4; i++)
        s[ty + 8*i][tx] = sb[(size_t)(c0 + ty + 8*i) * M + p0 + tx];
    __syncthreads();
    #pragma unroll
    for (int i = 0; i < 4; i++) {
        float v = s[tx][ty + 8*i];
        size_t o = ((size_t)b * M + p0 + ty + 8*i) * C + c0 + tx;
        bf16 hv = __float2bfloat16(v);
        dh[o] = hv;
        dl[o] = __float2bfloat16(v - __bfloat162float(hv));
    }
}

// ================= attention =================
static DIB float wsum(float v) {
    #pragma unroll
    for (int o = 16; o > 0; o >>= 1) v += __shfl_xor_sync(0xffffffffu, v, o);
    return v;
}
static DIB float sigm(float x) { return 1.0f / (1.0f + __expf(-x)); }
static DIB float rd2(const bf16* h, const bf16* l, size_t i) {
    return __bfloat162float(h[i]) + __bfloat162float(l[i]);
}
static DIB void wr2(bf16* h, bf16* l, size_t i, float v) {
    bf16 x = __float2bfloat16(v);
    h[i] = x;
    l[i] = __float2bfloat16(v - __bfloat162float(x));
}

__global__ __launch_bounds__(128)
void attend_k(const bf16* __restrict__ eah, const bf16* __restrict__ eal,
              const float* __restrict__ gateb, const float* __restrict__ gatec,
              const bf16* __restrict__ ebh, const bf16* __restrict__ ebl,
              const bf16* __restrict__ ech, const bf16* __restrict__ ecl,
              const float* __restrict__ Wab, const float* __restrict__ Wac,
              bf16* __restrict__ agh, bf16* __restrict__ agl)
{
    int gw = (blockIdx.x * 128 + threadIdx.x) >> 5;
    int lane = threadIdx.x & 31;
    int b = gw >> 12, n = gw & 4095;
    int h = n >> 6, w = n & 63;
    size_t nb = (size_t)b * 4096 + n;

    float ea[4], gb[4], gc[4];
    float pab = 0.f, pac = 0.f;
    #pragma unroll
    for (int j = 0; j < 4; j++) {
        int cc = lane + 32 * j;
        ea[j] = rd2(eah, eal, nb * 128 + cc);
        gb[j] = gateb[nb * 128 + cc];
        gc[j] = gatec[nb * 128 + cc];
        pab += Wab[cc] * ea[j];
        pac += Wac[cc] * ea[j];
    }
    float dab = wsum(pab), dac = wsum(pac);

    { // B branch
        float eb[4][4], lb[4];
        #pragma unroll
        for (int p = 0; p < 4; p++) {
            int kh = p >> 1, kw = p & 1;
            size_t base = ((size_t)b * 16384 + (size_t)(2*h + kh) * 128 + (2*w + kw)) * 128;
            float s = 0.f;
            #pragma unroll
            for (int j = 0; j < 4; j++) {
                int cc = lane + 32 * j;
                eb[p][j] = rd2(ebh, ebl, base + cc);
                s += Wab[128 + cc] * eb[p][j];
            }
            lb[p] = fmaxf(dab + wsum(s), 0.0f);
        }
        float mx = fmaxf(fmaxf(lb[0], lb[1]), fmaxf(lb[2], lb[3]));
        float ss = 0.f;
        #pragma unroll
        for (int p = 0; p < 4; p++) { lb[p] = __expf(lb[p] - mx); ss += lb[p]; }
        float inv = 1.0f / ss;
        #pragma unroll
        for (int j = 0; j < 4; j++) {
            float a = 0.f;
            #pragma unroll
            for (int p = 0; p < 4; p++) a += eb[p][j] * lb[p];
            wr2(agh, agl, nb * 384 + lane + 32 * j, sigm(a * inv * gb[j]));
        }
    }
    { // C branch
        float ec[16][4], lc[16];
        #pragma unroll
        for (int p = 0; p < 16; p++) {
            int kh = p >> 2, kw = p & 3;
            size_t base = ((size_t)b * 65536 + (size_t)(4*h + kh) * 256 + (4*w + kw)) * 128;
            float s = 0.f;
            #pragma unroll
            for (int j = 0; j < 4; j++) {
                int cc = lane + 32 * j;
                ec[p][j] = rd2(ech, ecl, base + cc);
                s += Wac[128 + cc] * ec[p][j];
            }
            lc[p] = fmaxf(dac + wsum(s), 0.0f);
        }
        float mx = lc[0];
        #pragma unroll
        for (int p = 1; p < 16; p++) mx = fmaxf(mx, lc[p]);
        float ss = 0.f;
        #pragma unroll
        for (int p = 0; p < 16; p++) { lc[p] = __expf(lc[p] - mx); ss += lc[p]; }
        float inv = 1.0f / ss;
        #pragma unroll
        for (int j = 0; j < 4; j++) {
            float a = 0.f;
            #pragma unroll
            for (int p = 0; p < 16; p++) a += ec[p][j] * lc[p];
            wr2(agh, agl, nb * 384 + 128 + lane + 32 * j, sigm(a * inv * gc[j]));
        }
    }
    #pragma unroll
    for (int j = 0; j < 4; j++)
        wr2(agh, agl, nb * 384 + 256 + lane + 32 * j, sigm(ea[j]));
}

// ================= launch =================
static inline int fsz(int O1M, int NG, int O2) {
    int O1T = O1M + NG * 128;
    int WR = (O1T > O2) ? O1T : O2;
    int XPL = 64 * 40, WPL = WR * 40;
    int STAGE = 2 * XPL + 2 * WPL;
    return (2 * STAGE + 2 * 64 * (O1M + 8)) * 2;   // bytes
}

extern "C" void kernel_launch(void* const* d_in, const int* in_sizes, int n_in,
                              void* d_out, int out_size)
{
    const float* va  = (const float*)d_in[0];
    const float* vb  = (const float*)d_in[1];
    const float* vc  = (const float*)d_in[2];
    const float* Wa1 = (const float*)d_in[3];
    const float* Wa2 = (const float*)d_in[4];
    const float* Wgb = (const float*)d_in[5];
    const float* Wgc = (const float*)d_in[6];
    const float* Wb1 = (const float*)d_in[7];
    const float* Wb2 = (const float*)d_in[8];
    const float* Wc1 = (const float*)d_in[9];
    const float* Wc2 = (const float*)d_in[10];
    const float* Wab = (const float*)d_in[11];
    const float* Wac = (const float*)d_in[12];
    const float* Wr1 = (const float*)d_in[13];
    const float* Wr2 = (const float*)d_in[14];
    float* out = (float*)d_out;

    bf16 *XAh,*XAl,*XBh,*XBl,*XCh,*XCl,*eah,*eal,*ebh,*ebl,*ech,*ecl,*agh,*agl;
    float *gb,*gc;
    bf16 *WAh,*WAl,*Wa2h,*Wa2l,*Wb1h,*Wb1l,*Wb2h,*Wb2l,*Wc1h,*Wc1l,*Wc2h,*Wc2l,
         *Wr1h,*Wr1l,*Wr2h,*Wr2l;
    cudaGetSymbolAddress((void**)&XAh,g_XAh); cudaGetSymbolAddress((void**)&XAl,g_XAl);
    cudaGetSymbolAddress((void**)&XBh,g_XBh); cudaGetSymbolAddress((void**)&XBl,g_XBl);
    cudaGetSymbolAddress((void**)&XCh,g_XCh); cudaGetSymbolAddress((void**)&XCl,g_XCl);
    cudaGetSymbolAddress((void**)&eah,g_eah); cudaGetSymbolAddress((void**)&eal,g_eal);
    cudaGetSymbolAddress((void**)&gb,g_gb);   cudaGetSymbolAddress((void**)&gc,g_gc);
    cudaGetSymbolAddress((void**)&ebh,g_ebh); cudaGetSymbolAddress((void**)&ebl,g_ebl);
    cudaGetSymbolAddress((void**)&ech,g_ech); cudaGetSymbolAddress((void**)&ecl,g_ecl);
    cudaGetSymbolAddress((void**)&agh,g_agh); cudaGetSymbolAddress((void**)&agl,g_agl);
    cudaGetSymbolAddress((void**)&WAh,g_WAh); cudaGetSymbolAddress((void**)&WAl,g_WAl);
    cudaGetSymbolAddress((void**)&Wa2h,g_Wa2h); cudaGetSymbolAddress((void**)&Wa2l,g_Wa2l);
    cudaGetSymbolAddress((void**)&Wb1h,g_Wb1h); cudaGetSymbolAddress((void**)&Wb1l,g_Wb1l);
    cudaGetSymbolAddress((void**)&Wb2h,g_Wb2h); cudaGetSymbolAddress((void**)&Wb2l,g_Wb2l);
    cudaGetSymbolAddress((void**)&Wc1h,g_Wc1h); cudaGetSymbolAddress((void**)&Wc1l,g_Wc1l);
    cudaGetSymbolAddress((void**)&Wc2h,g_Wc2h); cudaGetSymbolAddress((void**)&Wc2l,g_Wc2l);
    cudaGetSymbolAddress((void**)&Wr1h,g_Wr1h); cudaGetSymbolAddress((void**)&Wr1l,g_Wr1l);
    cudaGetSymbolAddress((void**)&Wr2h,g_Wr2h); cudaGetSymbolAddress((void**)&Wr2l,g_Wr2l);

    // weight splits (one kernel, 10 segments)
    WParams P;
    P.w[0] = {Wa1, WAh,           WAl,           32768};
    P.w[1] = {Wgb, WAh + 32768,   WAl + 32768,   32768};
    P.w[2] = {Wgc, WAh + 65536,   WAl + 65536,   32768};
    P.w[3] = {Wa2, Wa2h, Wa2l, 16384};
    P.w[4] = {Wb1, Wb1h, Wb1l, 16384};
    P.w[5] = {Wb2, Wb2h, Wb2l, 16384};
    P.w[6] = {Wc1, Wc1h, Wc1l, 8192};
    P.w[7] = {Wc2, Wc2h, Wc2l, 16384};
    P.w[8] = {Wr1, Wr1h, Wr1l, 98304};
    P.w[9] = {Wr2, Wr2h, Wr2l, 65536};
    wsplit_all<<<(335872 + 255) / 256, 256>>>(P);

    prep_x<<<dim3(128, 8, NB), 256>>>(va, XAh, XAl, 256, 4096);
    prep_x<<<dim3(512, 4, NB), 256>>>(vb, XBh, XBl, 128, 16384);
    prep_x<<<dim3(2048, 2, NB), 256>>>(vc, XCh, XCl, 64, 65536);

    int sA = fsz(128, 2, 128);
    int sB = fsz(128, 0, 128);
    int sR = fsz(256, 0, 256);
    cudaFuncSetAttribute(fuse_k<256,128,2,128,1,0>, cudaFuncAttributeMaxDynamicSharedMemorySize, sA);
    cudaFuncSetAttribute(fuse_k<128,128,0,128,2,0>, cudaFuncAttributeMaxDynamicSharedMemorySize, sB);
    cudaFuncSetAttribute(fuse_k< 64,128,0,128,2,0>, cudaFuncAttributeMaxDynamicSharedMemorySize, sB);
    cudaFuncSetAttribute(fuse_k<384,256,0,256,1,2>, cudaFuncAttributeMaxDynamicSharedMemorySize, sR);

    // a-stage (fused: a1 + gates + a2)
    fuse_k<256,128,2,128,1,0><<<dim3(64, 1, NB), 256, sA>>>(
        XAh, XAl, WAh, WAl, Wa2h, Wa2l, gb, gc, eah, eal, nullptr, 4096);
    // b-stage
    fuse_k<128,128,0,128,2,0><<<dim3(256, 1, NB), 256, sB>>>(
        XBh, XBl, Wb1h, Wb1l, Wb2h, Wb2l, nullptr, nullptr, ebh, ebl, nullptr, 16384);
    // c-stage
    fuse_k< 64,128,0,128,2,0><<<dim3(1024, 1, NB), 256, sB>>>(
        XCh, XCl, Wc1h, Wc1l, Wc2h, Wc2l, nullptr, nullptr, ech, ecl, nullptr, 65536);

    attend_k<<<8192, 128>>>(eah, eal, gb, gc, ebh, ebl, ech, ecl, Wab, Wac, agh, agl);

    // readout
    fuse_k<384,256,0,256,1,2><<<dim3(64, 1, NB), 256, sR>>>(
        agh, agl, Wr1h, Wr1l, Wr2h, Wr2l, nullptr, nullptr, nullptr, nullptr, out, 4096);
}

// round 11
// speedup vs baseline: 1.8245x; 1.0384x over previous
#include <cuda_runtime.h>
#include <cuda_bf16.h>
#include <cstdint>

using bf16 = __nv_bfloat16;
#define DIB __device__ __forceinline__
#define NB 8

// ================= scratch (device globals) =================
__device__ __align__(16) bf16 g_eah[(size_t)NB*4096*128],  g_eal[(size_t)NB*4096*128];
__device__ __align__(16) float g_gb[(size_t)NB*4096*128],  g_gc[(size_t)NB*4096*128];
__device__ __align__(16) bf16 g_ebh[(size_t)NB*16384*128], g_ebl[(size_t)NB*16384*128];
__device__ __align__(16) bf16 g_ech[(size_t)NB*65536*128], g_ecl[(size_t)NB*65536*128];
__device__ __align__(16) bf16 g_agh[(size_t)NB*4096*384],  g_agl[(size_t)NB*4096*384];
__device__ __align__(16) bf16 g_WAh[384*256],  g_WAl[384*256];   // Wa1|Wgb|Wgc stacked
__device__ __align__(16) bf16 g_Wa2h[128*128], g_Wa2l[128*128];
__device__ __align__(16) bf16 g_Wb1h[128*128], g_Wb1l[128*128];
__device__ __align__(16) bf16 g_Wb2h[128*128], g_Wb2l[128*128];
__device__ __align__(16) bf16 g_Wc1h[128*64],  g_Wc1l[128*64];
__device__ __align__(16) bf16 g_Wc2h[128*128], g_Wc2l[128*128];
__device__ __align__(16) bf16 g_Wr1h[256*384], g_Wr1l[256*384];
__device__ __align__(16) bf16 g_Wr2h[256*256], g_Wr2l[256*256];

// ================= helpers =================
static DIB uint32_t smem_u32(const void* p) {
    uint32_t a;
    asm("{ .reg .u64 t; cvta.to.shared.u64 t, %1; cvt.u32.u64 %0, t; }" : "=r"(a) : "l"(p));
    return a;
}
static DIB void cpa16(uint32_t s, const void* g) {
    asm volatile("cp.async.ca.shared.global [%0],[%1],16;" :: "r"(s), "l"(g) : "memory");
}
#define CPA_COMMIT() asm volatile("cp.async.commit_group;" ::: "memory")
#define CPA_WAIT(N)  asm volatile("cp.async.wait_group " #N ";" ::: "memory")
static DIB void ldsm4(uint32_t* r, uint32_t a) {
    asm volatile("ldmatrix.sync.aligned.m8n8.x4.shared.b16 {%0,%1,%2,%3},[%4];"
        : "=r"(r[0]), "=r"(r[1]), "=r"(r[2]), "=r"(r[3]) : "r"(a));
}
static DIB void mma16816(float* d, const uint32_t* a, const uint32_t* b) {
    asm volatile(
        "mma.sync.aligned.m16n8k16.row.col.f32.bf16.bf16.f32 "
        "{%0,%1,%2,%3}, {%4,%5,%6,%7}, {%8,%9}, {%0,%1,%2,%3};"
        : "+f"(d[0]), "+f"(d[1]), "+f"(d[2]), "+f"(d[3])
        : "r"(a[0]), "r"(a[1]), "r"(a[2]), "r"(a[3]), "r"(b[0]), "r"(b[1]));
}
static DIB uint32_t pk(bf16 lo, bf16 hi) {
    return (uint32_t)__bfloat16_as_ushort(lo) | ((uint32_t)__bfloat16_as_ushort(hi) << 16);
}

// acc += Ah*(Bh+Bl) + Al*Bh over 32 k-elems
template<int STA, int STB, int NT>
static DIB void mma_blk(float (&acc)[2][NT][4], uint32_t aH, uint32_t aL,
                        uint32_t bH, uint32_t bL)
{
    #pragma unroll
    for (int ks = 0; ks < 32; ks += 16) {
        uint32_t Ah[2][4], Al[2][4], Bh[NT/2][4], Bl[NT/2][4];
        #pragma unroll
        for (int mt = 0; mt < 2; mt++) {
            ldsm4(Ah[mt], aH + (uint32_t)(mt*16*STA + ks) * 2);
            ldsm4(Al[mt], aL + (uint32_t)(mt*16*STA + ks) * 2);
        }
        #pragma unroll
        for (int g = 0; g < NT/2; g++) {
            ldsm4(Bh[g], bH + (uint32_t)(g*16*STB + ks) * 2);
            ldsm4(Bl[g], bL + (uint32_t)(g*16*STB + ks) * 2);
        }
        #pragma unroll
        for (int nt = 0; nt < NT; nt++) {
            uint32_t bh[2] = {Bh[nt>>1][(nt&1)*2], Bh[nt>>1][(nt&1)*2+1]};
            uint32_t bl[2] = {Bl[nt>>1][(nt&1)*2], Bl[nt>>1][(nt&1)*2+1]};
            #pragma unroll
            for (int mt = 0; mt < 2; mt++) {
                mma16816(acc[mt][nt], Ah[mt], bh);
                mma16816(acc[mt][nt], Ah[mt], bl);
                mma16816(acc[mt][nt], Al[mt], bh);
            }
        }
    }
}

// ================= unified fused 2-layer GEMM =================
// XMODE 1: X is fp32 channel-major [B][K1][M] loaded+transposed+split in-kernel.
// XMODE 0: X is bf16 hi/lo channel-last [B][M][K1], streamed per chunk.
template<int K1, int O1M, int NG, int O2, int OCC, int OUTM, int XMODE>
__global__ __launch_bounds__(256, OCC)
void fuse_k(const float* __restrict__ Xf,
            const bf16* __restrict__ Xh, const bf16* __restrict__ Xl,
            const bf16* __restrict__ W1h, const bf16* __restrict__ W1l,
            const bf16* __restrict__ W2h, const bf16* __restrict__ W2l,
            float* __restrict__ gate0, float* __restrict__ gate1,
            bf16* __restrict__ Oh, bf16* __restrict__ Ol, float* __restrict__ Of,
            int Mtot)
{
    constexpr int BM = 64, CH = 32, WST = 40;
    constexpr int O1T = O1M + NG * 128;
    constexpr int WR  = (O1T > O2) ? O1T : O2;
    constexpr int HST = O1M + 8;
    constexpr int WPL = WR * WST;
    constexpr int AST = K1 + 8;          // XMODE1 persistent A stride
    constexpr int APL = BM * AST;
    constexpr int XST = 40;              // XMODE0 streamed X stride
    constexpr int XPL = BM * XST;
    constexpr int STG  = (XMODE == 1) ? (2 * WPL) : (2 * XPL + 2 * WPL);
    constexpr int SOFF = (XMODE == 1) ? (2 * APL) : 0;
    constexpr int WIN  = (XMODE == 1) ? 0 : (2 * XPL);
    constexpr int HOFFn = SOFF + 2 * STG;
    constexpr int NC1 = K1 / CH, NC2 = O1M / CH;
    constexpr int NT1 = O1T / 32, NT2 = O2 / 32;

    extern __shared__ bf16 smm[];
    const int tid = threadIdx.x, lane = tid & 31, warp = tid >> 5;
    const int gid = lane >> 2, tq = (lane & 3) * 2;
    const int wm  = (warp >> 2) * 32;
    const int wn1 = (warp & 3) * (NT1 * 8);
    const int wn2 = (warp & 3) * (NT2 * 8);
    const int b = blockIdx.z, m0 = blockIdx.x * BM;
    const uint32_t su = smem_u32(smm);

    const int arow = (lane & 7) + ((lane >> 3) & 1) * 8;
    const int acol = (lane >> 4) * 8;
    const int brow = (lane & 7) + (lane >> 4) * 8;
    const int bcol = ((lane >> 3) & 1) * 8;

    auto load1 = [&](int kc, int s) {
        uint32_t wb = su + (uint32_t)(SOFF + s * STG + WIN) * 2;
        if constexpr (XMODE == 0) {
            uint32_t base = su + (uint32_t)(s * STG) * 2;
            const bf16* Xhb = Xh + ((size_t)b * Mtot + m0) * K1;
            const bf16* Xlb = Xl + ((size_t)b * Mtot + m0) * K1;
            #pragma unroll
            for (int i = tid; i < BM * 4; i += 256) {
                int r = i >> 2, c = (i & 3) * 8;
                cpa16(base + (uint32_t)(r * XST + c) * 2,       Xhb + (size_t)r * K1 + kc + c);
                cpa16(base + (uint32_t)(XPL + r * XST + c) * 2, Xlb + (size_t)r * K1 + kc + c);
            }
        }
        #pragma unroll
        for (int i = tid; i < O1T * 4; i += 256) {
            int r = i >> 2, c = (i & 3) * 8;
            cpa16(wb + (uint32_t)(r * WST + c) * 2,       W1h + (size_t)r * K1 + kc + c);
            cpa16(wb + (uint32_t)(WPL + r * WST + c) * 2, W1l + (size_t)r * K1 + kc + c);
        }
        CPA_COMMIT();
    };
    auto load2 = [&](int kc, int s) {
        uint32_t wb = su + (uint32_t)(SOFF + s * STG + WIN) * 2;
        #pragma unroll
        for (int i = tid; i < O2 * 4; i += 256) {
            int r = i >> 2, c = (i & 3) * 8;
            cpa16(wb + (uint32_t)(r * WST + c) * 2,       W2h + (size_t)r * O1M + kc + c);
            cpa16(wb + (uint32_t)(WPL + r * WST + c) * 2, W2l + (size_t)r * O1M + kc + c);
        }
        CPA_COMMIT();
    };

    // ---------------- phase 0: X ingest ----------------
    if constexpr (XMODE == 1) {
        // staging (fp32 [K1][68]) unioned with W-stage1 region (dead until GEMM1 prefetch)
        constexpr int SST_OFF = SOFF + STG;
        uint32_t sbase = su + (uint32_t)SST_OFF * 2;
        const float* Xg = Xf + (size_t)b * K1 * Mtot + m0;
        #pragma unroll
        for (int i = tid; i < K1 * 16; i += 256) {
            int r = i >> 4, c4 = (i & 15) * 4;
            cpa16(sbase + (uint32_t)(r * 68 + c4) * 4, Xg + (size_t)r * Mtot + c4);
        }
        CPA_COMMIT();
        load1(0, 0);          // W1 chunk0 behind staging
        CPA_WAIT(1);          // staging arrived
        __syncthreads();
        const float* stg = (const float*)(smm + SST_OFF);
        int m = tid & 63, k0 = (tid >> 6) * (K1 / 4);
        #pragma unroll
        for (int j = 0; j < K1 / 4; j += 2) {
            int k = k0 + j;
            float v0 = stg[k * 68 + m], v1 = stg[(k + 1) * 68 + m];
            bf16 h0 = __float2bfloat16(v0), h1 = __float2bfloat16(v1);
            bf16 l0 = __float2bfloat16(v0 - __bfloat162float(h0));
            bf16 l1 = __float2bfloat16(v1 - __bfloat162float(h1));
            *(uint32_t*)&smm[(size_t)m * AST + k]       = pk(h0, h1);
            *(uint32_t*)&smm[(size_t)APL + m * AST + k] = pk(l0, l1);
        }
        __syncthreads();
    } else {
        load1(0, 0);
    }

    // ---------------- GEMM1 ----------------
    float acc1[2][NT1][4];
    #pragma unroll
    for (int mt = 0; mt < 2; mt++)
        #pragma unroll
        for (int nt = 0; nt < NT1; nt++)
            #pragma unroll
            for (int q = 0; q < 4; q++) acc1[mt][nt][q] = 0.f;

    for (int ki = 0; ki < NC1; ki++) {
        if (ki + 1 < NC1) { load1((ki + 1) * CH, (ki + 1) & 1); CPA_WAIT(1); }
        else              { CPA_WAIT(0); }
        __syncthreads();
        uint32_t aH, aL;
        if constexpr (XMODE == 1) {
            aH = su + (uint32_t)((wm + arow) * AST + acol + ki * CH) * 2;
            aL = aH + (uint32_t)APL * 2;
        } else {
            uint32_t base = su + (uint32_t)((ki & 1) * STG) * 2;
            aH = base + (uint32_t)((wm + arow) * XST + acol) * 2;
            aL = aH + (uint32_t)XPL * 2;
        }
        uint32_t wb = su + (uint32_t)(SOFF + (ki & 1) * STG + WIN) * 2;
        uint32_t bH = wb + (uint32_t)((wn1 + brow) * WST + bcol) * 2;
        uint32_t bL = bH + (uint32_t)WPL * 2;
        mma_blk<(XMODE == 1 ? AST : XST), WST, NT1>(acc1, aH, aL, bH, bL);
        __syncthreads();
    }

    load2(0, 0);   // prefetch first W2 chunk under the epilogue

    // ---------------- relu+split -> h smem; gates -> global ----------------
    #pragma unroll
    for (int mt = 0; mt < 2; mt++)
        #pragma unroll
        for (int h2 = 0; h2 < 2; h2++) {
            int ml = wm + mt * 16 + gid + h2 * 8;
            #pragma unroll
            for (int nt = 0; nt < NT1; nt++) {
                int oc = wn1 + nt * 8 + tq;
                float v0 = acc1[mt][nt][h2 * 2], v1 = acc1[mt][nt][h2 * 2 + 1];
                if (NG == 0 || oc < O1M) {
                    v0 = fmaxf(v0, 0.f); v1 = fmaxf(v1, 0.f);
                    bf16 h0 = __float2bfloat16(v0), h1 = __float2bfloat16(v1);
                    bf16 l0 = __float2bfloat16(v0 - __bfloat162float(h0));
                    bf16 l1 = __float2bfloat16(v1 - __bfloat162float(h1));
                    *(uint32_t*)&smm[HOFFn + ml * HST + oc]            = pk(h0, h1);
                    *(uint32_t*)&smm[HOFFn + BM * HST + ml * HST + oc] = pk(l0, l1);
                } else {
                    int g = (oc - O1M) >> 7;
                    float* gp = (g ? gate1 : gate0) + ((size_t)b * Mtot + m0 + ml) * 128 + (oc & 127);
                    *(float2*)gp = make_float2(1.0f / (1.0f + __expf(v0)),
                                               1.0f / (1.0f + __expf(v1)));
                }
            }
        }
    __syncthreads();

    // ---------------- GEMM2 ----------------
    float acc2[2][NT2][4];
    #pragma unroll
    for (int mt = 0; mt < 2; mt++)
        #pragma unroll
        for (int nt = 0; nt < NT2; nt++)
            #pragma unroll
            for (int q = 0; q < 4; q++) acc2[mt][nt][q] = 0.f;

    for (int ki = 0; ki < NC2; ki++) {
        if (ki + 1 < NC2) { load2((ki + 1) * CH, (ki + 1) & 1); CPA_WAIT(1); }
        else              { CPA_WAIT(0); }
        __syncthreads();
        uint32_t aH = su + (uint32_t)(HOFFn + (wm + arow) * HST + acol + ki * CH) * 2;
        uint32_t aL = aH + (uint32_t)(BM * HST) * 2;
        uint32_t wb = su + (uint32_t)(SOFF + (ki & 1) * STG + WIN) * 2;
        uint32_t bH = wb + (uint32_t)((wn2 + brow) * WST + bcol) * 2;
        uint32_t bL = bH + (uint32_t)WPL * 2;
        mma_blk<HST, WST, NT2>(acc2, aH, aL, bH, bL);
        __syncthreads();
    }

    // ---------------- output ----------------
    #pragma unroll
    for (int mt = 0; mt < 2; mt++)
        #pragma unroll
        for (int h2 = 0; h2 < 2; h2++) {
            int m = m0 + wm + mt * 16 + gid + h2 * 8;
            #pragma unroll
            for (int nt = 0; nt < NT2; nt++) {
                int oc = wn2 + nt * 8 + tq;
                float v0 = acc2[mt][nt][h2 * 2], v1 = acc2[mt][nt][h2 * 2 + 1];
                if (OUTM == 0) {
                    bf16 h0 = __float2bfloat16(v0), h1 = __float2bfloat16(v1);
                    bf16 l0 = __float2bfloat16(v0 - __bfloat162float(h0));
                    bf16 l1 = __float2bfloat16(v1 - __bfloat162float(h1));
                    size_t go = ((size_t)b * Mtot + m) * O2 + oc;
                    *(uint32_t*)(Oh + go) = pk(h0, h1);
                    *(uint32_t*)(Ol + go) = pk(l0, l1);
                } else {
                    Of[((size_t)b * O2 + oc)     * Mtot + m] = v0;
                    Of[((size_t)b * O2 + oc + 1) * Mtot + m] = v1;
                }
            }
        }
}

// ================= merged weight split =================
struct WSeg { const float* s; bf16* h; bf16* l; int n; };
struct WParams { WSeg w[10]; };

__global__ __launch_bounds__(256)
void wsplit_all(WParams p) {
    int gi = blockIdx.x * 256 + threadIdx.x;
    #pragma unroll
    for (int s = 0; s < 10; s++) {
        int n = p.w[s].n;
        if (gi < n) {
            float v = p.w[s].s[gi];
            bf16 hv = __float2bfloat16(v);
            p.w[s].h[gi] = hv;
            p.w[s].l[gi] = __float2bfloat16(v - __bfloat162float(hv));
            return;
        }
        gi -= n;
    }
}

// ================= attention =================
static DIB float wsum(float v) {
    #pragma unroll
    for (int o = 16; o > 0; o >>= 1) v += __shfl_xor_sync(0xffffffffu, v, o);
    return v;
}
static DIB float sigm(float x) { return 1.0f / (1.0f + __expf(-x)); }
static DIB float rd2(const bf16* h, const bf16* l, size_t i) {
    return __bfloat162float(h[i]) + __bfloat162float(l[i]);
}
static DIB void wr2(bf16* h, bf16* l, size_t i, float v) {
    bf16 x = __float2bfloat16(v);
    h[i] = x;
    l[i] = __float2bfloat16(v - __bfloat162float(x));
}

__global__ __launch_bounds__(128)
void attend_k(const bf16* __restrict__ eah, const bf16* __restrict__ eal,
              const float* __restrict__ gateb, const float* __restrict__ gatec,
              const bf16* __restrict__ ebh, const bf16* __restrict__ ebl,
              const bf16* __restrict__ ech, const bf16* __restrict__ ecl,
              const float* __restrict__ Wab, const float* __restrict__ Wac,
              bf16* __restrict__ agh, bf16* __restrict__ agl)
{
    int gw = (blockIdx.x * 128 + threadIdx.x) >> 5;
    int lane = threadIdx.x & 31;
    int b = gw >> 12, n = gw & 4095;
    int h = n >> 6, w = n & 63;
    size_t nb = (size_t)b * 4096 + n;

    float ea[4], gb[4], gc[4];
    float pab = 0.f, pac = 0.f;
    #pragma unroll
    for (int j = 0; j < 4; j++) {
        int cc = lane + 32 * j;
        ea[j] = rd2(eah, eal, nb * 128 + cc);
        gb[j] = gateb[nb * 128 + cc];
        gc[j] = gatec[nb * 128 + cc];
        pab += Wab[cc] * ea[j];
        pac += Wac[cc] * ea[j];
    }
    float dab = wsum(pab), dac = wsum(pac);

    { // B branch
        float eb[4][4], lb[4];
        #pragma unroll
        for (int p = 0; p < 4; p++) {
            int kh = p >> 1, kw = p & 1;
            size_t base = ((size_t)b * 16384 + (size_t)(2*h + kh) * 128 + (2*w + kw)) * 128;
            float s = 0.f;
            #pragma unroll
            for (int j = 0; j < 4; j++) {
                int cc = lane + 32 * j;
                eb[p][j] = rd2(ebh, ebl, base + cc);
                s += Wab[128 + cc] * eb[p][j];
            }
            lb[p] = fmaxf(dab + wsum(s), 0.0f);
        }
        float mx = fmaxf(fmaxf(lb[0], lb[1]), fmaxf(lb[2], lb[3]));
        float ss = 0.f;
        #pragma unroll
        for (int p = 0; p < 4; p++) { lb[p] = __expf(lb[p] - mx); ss += lb[p]; }
        float inv = 1.0f / ss;
        #pragma unroll
        for (int j = 0; j < 4; j++) {
            float a = 0.f;
            #pragma unroll
            for (int p = 0; p < 4; p++) a += eb[p][j] * lb[p];
            wr2(agh, agl, nb * 384 + lane + 32 * j, sigm(a * inv * gb[j]));
        }
    }
    { // C branch
        float ec[16][4], lc[16];
        #pragma unroll
        for (int p = 0; p < 16; p++) {
            int kh = p >> 2, kw = p & 3;
            size_t base = ((size_t)b * 65536 + (size_t)(4*h + kh) * 256 + (4*w + kw)) * 128;
            float s = 0.f;
            #pragma unroll
            for (int j = 0; j < 4; j++) {
                int cc = lane + 32 * j;
                ec[p][j] = rd2(ech, ecl, base + cc);
                s += Wac[128 + cc] * ec[p][j];
            }
            lc[p] = fmaxf(dac + wsum(s), 0.0f);
        }
        float mx = lc[0];
        #pragma unroll
        for (int p = 1; p < 16; p++) mx = fmaxf(mx, lc[p]);
        float ss = 0.f;
        #pragma unroll
        for (int p = 0; p < 16; p++) { lc[p] = __expf(lc[p] - mx); ss += lc[p]; }
        float inv = 1.0f / ss;
        #pragma unroll
        for (int j = 0; j < 4; j++) {
            float a = 0.f;
            #pragma unroll
            for (int p = 0; p < 16; p++) a += ec[p][j] * lc[p];
            wr2(agh, agl, nb * 384 + 128 + lane + 32 * j, sigm(a * inv * gc[j]));
        }
    }
    #pragma unroll
    for (int j = 0; j < 4; j++)
        wr2(agh, agl, nb * 384 + 256 + lane + 32 * j, sigm(ea[j]));
}

// ================= launch =================
static inline int imax(int a, int b) { return a > b ? a : b; }
static inline int fsz1(int K1, int O1M, int NG, int O2) {   // XMODE1 bytes
    int O1T = O1M + NG * 128, WR = imax(O1T, O2);
    int staging_units = K1 * 68 * 2;                         // fp32 staging in bf16 units
    int units = 2*64*(K1+8) + 2*(2*WR*40) + 2*64*(O1M+8);
    int with_staging = 2*64*(K1+8) + 2*WR*40 + staging_units; // staging overlays stage-1
    return imax(units, with_staging) * 2;
}
static inline int fsz0(int O1M, int NG, int O2) {           // XMODE0 bytes
    int O1T = O1M + NG * 128, WR = imax(O1T, O2);
    int XPL = 64 * 40, WPL = WR * 40;
    int STG = 2 * XPL + 2 * WPL;
    return (2 * STG + 2 * 64 * (O1M + 8)) * 2;
}

extern "C" void kernel_launch(void* const* d_in, const int* in_sizes, int n_in,
                              void* d_out, int out_size)
{
    const float* va  = (const float*)d_in[0];
    const float* vb  = (const float*)d_in[1];
    const float* vc  = (const float*)d_in[2];
    const float* Wa1 = (const float*)d_in[3];
    const float* Wa2 = (const float*)d_in[4];
    const float* Wgb = (const float*)d_in[5];
    const float* Wgc = (const float*)d_in[6];
    const float* Wb1 = (const float*)d_in[7];
    const float* Wb2 = (const float*)d_in[8];
    const float* Wc1 = (const float*)d_in[9];
    const float* Wc2 = (const float*)d_in[10];
    const float* Wab = (const float*)d_in[11];
    const float* Wac = (const float*)d_in[12];
    const float* Wr1 = (const float*)d_in[13];
    const float* Wr2 = (const float*)d_in[14];
    float* out = (float*)d_out;

    bf16 *eah,*eal,*ebh,*ebl,*ech,*ecl,*agh,*agl;
    float *gb,*gc;
    bf16 *WAh,*WAl,*Wa2h,*Wa2l,*Wb1h,*Wb1l,*Wb2h,*Wb2l,*Wc1h,*Wc1l,*Wc2h,*Wc2l,
         *Wr1h,*Wr1l,*Wr2h,*Wr2l;
    cudaGetSymbolAddress((void**)&eah,g_eah); cudaGetSymbolAddress((void**)&eal,g_eal);
    cudaGetSymbolAddress((void**)&gb,g_gb);   cudaGetSymbolAddress((void**)&gc,g_gc);
    cudaGetSymbolAddress((void**)&ebh,g_ebh); cudaGetSymbolAddress((void**)&ebl,g_ebl);
    cudaGetSymbolAddress((void**)&ech,g_ech); cudaGetSymbolAddress((void**)&ecl,g_ecl);
    cudaGetSymbolAddress((void**)&agh,g_agh); cudaGetSymbolAddress((void**)&agl,g_agl);
    cudaGetSymbolAddress((void**)&WAh,g_WAh); cudaGetSymbolAddress((void**)&WAl,g_WAl);
    cudaGetSymbolAddress((void**)&Wa2h,g_Wa2h); cudaGetSymbolAddress((void**)&Wa2l,g_Wa2l);
    cudaGetSymbolAddress((void**)&Wb1h,g_Wb1h); cudaGetSymbolAddress((void**)&Wb1l,g_Wb1l);
    cudaGetSymbolAddress((void**)&Wb2h,g_Wb2h); cudaGetSymbolAddress((void**)&Wb2l,g_Wb2l);
    cudaGetSymbolAddress((void**)&Wc1h,g_Wc1h); cudaGetSymbolAddress((void**)&Wc1l,g_Wc1l);
    cudaGetSymbolAddress((void**)&Wc2h,g_Wc2h); cudaGetSymbolAddress((void**)&Wc2l,g_Wc2l);
    cudaGetSymbolAddress((void**)&Wr1h,g_Wr1h); cudaGetSymbolAddress((void**)&Wr1l,g_Wr1l);
    cudaGetSymbolAddress((void**)&Wr2h,g_Wr2h); cudaGetSymbolAddress((void**)&Wr2l,g_Wr2l);

    int sA = fsz1(256, 128, 2, 128);
    int sB = fsz1(128, 128, 0, 128);
    int sC = fsz1( 64, 128, 0, 128);
    int sR = fsz0(256, 0, 256);
    cudaFuncSetAttribute(fuse_k<256,128,2,128,1,0,1>, cudaFuncAttributeMaxDynamicSharedMemorySize, sA);
    cudaFuncSetAttribute(fuse_k<128,128,0,128,2,0,1>, cudaFuncAttributeMaxDynamicSharedMemorySize, sB);
    cudaFuncSetAttribute(fuse_k< 64,128,0,128,2,0,1>, cudaFuncAttributeMaxDynamicSharedMemorySize, sC);
    cudaFuncSetAttribute(fuse_k<384,256,0,256,1,2,0>, cudaFuncAttributeMaxDynamicSharedMemorySize, sR);

    // weight splits (one kernel)
    WParams P;
    P.w[0] = {Wa1, WAh,           WAl,           32768};
    P.w[1] = {Wgb, WAh + 32768,   WAl + 32768,   32768};
    P.w[2] = {Wgc, WAh + 65536,   WAl + 65536,   32768};
    P.w[3] = {Wa2, Wa2h, Wa2l, 16384};
    P.w[4] = {Wb1, Wb1h, Wb1l, 16384};
    P.w[5] = {Wb2, Wb2h, Wb2l, 16384};
    P.w[6] = {Wc1, Wc1h, Wc1l, 8192};
    P.w[7] = {Wc2, Wc2h, Wc2l, 16384};
    P.w[8] = {Wr1, Wr1h, Wr1l, 98304};
    P.w[9] = {Wr2, Wr2h, Wr2l, 65536};
    wsplit_all<<<(335872 + 255) / 256, 256>>>(P);

    // a-stage (fp32 X direct)
    fuse_k<256,128,2,128,1,0,1><<<dim3(64, 1, NB), 256, sA>>>(
        va, nullptr, nullptr, WAh, WAl, Wa2h, Wa2l, gb, gc, eah, eal, nullptr, 4096);
    // b-stage
    fuse_k<128,128,0,128,2,0,1><<<dim3(256, 1, NB), 256, sB>>>(
        vb, nullptr, nullptr, Wb1h, Wb1l, Wb2h, Wb2l, nullptr, nullptr, ebh, ebl, nullptr, 16384);
    // c-stage
    fuse_k< 64,128,0,128,2,0,1><<<dim3(1024, 1, NB), 256, sC>>>(
        vc, nullptr, nullptr, Wc1h, Wc1l, Wc2h, Wc2l, nullptr, nullptr, ech, ecl, nullptr, 65536);

    attend_k<<<8192, 128>>>(eah, eal, gb, gc, ebh, ebl, ech, ecl, Wab, Wac, agh, agl);

    // readout (bf16 hi/lo X)
    fuse_k<384,256,0,256,1,2,0><<<dim3(64, 1, NB), 256, sR>>>(
        nullptr, agh, agl, Wr1h, Wr1l, Wr2h, Wr2l, nullptr, nullptr, nullptr, nullptr, out, 4096);
}

// round 12
// speedup vs baseline: 1.8909x; 1.0364x over previous
#include <cuda_runtime.h>
#include <cuda_bf16.h>
#include <cstdint>

using bf16 = __nv_bfloat16;
#define DIB __device__ __forceinline__
#define NB 8

// ================= scratch (device globals) =================
__device__ __align__(16) bf16 g_eah[(size_t)NB*4096*128],  g_eal[(size_t)NB*4096*128];
__device__ __align__(16) float g_gb[(size_t)NB*4096*128],  g_gc[(size_t)NB*4096*128];
__device__ __align__(16) bf16 g_ebh[(size_t)NB*16384*128], g_ebl[(size_t)NB*16384*128];
__device__ __align__(16) bf16 g_ech[(size_t)NB*65536*128], g_ecl[(size_t)NB*65536*128];
__device__ __align__(16) bf16 g_agh[(size_t)NB*4096*384],  g_agl[(size_t)NB*4096*384];
__device__ __align__(16) bf16 g_WAh[384*256],  g_WAl[384*256];   // Wa1|Wgb|Wgc stacked
__device__ __align__(16) bf16 g_Wa2h[128*128], g_Wa2l[128*128];
__device__ __align__(16) bf16 g_Wb1h[128*128], g_Wb1l[128*128];
__device__ __align__(16) bf16 g_Wb2h[128*128], g_Wb2l[128*128];
__device__ __align__(16) bf16 g_Wc1h[128*64],  g_Wc1l[128*64];
__device__ __align__(16) bf16 g_Wc2h[128*128], g_Wc2l[128*128];
__device__ __align__(16) bf16 g_Wr1h[256*384], g_Wr1l[256*384];
__device__ __align__(16) bf16 g_Wr2h[256*256], g_Wr2l[256*256];

// ================= helpers =================
static DIB uint32_t smem_u32(const void* p) {
    uint32_t a;
    asm("{ .reg .u64 t; cvta.to.shared.u64 t, %1; cvt.u32.u64 %0, t; }" : "=r"(a) : "l"(p));
    return a;
}
static DIB void cpa16(uint32_t s, const void* g) {
    asm volatile("cp.async.ca.shared.global [%0],[%1],16;" :: "r"(s), "l"(g) : "memory");
}
#define CPA_COMMIT() asm volatile("cp.async.commit_group;" ::: "memory")
#define CPA_WAIT(N)  asm volatile("cp.async.wait_group " #N ";" ::: "memory")
static DIB void ldsm4(uint32_t* r, uint32_t a) {
    asm volatile("ldmatrix.sync.aligned.m8n8.x4.shared.b16 {%0,%1,%2,%3},[%4];"
        : "=r"(r[0]), "=r"(r[1]), "=r"(r[2]), "=r"(r[3]) : "r"(a));
}
static DIB void mma16816(float* d, const uint32_t* a, const uint32_t* b) {
    asm volatile(
        "mma.sync.aligned.m16n8k16.row.col.f32.bf16.bf16.f32 "
        "{%0,%1,%2,%3}, {%4,%5,%6,%7}, {%8,%9}, {%0,%1,%2,%3};"
        : "+f"(d[0]), "+f"(d[1]), "+f"(d[2]), "+f"(d[3])
        : "r"(a[0]), "r"(a[1]), "r"(a[2]), "r"(a[3]), "r"(b[0]), "r"(b[1]));
}
static DIB uint32_t pk(bf16 lo, bf16 hi) {
    return (uint32_t)__bfloat16_as_ushort(lo) | ((uint32_t)__bfloat16_as_ushort(hi) << 16);
}

// acc += Ah*(Bh+Bl) + Al*Bh over CHT k-elems
template<int STA, int STB, int NT, int CHT>
static DIB void mma_blk(float (&acc)[2][NT][4], uint32_t aH, uint32_t aL,
                        uint32_t bH, uint32_t bL)
{
    #pragma unroll
    for (int ks = 0; ks < CHT; ks += 16) {
        uint32_t Ah[2][4], Al[2][4], Bh[NT/2][4], Bl[NT/2][4];
        #pragma unroll
        for (int mt = 0; mt < 2; mt++) {
            ldsm4(Ah[mt], aH + (uint32_t)(mt*16*STA + ks) * 2);
            ldsm4(Al[mt], aL + (uint32_t)(mt*16*STA + ks) * 2);
        }
        #pragma unroll
        for (int g = 0; g < NT/2; g++) {
            ldsm4(Bh[g], bH + (uint32_t)(g*16*STB + ks) * 2);
            ldsm4(Bl[g], bL + (uint32_t)(g*16*STB + ks) * 2);
        }
        #pragma unroll
        for (int nt = 0; nt < NT; nt++) {
            uint32_t bh[2] = {Bh[nt>>1][(nt&1)*2], Bh[nt>>1][(nt&1)*2+1]};
            uint32_t bl[2] = {Bl[nt>>1][(nt&1)*2], Bl[nt>>1][(nt&1)*2+1]};
            #pragma unroll
            for (int mt = 0; mt < 2; mt++) {
                mma16816(acc[mt][nt], Ah[mt], bh);
                mma16816(acc[mt][nt], Ah[mt], bl);
                mma16816(acc[mt][nt], Al[mt], bh);
            }
        }
    }
}

// ================= unified fused 2-layer GEMM (a/b/readout) =================
template<int K1, int O1M, int NG, int O2, int OCC, int OUTM, int XMODE>
__global__ __launch_bounds__(256, OCC)
void fuse_k(const float* __restrict__ Xf,
            const bf16* __restrict__ Xh, const bf16* __restrict__ Xl,
            const bf16* __restrict__ W1h, const bf16* __restrict__ W1l,
            const bf16* __restrict__ W2h, const bf16* __restrict__ W2l,
            float* __restrict__ gate0, float* __restrict__ gate1,
            bf16* __restrict__ Oh, bf16* __restrict__ Ol, float* __restrict__ Of,
            int Mtot)
{
    constexpr int BM = 64, CH = 32, WST = 40;
    constexpr int O1T = O1M + NG * 128;
    constexpr int WR  = (O1T > O2) ? O1T : O2;
    constexpr int HST = O1M + 8;
    constexpr int WPL = WR * WST;
    constexpr int AST = K1 + 8;
    constexpr int APL = BM * AST;
    constexpr int XST = 40;
    constexpr int XPL = BM * XST;
    constexpr int STG  = (XMODE == 1) ? (2 * WPL) : (2 * XPL + 2 * WPL);
    constexpr int SOFF = (XMODE == 1) ? (2 * APL) : 0;
    constexpr int WIN  = (XMODE == 1) ? 0 : (2 * XPL);
    constexpr int HOFFn = SOFF + 2 * STG;
    constexpr int NC1 = K1 / CH, NC2 = O1M / CH;
    constexpr int NT1 = O1T / 32, NT2 = O2 / 32;

    extern __shared__ bf16 smm[];
    const int tid = threadIdx.x, lane = tid & 31, warp = tid >> 5;
    const int gid = lane >> 2, tq = (lane & 3) * 2;
    const int wm  = (warp >> 2) * 32;
    const int wn1 = (warp & 3) * (NT1 * 8);
    const int wn2 = (warp & 3) * (NT2 * 8);
    const int b = blockIdx.z, m0 = blockIdx.x * BM;
    const uint32_t su = smem_u32(smm);

    const int arow = (lane & 7) + ((lane >> 3) & 1) * 8;
    const int acol = (lane >> 4) * 8;
    const int brow = (lane & 7) + (lane >> 4) * 8;
    const int bcol = ((lane >> 3) & 1) * 8;

    auto load1 = [&](int kc, int s) {
        uint32_t wb = su + (uint32_t)(SOFF + s * STG + WIN) * 2;
        if constexpr (XMODE == 0) {
            uint32_t base = su + (uint32_t)(s * STG) * 2;
            const bf16* Xhb = Xh + ((size_t)b * Mtot + m0) * K1;
            const bf16* Xlb = Xl + ((size_t)b * Mtot + m0) * K1;
            #pragma unroll
            for (int i = tid; i < BM * 4; i += 256) {
                int r = i >> 2, c = (i & 3) * 8;
                cpa16(base + (uint32_t)(r * XST + c) * 2,       Xhb + (size_t)r * K1 + kc + c);
                cpa16(base + (uint32_t)(XPL + r * XST + c) * 2, Xlb + (size_t)r * K1 + kc + c);
            }
        }
        #pragma unroll
        for (int i = tid; i < O1T * 4; i += 256) {
            int r = i >> 2, c = (i & 3) * 8;
            cpa16(wb + (uint32_t)(r * WST + c) * 2,       W1h + (size_t)r * K1 + kc + c);
            cpa16(wb + (uint32_t)(WPL + r * WST + c) * 2, W1l + (size_t)r * K1 + kc + c);
        }
        CPA_COMMIT();
    };
    auto load2 = [&](int kc, int s) {
        uint32_t wb = su + (uint32_t)(SOFF + s * STG + WIN) * 2;
        #pragma unroll
        for (int i = tid; i < O2 * 4; i += 256) {
            int r = i >> 2, c = (i & 3) * 8;
            cpa16(wb + (uint32_t)(r * WST + c) * 2,       W2h + (size_t)r * O1M + kc + c);
            cpa16(wb + (uint32_t)(WPL + r * WST + c) * 2, W2l + (size_t)r * O1M + kc + c);
        }
        CPA_COMMIT();
    };

    if constexpr (XMODE == 1) {
        constexpr int SST_OFF = SOFF + STG;
        uint32_t sbase = su + (uint32_t)SST_OFF * 2;
        const float* Xg = Xf + (size_t)b * K1 * Mtot + m0;
        #pragma unroll
        for (int i = tid; i < K1 * 16; i += 256) {
            int r = i >> 4, c4 = (i & 15) * 4;
            cpa16(sbase + (uint32_t)(r * 68 + c4) * 4, Xg + (size_t)r * Mtot + c4);
        }
        CPA_COMMIT();
        load1(0, 0);
        CPA_WAIT(1);
        __syncthreads();
        const float* stg = (const float*)(smm + SST_OFF);
        int m = tid & 63, k0 = (tid >> 6) * (K1 / 4);
        #pragma unroll
        for (int j = 0; j < K1 / 4; j += 2) {
            int k = k0 + j;
            float v0 = stg[k * 68 + m], v1 = stg[(k + 1) * 68 + m];
            bf16 h0 = __float2bfloat16(v0), h1 = __float2bfloat16(v1);
            bf16 l0 = __float2bfloat16(v0 - __bfloat162float(h0));
            bf16 l1 = __float2bfloat16(v1 - __bfloat162float(h1));
            *(uint32_t*)&smm[(size_t)m * AST + k]       = pk(h0, h1);
            *(uint32_t*)&smm[(size_t)APL + m * AST + k] = pk(l0, l1);
        }
        __syncthreads();
    } else {
        load1(0, 0);
    }

    float acc1[2][NT1][4];
    #pragma unroll
    for (int mt = 0; mt < 2; mt++)
        #pragma unroll
        for (int nt = 0; nt < NT1; nt++)
            #pragma unroll
            for (int q = 0; q < 4; q++) acc1[mt][nt][q] = 0.f;

    for (int ki = 0; ki < NC1; ki++) {
        if (ki + 1 < NC1) { load1((ki + 1) * CH, (ki + 1) & 1); CPA_WAIT(1); }
        else              { CPA_WAIT(0); }
        __syncthreads();
        uint32_t aH, aL;
        if constexpr (XMODE == 1) {
            aH = su + (uint32_t)((wm + arow) * AST + acol + ki * CH) * 2;
            aL = aH + (uint32_t)APL * 2;
        } else {
            uint32_t base = su + (uint32_t)((ki & 1) * STG) * 2;
            aH = base + (uint32_t)((wm + arow) * XST + acol) * 2;
            aL = aH + (uint32_t)XPL * 2;
        }
        uint32_t wb = su + (uint32_t)(SOFF + (ki & 1) * STG + WIN) * 2;
        uint32_t bH = wb + (uint32_t)((wn1 + brow) * WST + bcol) * 2;
        uint32_t bL = bH + (uint32_t)WPL * 2;
        mma_blk<(XMODE == 1 ? AST : XST), WST, NT1, CH>(acc1, aH, aL, bH, bL);
        __syncthreads();
    }

    load2(0, 0);

    #pragma unroll
    for (int mt = 0; mt < 2; mt++)
        #pragma unroll
        for (int h2 = 0; h2 < 2; h2++) {
            int ml = wm + mt * 16 + gid + h2 * 8;
            #pragma unroll
            for (int nt = 0; nt < NT1; nt++) {
                int oc = wn1 + nt * 8 + tq;
                float v0 = acc1[mt][nt][h2 * 2], v1 = acc1[mt][nt][h2 * 2 + 1];
                if (NG == 0 || oc < O1M) {
                    v0 = fmaxf(v0, 0.f); v1 = fmaxf(v1, 0.f);
                    bf16 h0 = __float2bfloat16(v0), h1 = __float2bfloat16(v1);
                    bf16 l0 = __float2bfloat16(v0 - __bfloat162float(h0));
                    bf16 l1 = __float2bfloat16(v1 - __bfloat162float(h1));
                    *(uint32_t*)&smm[HOFFn + ml * HST + oc]            = pk(h0, h1);
                    *(uint32_t*)&smm[HOFFn + BM * HST + ml * HST + oc] = pk(l0, l1);
                } else {
                    int g = (oc - O1M) >> 7;
                    float* gp = (g ? gate1 : gate0) + ((size_t)b * Mtot + m0 + ml) * 128 + (oc & 127);
                    *(float2*)gp = make_float2(1.0f / (1.0f + __expf(v0)),
                                               1.0f / (1.0f + __expf(v1)));
                }
            }
        }
    __syncthreads();

    float acc2[2][NT2][4];
    #pragma unroll
    for (int mt = 0; mt < 2; mt++)
        #pragma unroll
        for (int nt = 0; nt < NT2; nt++)
            #pragma unroll
            for (int q = 0; q < 4; q++) acc2[mt][nt][q] = 0.f;

    for (int ki = 0; ki < NC2; ki++) {
        if (ki + 1 < NC2) { load2((ki + 1) * CH, (ki + 1) & 1); CPA_WAIT(1); }
        else              { CPA_WAIT(0); }
        __syncthreads();
        uint32_t aH = su + (uint32_t)(HOFFn + (wm + arow) * HST + acol + ki * CH) * 2;
        uint32_t aL = aH + (uint32_t)(BM * HST) * 2;
        uint32_t wb = su + (uint32_t)(SOFF + (ki & 1) * STG + WIN) * 2;
        uint32_t bH = wb + (uint32_t)((wn2 + brow) * WST + bcol) * 2;
        uint32_t bL = bH + (uint32_t)WPL * 2;
        mma_blk<HST, WST, NT2, CH>(acc2, aH, aL, bH, bL);
        __syncthreads();
    }

    #pragma unroll
    for (int mt = 0; mt < 2; mt++)
        #pragma unroll
        for (int h2 = 0; h2 < 2; h2++) {
            int m = m0 + wm + mt * 16 + gid + h2 * 8;
            #pragma unroll
            for (int nt = 0; nt < NT2; nt++) {
                int oc = wn2 + nt * 8 + tq;
                float v0 = acc2[mt][nt][h2 * 2], v1 = acc2[mt][nt][h2 * 2 + 1];
                if (OUTM == 0) {
                    bf16 h0 = __float2bfloat16(v0), h1 = __float2bfloat16(v1);
                    bf16 l0 = __float2bfloat16(v0 - __bfloat162float(h0));
                    bf16 l1 = __float2bfloat16(v1 - __bfloat162float(h1));
                    size_t go = ((size_t)b * Mtot + m) * O2 + oc;
                    *(uint32_t*)(Oh + go) = pk(h0, h1);
                    *(uint32_t*)(Ol + go) = pk(l0, l1);
                } else {
                    Of[((size_t)b * O2 + oc)     * Mtot + m] = v0;
                    Of[((size_t)b * O2 + oc + 1) * Mtot + m] = v1;
                }
            }
        }
}

// ================= persistent-weight c-stage kernel =================
// K1=64, O1=128, O2=128, BM=64. Weights resident in SMEM; loop over M-tiles
// with double-buffered fp32 X staging.
#define C_TILES 8192
#define C_GRID  1024
// smem layout (bf16 units)
#define C_W1H 0
#define C_W1L 9216
#define C_W2H 18432
#define C_W2L 35840
#define C_AH  53248
#define C_AL  57856
#define C_HH  62464
#define C_HL  71168
#define C_STG 79872         // 2 buffers of 8704 units (fp32 64x68)
#define C_UNITS 97280       // 194560 bytes

__global__ __launch_bounds__(256, 1)
void cpers_k(const float* __restrict__ Xf,
             const bf16* __restrict__ W1h, const bf16* __restrict__ W1l,
             const bf16* __restrict__ W2h, const bf16* __restrict__ W2l,
             bf16* __restrict__ Oh, bf16* __restrict__ Ol)
{
    extern __shared__ bf16 smm[];
    const int tid = threadIdx.x, lane = tid & 31, warp = tid >> 5;
    const int gid = lane >> 2, tq = (lane & 3) * 2;
    const int wm = (warp >> 2) * 32, wn = (warp & 3) * 32;
    const uint32_t su = smem_u32(smm);

    const int arow = (lane & 7) + ((lane >> 3) & 1) * 8;
    const int acol = (lane >> 4) * 8;
    const int brow = (lane & 7) + (lane >> 4) * 8;
    const int bcol = ((lane >> 3) & 1) * 8;

    // ---- load all weights (once) ----
    #pragma unroll
    for (int i = tid; i < 128 * 8; i += 256) {      // W1: 128 rows x 64 (8x16B)
        int r = i >> 3, c = (i & 7) * 8;
        cpa16(su + (uint32_t)(C_W1H + r * 72 + c) * 2, W1h + (size_t)r * 64 + c);
        cpa16(su + (uint32_t)(C_W1L + r * 72 + c) * 2, W1l + (size_t)r * 64 + c);
    }
    #pragma unroll
    for (int i = tid; i < 128 * 16; i += 256) {     // W2: 128 rows x 128 (16x16B)
        int r = i >> 4, c = (i & 15) * 8;
        cpa16(su + (uint32_t)(C_W2H + r * 136 + c) * 2, W2h + (size_t)r * 128 + c);
        cpa16(su + (uint32_t)(C_W2L + r * 136 + c) * 2, W2l + (size_t)r * 128 + c);
    }
    CPA_COMMIT();

    auto stage = [&](int t, int s) {
        int b = t >> 10, mi = (t & 1023) << 6;
        const float* Xg = Xf + (size_t)b * 64 * 65536 + mi;
        uint32_t sbase = su + (uint32_t)(C_STG + s * 8704) * 2;
        #pragma unroll
        for (int i = tid; i < 64 * 16; i += 256) {
            int r = i >> 4, c4 = (i & 15) * 4;
            cpa16(sbase + (uint32_t)(r * 68 + c4) * 4, Xg + (size_t)r * 65536 + c4);
        }
        CPA_COMMIT();
    };

    stage(blockIdx.x, 0);   // first tile's X behind the weights
    CPA_WAIT(0);
    __syncthreads();

    int cur = 0;
    for (int t = blockIdx.x, it = 0; t < C_TILES; t += C_GRID, it++) {
        if (it > 0) { CPA_WAIT(0); __syncthreads(); }

        // ---- transpose + split staging -> A ----
        {
            const float* stg = (const float*)(smm + C_STG + cur * 8704);
            int m = tid & 63, k0 = (tid >> 6) * 16;
            #pragma unroll
            for (int j = 0; j < 16; j += 2) {
                int k = k0 + j;
                float v0 = stg[k * 68 + m], v1 = stg[(k + 1) * 68 + m];
                bf16 h0 = __float2bfloat16(v0), h1 = __float2bfloat16(v1);
                bf16 l0 = __float2bfloat16(v0 - __bfloat162float(h0));
                bf16 l1 = __float2bfloat16(v1 - __bfloat162float(h1));
                *(uint32_t*)&smm[C_AH + m * 72 + k] = pk(h0, h1);
                *(uint32_t*)&smm[C_AL + m * 72 + k] = pk(l0, l1);
            }
        }
        __syncthreads();

        if (t + C_GRID < C_TILES) stage(t + C_GRID, cur ^ 1);   // prefetch next X

        // ---- GEMM1: K=64, resident A x resident W1 ----
        float acc1[2][4][4];
        #pragma unroll
        for (int mt = 0; mt < 2; mt++)
            #pragma unroll
            for (int nt = 0; nt < 4; nt++)
                #pragma unroll
                for (int q = 0; q < 4; q++) acc1[mt][nt][q] = 0.f;
        {
            uint32_t aH = su + (uint32_t)(C_AH + (wm + arow) * 72 + acol) * 2;
            uint32_t aL = su + (uint32_t)(C_AL + (wm + arow) * 72 + acol) * 2;
            uint32_t bH = su + (uint32_t)(C_W1H + (wn + brow) * 72 + bcol) * 2;
            uint32_t bL = su + (uint32_t)(C_W1L + (wn + brow) * 72 + bcol) * 2;
            mma_blk<72, 72, 4, 64>(acc1, aH, aL, bH, bL);
        }

        // ---- relu + split -> h ----
        #pragma unroll
        for (int mt = 0; mt < 2; mt++)
            #pragma unroll
            for (int h2 = 0; h2 < 2; h2++) {
                int ml = wm + mt * 16 + gid + h2 * 8;
                #pragma unroll
                for (int nt = 0; nt < 4; nt++) {
                    int oc = wn + nt * 8 + tq;
                    float v0 = fmaxf(acc1[mt][nt][h2 * 2],     0.f);
                    float v1 = fmaxf(acc1[mt][nt][h2 * 2 + 1], 0.f);
                    bf16 h0 = __float2bfloat16(v0), h1 = __float2bfloat16(v1);
                    bf16 l0 = __float2bfloat16(v0 - __bfloat162float(h0));
                    bf16 l1 = __float2bfloat16(v1 - __bfloat162float(h1));
                    *(uint32_t*)&smm[C_HH + ml * 136 + oc] = pk(h0, h1);
                    *(uint32_t*)&smm[C_HL + ml * 136 + oc] = pk(l0, l1);
                }
            }
        __syncthreads();

        // ---- GEMM2: K=128, h x resident W2 ----
        float acc2[2][4][4];
        #pragma unroll
        for (int mt = 0; mt < 2; mt++)
            #pragma unroll
            for (int nt = 0; nt < 4; nt++)
                #pragma unroll
                for (int q = 0; q < 4; q++) acc2[mt][nt][q] = 0.f;
        {
            uint32_t aH = su + (uint32_t)(C_HH + (wm + arow) * 136 + acol) * 2;
            uint32_t aL = su + (uint32_t)(C_HL + (wm + arow) * 136 + acol) * 2;
            uint32_t bH = su + (uint32_t)(C_W2H + (wn + brow) * 136 + bcol) * 2;
            uint32_t bL = su + (uint32_t)(C_W2L + (wn + brow) * 136 + bcol) * 2;
            mma_blk<136, 136, 4, 128>(acc2, aH, aL, bH, bL);
        }

        // ---- output ----
        {
            int b = t >> 10, mi = (t & 1023) << 6;
            #pragma unroll
            for (int mt = 0; mt < 2; mt++)
                #pragma unroll
                for (int h2 = 0; h2 < 2; h2++) {
                    int m = mi + wm + mt * 16 + gid + h2 * 8;
                    #pragma unroll
                    for (int nt = 0; nt < 4; nt++) {
                        int oc = wn + nt * 8 + tq;
                        float v0 = acc2[mt][nt][h2 * 2], v1 = acc2[mt][nt][h2 * 2 + 1];
                        bf16 h0 = __float2bfloat16(v0), h1 = __float2bfloat16(v1);
                        bf16 l0 = __float2bfloat16(v0 - __bfloat162float(h0));
                        bf16 l1 = __float2bfloat16(v1 - __bfloat162float(h1));
                        size_t go = ((size_t)b * 65536 + m) * 128 + oc;
                        *(uint32_t*)(Oh + go) = pk(h0, h1);
                        *(uint32_t*)(Ol + go) = pk(l0, l1);
                    }
                }
        }
        cur ^= 1;
    }
}

// ================= merged weight split =================
struct WSeg { const float* s; bf16* h; bf16* l; int n; };
struct WParams { WSeg w[10]; };

__global__ __launch_bounds__(256)
void wsplit_all(WParams p) {
    int gi = blockIdx.x * 256 + threadIdx.x;
    #pragma unroll
    for (int s = 0; s < 10; s++) {
        int n = p.w[s].n;
        if (gi < n) {
            float v = p.w[s].s[gi];
            bf16 hv = __float2bfloat16(v);
            p.w[s].h[gi] = hv;
            p.w[s].l[gi] = __float2bfloat16(v - __bfloat162float(hv));
            return;
        }
        gi -= n;
    }
}

// ================= attention =================
static DIB float wsum(float v) {
    #pragma unroll
    for (int o = 16; o > 0; o >>= 1) v += __shfl_xor_sync(0xffffffffu, v, o);
    return v;
}
static DIB float sigm(float x) { return 1.0f / (1.0f + __expf(-x)); }
static DIB float rd2(const bf16* h, const bf16* l, size_t i) {
    return __bfloat162float(h[i]) + __bfloat162float(l[i]);
}
static DIB void wr2(bf16* h, bf16* l, size_t i, float v) {
    bf16 x = __float2bfloat16(v);
    h[i] = x;
    l[i] = __float2bfloat16(v - __bfloat162float(x));
}

__global__ __launch_bounds__(128)
void attend_k(const bf16* __restrict__ eah, const bf16* __restrict__ eal,
              const float* __restrict__ gateb, const float* __restrict__ gatec,
              const bf16* __restrict__ ebh, const bf16* __restrict__ ebl,
              const bf16* __restrict__ ech, const bf16* __restrict__ ecl,
              const float* __restrict__ Wab, const float* __restrict__ Wac,
              bf16* __restrict__ agh, bf16* __restrict__ agl)
{
    int gw = (blockIdx.x * 128 + threadIdx.x) >> 5;
    int lane = threadIdx.x & 31;
    int b = gw >> 12, n = gw & 4095;
    int h = n >> 6, w = n & 63;
    size_t nb = (size_t)b * 4096 + n;

    float ea[4], gb[4], gc[4];
    float pab = 0.f, pac = 0.f;
    #pragma unroll
    for (int j = 0; j < 4; j++) {
        int cc = lane + 32 * j;
        ea[j] = rd2(eah, eal, nb * 128 + cc);
        gb[j] = gateb[nb * 128 + cc];
        gc[j] = gatec[nb * 128 + cc];
        pab += Wab[cc] * ea[j];
        pac += Wac[cc] * ea[j];
    }
    float dab = wsum(pab), dac = wsum(pac);

    { // B branch
        float eb[4][4], lb[4];
        #pragma unroll
        for (int p = 0; p < 4; p++) {
            int kh = p >> 1, kw = p & 1;
            size_t base = ((size_t)b * 16384 + (size_t)(2*h + kh) * 128 + (2*w + kw)) * 128;
            float s = 0.f;
            #pragma unroll
            for (int j = 0; j < 4; j++) {
                int cc = lane + 32 * j;
                eb[p][j] = rd2(ebh, ebl, base + cc);
                s += Wab[128 + cc] * eb[p][j];
            }
            lb[p] = fmaxf(dab + wsum(s), 0.0f);
        }
        float mx = fmaxf(fmaxf(lb[0], lb[1]), fmaxf(lb[2], lb[3]));
        float ss = 0.f;
        #pragma unroll
        for (int p = 0; p < 4; p++) { lb[p] = __expf(lb[p] - mx); ss += lb[p]; }
        float inv = 1.0f / ss;
        #pragma unroll
        for (int j = 0; j < 4; j++) {
            float a = 0.f;
            #pragma unroll
            for (int p = 0; p < 4; p++) a += eb[p][j] * lb[p];
            wr2(agh, agl, nb * 384 + lane + 32 * j, sigm(a * inv * gb[j]));
        }
    }
    { // C branch
        float ec[16][4], lc[16];
        #pragma unroll
        for (int p = 0; p < 16; p++) {
            int kh = p >> 2, kw = p & 3;
            size_t base = ((size_t)b * 65536 + (size_t)(4*h + kh) * 256 + (4*w + kw)) * 128;
            float s = 0.f;
            #pragma unroll
            for (int j = 0; j < 4; j++) {
                int cc = lane + 32 * j;
                ec[p][j] = rd2(ech, ecl, base + cc);
                s += Wac[128 + cc] * ec[p][j];
            }
            lc[p] = fmaxf(dac + wsum(s), 0.0f);
        }
        float mx = lc[0];
        #pragma unroll
        for (int p = 1; p < 16; p++) mx = fmaxf(mx, lc[p]);
        float ss = 0.f;
        #pragma unroll
        for (int p = 0; p < 16; p++) { lc[p] = __expf(lc[p] - mx); ss += lc[p]; }
        float inv = 1.0f / ss;
        #pragma unroll
        for (int j = 0; j < 4; j++) {
            float a = 0.f;
            #pragma unroll
            for (int p = 0; p < 16; p++) a += ec[p][j] * lc[p];
            wr2(agh, agl, nb * 384 + 128 + lane + 32 * j, sigm(a * inv * gc[j]));
        }
    }
    #pragma unroll
    for (int j = 0; j < 4; j++)
        wr2(agh, agl, nb * 384 + 256 + lane + 32 * j, sigm(ea[j]));
}

// ================= launch =================
static inline int imax(int a, int b) { return a > b ? a : b; }
static inline int fsz1(int K1, int O1M, int NG, int O2) {
    int O1T = O1M + NG * 128, WR = imax(O1T, O2);
    int staging_units = K1 * 68 * 2;
    int units = 2*64*(K1+8) + 2*(2*WR*40) + 2*64*(O1M+8);
    int with_staging = 2*64*(K1+8) + 2*WR*40 + staging_units;
    return imax(units, with_staging) * 2;
}
static inline int fsz0(int O1M, int NG, int O2) {
    int O1T = O1M + NG * 128, WR = imax(O1T, O2);
    int XPL = 64 * 40, WPL = WR * 40;
    int STG = 2 * XPL + 2 * WPL;
    return (2 * STG + 2 * 64 * (O1M + 8)) * 2;
}

extern "C" void kernel_launch(void* const* d_in, const int* in_sizes, int n_in,
                              void* d_out, int out_size)
{
    const float* va  = (const float*)d_in[0];
    const float* vb  = (const float*)d_in[1];
    const float* vc  = (const float*)d_in[2];
    const float* Wa1 = (const float*)d_in[3];
    const float* Wa2 = (const float*)d_in[4];
    const float* Wgb = (const float*)d_in[5];
    const float* Wgc = (const float*)d_in[6];
    const float* Wb1 = (const float*)d_in[7];
    const float* Wb2 = (const float*)d_in[8];
    const float* Wc1 = (const float*)d_in[9];
    const float* Wc2 = (const float*)d_in[10];
    const float* Wab = (const float*)d_in[11];
    const float* Wac = (const float*)d_in[12];
    const float* Wr1 = (const float*)d_in[13];
    const float* Wr2 = (const float*)d_in[14];
    float* out = (float*)d_out;

    bf16 *eah,*eal,*ebh,*ebl,*ech,*ecl,*agh,*agl;
    float *gb,*gc;
    bf16 *WAh,*WAl,*Wa2h,*Wa2l,*Wb1h,*Wb1l,*Wb2h,*Wb2l,*Wc1h,*Wc1l,*Wc2h,*Wc2l,
         *Wr1h,*Wr1l,*Wr2h,*Wr2l;
    cudaGetSymbolAddress((void**)&eah,g_eah); cudaGetSymbolAddress((void**)&eal,g_eal);
    cudaGetSymbolAddress((void**)&gb,g_gb);   cudaGetSymbolAddress((void**)&gc,g_gc);
    cudaGetSymbolAddress((void**)&ebh,g_ebh); cudaGetSymbolAddress((void**)&ebl,g_ebl);
    cudaGetSymbolAddress((void**)&ech,g_ech); cudaGetSymbolAddress((void**)&ecl,g_ecl);
    cudaGetSymbolAddress((void**)&agh,g_agh); cudaGetSymbolAddress((void**)&agl,g_agl);
    cudaGetSymbolAddress((void**)&WAh,g_WAh); cudaGetSymbolAddress((void**)&WAl,g_WAl);
    cudaGetSymbolAddress((void**)&Wa2h,g_Wa2h); cudaGetSymbolAddress((void**)&Wa2l,g_Wa2l);
    cudaGetSymbolAddress((void**)&Wb1h,g_Wb1h); cudaGetSymbolAddress((void**)&Wb1l,g_Wb1l);
    cudaGetSymbolAddress((void**)&Wb2h,g_Wb2h); cudaGetSymbolAddress((void**)&Wb2l,g_Wb2l);
    cudaGetSymbolAddress((void**)&Wc1h,g_Wc1h); cudaGetSymbolAddress((void**)&Wc1l,g_Wc1l);
    cudaGetSymbolAddress((void**)&Wc2h,g_Wc2h); cudaGetSymbolAddress((void**)&Wc2l,g_Wc2l);
    cudaGetSymbolAddress((void**)&Wr1h,g_Wr1h); cudaGetSymbolAddress((void**)&Wr1l,g_Wr1l);
    cudaGetSymbolAddress((void**)&Wr2h,g_Wr2h); cudaGetSymbolAddress((void**)&Wr2l,g_Wr2l);

    int sA = fsz1(256, 128, 2, 128);
    int sB = fsz1(128, 128, 0, 128);
    int sR = fsz0(256, 0, 256);
    int sC = C_UNITS * 2;
    cudaFuncSetAttribute(fuse_k<256,128,2,128,1,0,1>, cudaFuncAttributeMaxDynamicSharedMemorySize, sA);
    cudaFuncSetAttribute(fuse_k<128,128,0,128,2,0,1>, cudaFuncAttributeMaxDynamicSharedMemorySize, sB);
    cudaFuncSetAttribute(fuse_k<384,256,0,256,1,2,0>, cudaFuncAttributeMaxDynamicSharedMemorySize, sR);
    cudaFuncSetAttribute(cpers_k, cudaFuncAttributeMaxDynamicSharedMemorySize, sC);

    WParams P;
    P.w[0] = {Wa1, WAh,           WAl,           32768};
    P.w[1] = {Wgb, WAh + 32768,   WAl + 32768,   32768};
    P.w[2] = {Wgc, WAh + 65536,   WAl + 65536,   32768};
    P.w[3] = {Wa2, Wa2h, Wa2l, 16384};
    P.w[4] = {Wb1, Wb1h, Wb1l, 16384};
    P.w[5] = {Wb2, Wb2h, Wb2l, 16384};
    P.w[6] = {Wc1, Wc1h, Wc1l, 8192};
    P.w[7] = {Wc2, Wc2h, Wc2l, 16384};
    P.w[8] = {Wr1, Wr1h, Wr1l, 98304};
    P.w[9] = {Wr2, Wr2h, Wr2l, 65536};
    wsplit_all<<<(335872 + 255) / 256, 256>>>(P);

    // a-stage (fp32 X direct)
    fuse_k<256,128,2,128,1,0,1><<<dim3(64, 1, NB), 256, sA>>>(
        va, nullptr, nullptr, WAh, WAl, Wa2h, Wa2l, gb, gc, eah, eal, nullptr, 4096);
    // b-stage
    fuse_k<128,128,0,128,2,0,1><<<dim3(256, 1, NB), 256, sB>>>(
        vb, nullptr, nullptr, Wb1h, Wb1l, Wb2h, Wb2l, nullptr, nullptr, ebh, ebl, nullptr, 16384);
    // c-stage (persistent weights)
    cpers_k<<<C_GRID, 256, sC>>>(vc, Wc1h, Wc1l, Wc2h, Wc2l, ech, ecl);

    attend_k<<<8192, 128>>>(eah, eal, gb, gc, ebh, ebl, ech, ecl, Wab, Wac, agh, agl);

    // readout (bf16 hi/lo X)
    fuse_k<384,256,0,256,1,2,0><<<dim3(64, 1, NB), 256, sR>>>(
        nullptr, agh, agl, Wr1h, Wr1l, Wr2h, Wr2l, nullptr, nullptr, nullptr, nullptr, out, 4096);
}

// round 13
// speedup vs baseline: 1.9176x; 1.0141x over previous
#include <cuda_runtime.h>
#include <cuda_bf16.h>
#include <cstdint>

using bf16 = __nv_bfloat16;
#define DIB __device__ __forceinline__
#define NB 8

// ================= scratch (device globals) =================
__device__ __align__(16) bf16 g_eah[(size_t)NB*4096*128],  g_eal[(size_t)NB*4096*128];
__device__ __align__(16) float g_gb[(size_t)NB*4096*128],  g_gc[(size_t)NB*4096*128];
__device__ __align__(16) bf16 g_ebh[(size_t)NB*16384*128], g_ebl[(size_t)NB*16384*128];
__device__ __align__(16) bf16 g_ech[(size_t)NB*65536*128], g_ecl[(size_t)NB*65536*128];
__device__ __align__(16) bf16 g_agh[(size_t)NB*4096*384],  g_agl[(size_t)NB*4096*384];
__device__ __align__(16) bf16 g_WAh[384*256],  g_WAl[384*256];   // Wa1|Wgb|Wgc stacked
__device__ __align__(16) bf16 g_Wa2h[128*128], g_Wa2l[128*128];
__device__ __align__(16) bf16 g_Wb1h[128*128], g_Wb1l[128*128];
__device__ __align__(16) bf16 g_Wb2h[128*128], g_Wb2l[128*128];
__device__ __align__(16) bf16 g_Wc1h[128*64],  g_Wc1l[128*64];
__device__ __align__(16) bf16 g_Wc2h[128*128], g_Wc2l[128*128];
__device__ __align__(16) bf16 g_Wr1h[256*384], g_Wr1l[256*384];
__device__ __align__(16) bf16 g_Wr2h[256*256], g_Wr2l[256*256];

// ================= helpers =================
static DIB uint32_t smem_u32(const void* p) {
    uint32_t a;
    asm("{ .reg .u64 t; cvta.to.shared.u64 t, %1; cvt.u32.u64 %0, t; }" : "=r"(a) : "l"(p));
    return a;
}
static DIB void cpa16(uint32_t s, const void* g) {
    asm volatile("cp.async.ca.shared.global [%0],[%1],16;" :: "r"(s), "l"(g) : "memory");
}
#define CPA_COMMIT() asm volatile("cp.async.commit_group;" ::: "memory")
#define CPA_WAIT(N)  asm volatile("cp.async.wait_group " #N ";" ::: "memory")
static DIB void ldsm4(uint32_t* r, uint32_t a) {
    asm volatile("ldmatrix.sync.aligned.m8n8.x4.shared.b16 {%0,%1,%2,%3},[%4];"
        : "=r"(r[0]), "=r"(r[1]), "=r"(r[2]), "=r"(r[3]) : "r"(a));
}
static DIB void mma16816(float* d, const uint32_t* a, const uint32_t* b) {
    asm volatile(
        "mma.sync.aligned.m16n8k16.row.col.f32.bf16.bf16.f32 "
        "{%0,%1,%2,%3}, {%4,%5,%6,%7}, {%8,%9}, {%0,%1,%2,%3};"
        : "+f"(d[0]), "+f"(d[1]), "+f"(d[2]), "+f"(d[3])
        : "r"(a[0]), "r"(a[1]), "r"(a[2]), "r"(a[3]), "r"(b[0]), "r"(b[1]));
}
static DIB uint32_t pk(bf16 lo, bf16 hi) {
    return (uint32_t)__bfloat16_as_ushort(lo) | ((uint32_t)__bfloat16_as_ushort(hi) << 16);
}

// acc += Ah*(Bh+Bl) + Al*Bh over CHT k-elems; MT x NT warp tile
template<int STA, int STB, int MT, int NT, int CHT>
static DIB void mma_blk(float (&acc)[MT][NT][4], uint32_t aH, uint32_t aL,
                        uint32_t bH, uint32_t bL)
{
    #pragma unroll
    for (int ks = 0; ks < CHT; ks += 16) {
        uint32_t Ah[MT][4], Al[MT][4], Bh[NT/2][4], Bl[NT/2][4];
        #pragma unroll
        for (int mt = 0; mt < MT; mt++) {
            ldsm4(Ah[mt], aH + (uint32_t)(mt*16*STA + ks) * 2);
            ldsm4(Al[mt], aL + (uint32_t)(mt*16*STA + ks) * 2);
        }
        #pragma unroll
        for (int g = 0; g < NT/2; g++) {
            ldsm4(Bh[g], bH + (uint32_t)(g*16*STB + ks) * 2);
            ldsm4(Bl[g], bL + (uint32_t)(g*16*STB + ks) * 2);
        }
        #pragma unroll
        for (int nt = 0; nt < NT; nt++) {
            uint32_t bh[2] = {Bh[nt>>1][(nt&1)*2], Bh[nt>>1][(nt&1)*2+1]};
            uint32_t bl[2] = {Bl[nt>>1][(nt&1)*2], Bl[nt>>1][(nt&1)*2+1]};
            #pragma unroll
            for (int mt = 0; mt < MT; mt++) {
                mma16816(acc[mt][nt], Ah[mt], bh);
                mma16816(acc[mt][nt], Ah[mt], bl);
                mma16816(acc[mt][nt], Al[mt], bh);
            }
        }
    }
}

// ================= unified fused 2-layer GEMM (a/b/readout) =================
template<int K1, int O1M, int NG, int O2, int OCC, int OUTM, int XMODE>
__global__ __launch_bounds__(256, OCC)
void fuse_k(const float* __restrict__ Xf,
            const bf16* __restrict__ Xh, const bf16* __restrict__ Xl,
            const bf16* __restrict__ W1h, const bf16* __restrict__ W1l,
            const bf16* __restrict__ W2h, const bf16* __restrict__ W2l,
            float* __restrict__ gate0, float* __restrict__ gate1,
            bf16* __restrict__ Oh, bf16* __restrict__ Ol, float* __restrict__ Of,
            int Mtot)
{
    constexpr int BM = 64, CH = 32, WST = 40;
    constexpr int O1T = O1M + NG * 128;
    constexpr int WR  = (O1T > O2) ? O1T : O2;
    constexpr int HST = O1M + 8;
    constexpr int WPL = WR * WST;
    constexpr int AST = K1 + 8;
    constexpr int APL = BM * AST;
    constexpr int XST = 40;
    constexpr int XPL = BM * XST;
    constexpr int STG  = (XMODE == 1) ? (2 * WPL) : (2 * XPL + 2 * WPL);
    constexpr int SOFF = (XMODE == 1) ? (2 * APL) : 0;
    constexpr int WIN  = (XMODE == 1) ? 0 : (2 * XPL);
    constexpr int HOFFn = SOFF + 2 * STG;
    constexpr int NC1 = K1 / CH, NC2 = O1M / CH;
    constexpr int NT1 = O1T / 32, NT2 = O2 / 32;

    extern __shared__ bf16 smm[];
    const int tid = threadIdx.x, lane = tid & 31, warp = tid >> 5;
    const int gid = lane >> 2, tq = (lane & 3) * 2;
    const int wm  = (warp >> 2) * 32;
    const int wn1 = (warp & 3) * (NT1 * 8);
    const int wn2 = (warp & 3) * (NT2 * 8);
    const int b = blockIdx.z, m0 = blockIdx.x * BM;
    const uint32_t su = smem_u32(smm);

    const int arow = (lane & 7) + ((lane >> 3) & 1) * 8;
    const int acol = (lane >> 4) * 8;
    const int brow = (lane & 7) + (lane >> 4) * 8;
    const int bcol = ((lane >> 3) & 1) * 8;

    auto load1 = [&](int kc, int s) {
        uint32_t wb = su + (uint32_t)(SOFF + s * STG + WIN) * 2;
        if constexpr (XMODE == 0) {
            uint32_t base = su + (uint32_t)(s * STG) * 2;
            const bf16* Xhb = Xh + ((size_t)b * Mtot + m0) * K1;
            const bf16* Xlb = Xl + ((size_t)b * Mtot + m0) * K1;
            #pragma unroll
            for (int i = tid; i < BM * 4; i += 256) {
                int r = i >> 2, c = (i & 3) * 8;
                cpa16(base + (uint32_t)(r * XST + c) * 2,       Xhb + (size_t)r * K1 + kc + c);
                cpa16(base + (uint32_t)(XPL + r * XST + c) * 2, Xlb + (size_t)r * K1 + kc + c);
            }
        }
        #pragma unroll
        for (int i = tid; i < O1T * 4; i += 256) {
            int r = i >> 2, c = (i & 3) * 8;
            cpa16(wb + (uint32_t)(r * WST + c) * 2,       W1h + (size_t)r * K1 + kc + c);
            cpa16(wb + (uint32_t)(WPL + r * WST + c) * 2, W1l + (size_t)r * K1 + kc + c);
        }
        CPA_COMMIT();
    };
    auto load2 = [&](int kc, int s) {
        uint32_t wb = su + (uint32_t)(SOFF + s * STG + WIN) * 2;
        #pragma unroll
        for (int i = tid; i < O2 * 4; i += 256) {
            int r = i >> 2, c = (i & 3) * 8;
            cpa16(wb + (uint32_t)(r * WST + c) * 2,       W2h + (size_t)r * O1M + kc + c);
            cpa16(wb + (uint32_t)(WPL + r * WST + c) * 2, W2l + (size_t)r * O1M + kc + c);
        }
        CPA_COMMIT();
    };

    if constexpr (XMODE == 1) {
        constexpr int SST_OFF = SOFF + STG;
        uint32_t sbase = su + (uint32_t)SST_OFF * 2;
        const float* Xg = Xf + (size_t)b * K1 * Mtot + m0;
        #pragma unroll
        for (int i = tid; i < K1 * 16; i += 256) {
            int r = i >> 4, c4 = (i & 15) * 4;
            cpa16(sbase + (uint32_t)(r * 68 + c4) * 4, Xg + (size_t)r * Mtot + c4);
        }
        CPA_COMMIT();
        load1(0, 0);
        CPA_WAIT(1);
        __syncthreads();
        const float* stg = (const float*)(smm + SST_OFF);
        int m = tid & 63, k0 = (tid >> 6) * (K1 / 4);
        #pragma unroll
        for (int j = 0; j < K1 / 4; j += 2) {
            int k = k0 + j;
            float v0 = stg[k * 68 + m], v1 = stg[(k + 1) * 68 + m];
            bf16 h0 = __float2bfloat16(v0), h1 = __float2bfloat16(v1);
            bf16 l0 = __float2bfloat16(v0 - __bfloat162float(h0));
            bf16 l1 = __float2bfloat16(v1 - __bfloat162float(h1));
            *(uint32_t*)&smm[(size_t)m * AST + k]       = pk(h0, h1);
            *(uint32_t*)&smm[(size_t)APL + m * AST + k] = pk(l0, l1);
        }
        __syncthreads();
    } else {
        load1(0, 0);
    }

    float acc1[2][NT1][4];
    #pragma unroll
    for (int mt = 0; mt < 2; mt++)
        #pragma unroll
        for (int nt = 0; nt < NT1; nt++)
            #pragma unroll
            for (int q = 0; q < 4; q++) acc1[mt][nt][q] = 0.f;

    for (int ki = 0; ki < NC1; ki++) {
        if (ki + 1 < NC1) { load1((ki + 1) * CH, (ki + 1) & 1); CPA_WAIT(1); }
        else              { CPA_WAIT(0); }
        __syncthreads();
        uint32_t aH, aL;
        if constexpr (XMODE == 1) {
            aH = su + (uint32_t)((wm + arow) * AST + acol + ki * CH) * 2;
            aL = aH + (uint32_t)APL * 2;
        } else {
            uint32_t base = su + (uint32_t)((ki & 1) * STG) * 2;
            aH = base + (uint32_t)((wm + arow) * XST + acol) * 2;
            aL = aH + (uint32_t)XPL * 2;
        }
        uint32_t wb = su + (uint32_t)(SOFF + (ki & 1) * STG + WIN) * 2;
        uint32_t bH = wb + (uint32_t)((wn1 + brow) * WST + bcol) * 2;
        uint32_t bL = bH + (uint32_t)WPL * 2;
        mma_blk<(XMODE == 1 ? AST : XST), WST, 2, NT1, CH>(acc1, aH, aL, bH, bL);
        __syncthreads();
    }

    load2(0, 0);

    #pragma unroll
    for (int mt = 0; mt < 2; mt++)
        #pragma unroll
        for (int h2 = 0; h2 < 2; h2++) {
            int ml = wm + mt * 16 + gid + h2 * 8;
            #pragma unroll
            for (int nt = 0; nt < NT1; nt++) {
                int oc = wn1 + nt * 8 + tq;
                float v0 = acc1[mt][nt][h2 * 2], v1 = acc1[mt][nt][h2 * 2 + 1];
                if (NG == 0 || oc < O1M) {
                    v0 = fmaxf(v0, 0.f); v1 = fmaxf(v1, 0.f);
                    bf16 h0 = __float2bfloat16(v0), h1 = __float2bfloat16(v1);
                    bf16 l0 = __float2bfloat16(v0 - __bfloat162float(h0));
                    bf16 l1 = __float2bfloat16(v1 - __bfloat162float(h1));
                    *(uint32_t*)&smm[HOFFn + ml * HST + oc]            = pk(h0, h1);
                    *(uint32_t*)&smm[HOFFn + BM * HST + ml * HST + oc] = pk(l0, l1);
                } else {
                    int g = (oc - O1M) >> 7;
                    float* gp = (g ? gate1 : gate0) + ((size_t)b * Mtot + m0 + ml) * 128 + (oc & 127);
                    *(float2*)gp = make_float2(1.0f / (1.0f + __expf(v0)),
                                               1.0f / (1.0f + __expf(v1)));
                }
            }
        }
    __syncthreads();

    float acc2[2][NT2][4];
    #pragma unroll
    for (int mt = 0; mt < 2; mt++)
        #pragma unroll
        for (int nt = 0; nt < NT2; nt++)
            #pragma unroll
            for (int q = 0; q < 4; q++) acc2[mt][nt][q] = 0.f;

    for (int ki = 0; ki < NC2; ki++) {
        if (ki + 1 < NC2) { load2((ki + 1) * CH, (ki + 1) & 1); CPA_WAIT(1); }
        else              { CPA_WAIT(0); }
        __syncthreads();
        uint32_t aH = su + (uint32_t)(HOFFn + (wm + arow) * HST + acol + ki * CH) * 2;
        uint32_t aL = aH + (uint32_t)(BM * HST) * 2;
        uint32_t wb = su + (uint32_t)(SOFF + (ki & 1) * STG + WIN) * 2;
        uint32_t bH = wb + (uint32_t)((wn2 + brow) * WST + bcol) * 2;
        uint32_t bL = bH + (uint32_t)WPL * 2;
        mma_blk<HST, WST, 2, NT2, CH>(acc2, aH, aL, bH, bL);
        __syncthreads();
    }

    #pragma unroll
    for (int mt = 0; mt < 2; mt++)
        #pragma unroll
        for (int h2 = 0; h2 < 2; h2++) {
            int m = m0 + wm + mt * 16 + gid + h2 * 8;
            #pragma unroll
            for (int nt = 0; nt < NT2; nt++) {
                int oc = wn2 + nt * 8 + tq;
                float v0 = acc2[mt][nt][h2 * 2], v1 = acc2[mt][nt][h2 * 2 + 1];
                if (OUTM == 0) {
                    bf16 h0 = __float2bfloat16(v0), h1 = __float2bfloat16(v1);
                    bf16 l0 = __float2bfloat16(v0 - __bfloat162float(h0));
                    bf16 l1 = __float2bfloat16(v1 - __bfloat162float(h1));
                    size_t go = ((size_t)b * Mtot + m) * O2 + oc;
                    *(uint32_t*)(Oh + go) = pk(h0, h1);
                    *(uint32_t*)(Ol + go) = pk(l0, l1);
                } else {
                    Of[((size_t)b * O2 + oc)     * Mtot + m] = v0;
                    Of[((size_t)b * O2 + oc + 1) * Mtot + m] = v1;
                }
            }
        }
}

// ================= persistent-weight c-stage kernel (16 warps) =================
#define C_TILES 8192
#define C_GRID  1024
#define C_THREADS 512
// smem layout (bf16 units)
#define C_W1H 0
#define C_W1L 9216
#define C_W2H 18432
#define C_W2L 35840
#define C_AH  53248
#define C_AL  57856
#define C_HH  62464
#define C_HL  71168
#define C_STG 79872         // 2 buffers of 8704 units (fp32 64x68)
#define C_UNITS 97280       // 194560 bytes

__global__ __launch_bounds__(C_THREADS, 1)
void cpers_k(const float* __restrict__ Xf,
             const bf16* __restrict__ W1h, const bf16* __restrict__ W1l,
             const bf16* __restrict__ W2h, const bf16* __restrict__ W2l,
             bf16* __restrict__ Oh, bf16* __restrict__ Ol)
{
    extern __shared__ bf16 smm[];
    const int tid = threadIdx.x, lane = tid & 31, warp = tid >> 5;
    const int gid = lane >> 2, tq = (lane & 3) * 2;
    const int wm = (warp >> 2) * 16, wn = (warp & 3) * 32;   // 4x4 warp grid
    const uint32_t su = smem_u32(smm);

    const int arow = (lane & 7) + ((lane >> 3) & 1) * 8;
    const int acol = (lane >> 4) * 8;
    const int brow = (lane & 7) + (lane >> 4) * 8;
    const int bcol = ((lane >> 3) & 1) * 8;

    // ---- load all weights (once) ----
    #pragma unroll
    for (int i = tid; i < 128 * 8; i += C_THREADS) {
        int r = i >> 3, c = (i & 7) * 8;
        cpa16(su + (uint32_t)(C_W1H + r * 72 + c) * 2, W1h + (size_t)r * 64 + c);
        cpa16(su + (uint32_t)(C_W1L + r * 72 + c) * 2, W1l + (size_t)r * 64 + c);
    }
    #pragma unroll
    for (int i = tid; i < 128 * 16; i += C_THREADS) {
        int r = i >> 4, c = (i & 15) * 8;
        cpa16(su + (uint32_t)(C_W2H + r * 136 + c) * 2, W2h + (size_t)r * 128 + c);
        cpa16(su + (uint32_t)(C_W2L + r * 136 + c) * 2, W2l + (size_t)r * 128 + c);
    }
    CPA_COMMIT();

    auto stage = [&](int t, int s) {
        int b = t >> 10, mi = (t & 1023) << 6;
        const float* Xg = Xf + (size_t)b * 64 * 65536 + mi;
        uint32_t sbase = su + (uint32_t)(C_STG + s * 8704) * 2;
        #pragma unroll
        for (int i = tid; i < 64 * 16; i += C_THREADS) {
            int r = i >> 4, c4 = (i & 15) * 4;
            cpa16(sbase + (uint32_t)(r * 68 + c4) * 4, Xg + (size_t)r * 65536 + c4);
        }
        CPA_COMMIT();
    };

    stage(blockIdx.x, 0);
    CPA_WAIT(0);
    __syncthreads();

    int cur = 0;
    for (int t = blockIdx.x, it = 0; t < C_TILES; t += C_GRID, it++) {
        if (it > 0) { CPA_WAIT(0); __syncthreads(); }

        // ---- transpose + split staging -> A ----
        {
            const float* stg = (const float*)(smm + C_STG + cur * 8704);
            int m = tid & 63, k0 = (tid >> 6) * 8;   // 8 thread-groups x 8 k each
            #pragma unroll
            for (int j = 0; j < 8; j += 2) {
                int k = k0 + j;
                float v0 = stg[k * 68 + m], v1 = stg[(k + 1) * 68 + m];
                bf16 h0 = __float2bfloat16(v0), h1 = __float2bfloat16(v1);
                bf16 l0 = __float2bfloat16(v0 - __bfloat162float(h0));
                bf16 l1 = __float2bfloat16(v1 - __bfloat162float(h1));
                *(uint32_t*)&smm[C_AH + m * 72 + k] = pk(h0, h1);
                *(uint32_t*)&smm[C_AL + m * 72 + k] = pk(l0, l1);
            }
        }
        __syncthreads();

        if (t + C_GRID < C_TILES) stage(t + C_GRID, cur ^ 1);

        // ---- GEMM1: K=64 ----
        float acc1[1][4][4];
        #pragma unroll
        for (int nt = 0; nt < 4; nt++)
            #pragma unroll
            for (int q = 0; q < 4; q++) acc1[0][nt][q] = 0.f;
        {
            uint32_t aH = su + (uint32_t)(C_AH + (wm + arow) * 72 + acol) * 2;
            uint32_t aL = su + (uint32_t)(C_AL + (wm + arow) * 72 + acol) * 2;
            uint32_t bH = su + (uint32_t)(C_W1H + (wn + brow) * 72 + bcol) * 2;
            uint32_t bL = su + (uint32_t)(C_W1L + (wn + brow) * 72 + bcol) * 2;
            mma_blk<72, 72, 1, 4, 64>(acc1, aH, aL, bH, bL);
        }

        // ---- relu + split -> h ----
        #pragma unroll
        for (int h2 = 0; h2 < 2; h2++) {
            int ml = wm + gid + h2 * 8;
            #pragma unroll
            for (int nt = 0; nt < 4; nt++) {
                int oc = wn + nt * 8 + tq;
                float v0 = fmaxf(acc1[0][nt][h2 * 2],     0.f);
                float v1 = fmaxf(acc1[0][nt][h2 * 2 + 1], 0.f);
                bf16 h0 = __float2bfloat16(v0), h1 = __float2bfloat16(v1);
                bf16 l0 = __float2bfloat16(v0 - __bfloat162float(h0));
                bf16 l1 = __float2bfloat16(v1 - __bfloat162float(h1));
                *(uint32_t*)&smm[C_HH + ml * 136 + oc] = pk(h0, h1);
                *(uint32_t*)&smm[C_HL + ml * 136 + oc] = pk(l0, l1);
            }
        }
        __syncthreads();

        // ---- GEMM2: K=128 ----
        float acc2[1][4][4];
        #pragma unroll
        for (int nt = 0; nt < 4; nt++)
            #pragma unroll
            for (int q = 0; q < 4; q++) acc2[0][nt][q] = 0.f;
        {
            uint32_t aH = su + (uint32_t)(C_HH + (wm + arow) * 136 + acol) * 2;
            uint32_t aL = su + (uint32_t)(C_HL + (wm + arow) * 136 + acol) * 2;
            uint32_t bH = su + (uint32_t)(C_W2H + (wn + brow) * 136 + bcol) * 2;
            uint32_t bL = su + (uint32_t)(C_W2L + (wn + brow) * 136 + bcol) * 2;
            mma_blk<136, 136, 1, 4, 128>(acc2, aH, aL, bH, bL);
        }

        // ---- output ----
        {
            int b = t >> 10, mi = (t & 1023) << 6;
            #pragma unroll
            for (int h2 = 0; h2 < 2; h2++) {
                int m = mi + wm + gid + h2 * 8;
                #pragma unroll
                for (int nt = 0; nt < 4; nt++) {
                    int oc = wn + nt * 8 + tq;
                    float v0 = acc2[0][nt][h2 * 2], v1 = acc2[0][nt][h2 * 2 + 1];
                    bf16 h0 = __float2bfloat16(v0), h1 = __float2bfloat16(v1);
                    bf16 l0 = __float2bfloat16(v0 - __bfloat162float(h0));
                    bf16 l1 = __float2bfloat16(v1 - __bfloat162float(h1));
                    size_t go = ((size_t)b * 65536 + m) * 128 + oc;
                    *(uint32_t*)(Oh + go) = pk(h0, h1);
                    *(uint32_t*)(Ol + go) = pk(l0, l1);
                }
            }
        }
        cur ^= 1;
    }
}

// ================= merged weight split =================
struct WSeg { const float* s; bf16* h; bf16* l; int n; };
struct WParams { WSeg w[10]; };

__global__ __launch_bounds__(256)
void wsplit_all(WParams p) {
    int gi = blockIdx.x * 256 + threadIdx.x;
    #pragma unroll
    for (int s = 0; s < 10; s++) {
        int n = p.w[s].n;
        if (gi < n) {
            float v = p.w[s].s[gi];
            bf16 hv = __float2bfloat16(v);
            p.w[s].h[gi] = hv;
            p.w[s].l[gi] = __float2bfloat16(v - __bfloat162float(hv));
            return;
        }
        gi -= n;
    }
}

// ================= attention =================
static DIB float wsum(float v) {
    #pragma unroll
    for (int o = 16; o > 0; o >>= 1) v += __shfl_xor_sync(0xffffffffu, v, o);
    return v;
}
static DIB float sigm(float x) { return 1.0f / (1.0f + __expf(-x)); }
static DIB float rd2(const bf16* h, const bf16* l, size_t i) {
    return __bfloat162float(h[i]) + __bfloat162float(l[i]);
}
static DIB void wr2(bf16* h, bf16* l, size_t i, float v) {
    bf16 x = __float2bfloat16(v);
    h[i] = x;
    l[i] = __float2bfloat16(v - __bfloat162float(x));
}

__global__ __launch_bounds__(128)
void attend_k(const bf16* __restrict__ eah, const bf16* __restrict__ eal,
              const float* __restrict__ gateb, const float* __restrict__ gatec,
              const bf16* __restrict__ ebh, const bf16* __restrict__ ebl,
              const bf16* __restrict__ ech, const bf16* __restrict__ ecl,
              const float* __restrict__ Wab, const float* __restrict__ Wac,
              bf16* __restrict__ agh, bf16* __restrict__ agl)
{
    int gw = (blockIdx.x * 128 + threadIdx.x) >> 5;
    int lane = threadIdx.x & 31;
    int b = gw >> 12, n = gw & 4095;
    int h = n >> 6, w = n & 63;
    size_t nb = (size_t)b * 4096 + n;

    float ea[4], gb[4], gc[4];
    float pab = 0.f, pac = 0.f;
    #pragma unroll
    for (int j = 0; j < 4; j++) {
        int cc = lane + 32 * j;
        ea[j] = rd2(eah, eal, nb * 128 + cc);
        gb[j] = gateb[nb * 128 + cc];
        gc[j] = gatec[nb * 128 + cc];
        pab += Wab[cc] * ea[j];
        pac += Wac[cc] * ea[j];
    }
    float dab = wsum(pab), dac = wsum(pac);

    { // B branch
        float eb[4][4], lb[4];
        #pragma unroll
        for (int p = 0; p < 4; p++) {
            int kh = p >> 1, kw = p & 1;
            size_t base = ((size_t)b * 16384 + (size_t)(2*h + kh) * 128 + (2*w + kw)) * 128;
            float s = 0.f;
            #pragma unroll
            for (int j = 0; j < 4; j++) {
                int cc = lane + 32 * j;
                eb[p][j] = rd2(ebh, ebl, base + cc);
                s += Wab[128 + cc] * eb[p][j];
            }
            lb[p] = fmaxf(dab + wsum(s), 0.0f);
        }
        float mx = fmaxf(fmaxf(lb[0], lb[1]), fmaxf(lb[2], lb[3]));
        float ss = 0.f;
        #pragma unroll
        for (int p = 0; p < 4; p++) { lb[p] = __expf(lb[p] - mx); ss += lb[p]; }
        float inv = 1.0f / ss;
        #pragma unroll
        for (int j = 0; j < 4; j++) {
            float a = 0.f;
            #pragma unroll
            for (int p = 0; p < 4; p++) a += eb[p][j] * lb[p];
            wr2(agh, agl, nb * 384 + lane + 32 * j, sigm(a * inv * gb[j]));
        }
    }
    { // C branch
        float ec[16][4], lc[16];
        #pragma unroll
        for (int p = 0; p < 16; p++) {
            int kh = p >> 2, kw = p & 3;
            size_t base = ((size_t)b * 65536 + (size_t)(4*h + kh) * 256 + (4*w + kw)) * 128;
            float s = 0.f;
            #pragma unroll
            for (int j = 0; j < 4; j++) {
                int cc = lane + 32 * j;
                ec[p][j] = rd2(ech, ecl, base + cc);
                s += Wac[128 + cc] * ec[p][j];
            }
            lc[p] = fmaxf(dac + wsum(s), 0.0f);
        }
        float mx = lc[0];
        #pragma unroll
        for (int p = 1; p < 16; p++) mx = fmaxf(mx, lc[p]);
        float ss = 0.f;
        #pragma unroll
        for (int p = 0; p < 16; p++) { lc[p] = __expf(lc[p] - mx); ss += lc[p]; }
        float inv = 1.0f / ss;
        #pragma unroll
        for (int j = 0; j < 4; j++) {
            float a = 0.f;
            #pragma unroll
            for (int p = 0; p < 16; p++) a += ec[p][j] * lc[p];
            wr2(agh, agl, nb * 384 + 128 + lane + 32 * j, sigm(a * inv * gc[j]));
        }
    }
    #pragma unroll
    for (int j = 0; j < 4; j++)
        wr2(agh, agl, nb * 384 + 256 + lane + 32 * j, sigm(ea[j]));
}

// ================= launch =================
static inline int imax(int a, int b) { return a > b ? a : b; }
static inline int fsz1(int K1, int O1M, int NG, int O2) {
    int O1T = O1M + NG * 128, WR = imax(O1T, O2);
    int staging_units = K1 * 68 * 2;
    int units = 2*64*(K1+8) + 2*(2*WR*40) + 2*64*(O1M+8);
    int with_staging = 2*64*(K1+8) + 2*WR*40 + staging_units;
    return imax(units, with_staging) * 2;
}
static inline int fsz0(int O1M, int NG, int O2) {
    int O1T = O1M + NG * 128, WR = imax(O1T, O2);
    int XPL = 64 * 40, WPL = WR * 40;
    int STG = 2 * XPL + 2 * WPL;
    return (2 * STG + 2 * 64 * (O1M + 8)) * 2;
}

extern "C" void kernel_launch(void* const* d_in, const int* in_sizes, int n_in,
                              void* d_out, int out_size)
{
    const float* va  = (const float*)d_in[0];
    const float* vb  = (const float*)d_in[1];
    const float* vc  = (const float*)d_in[2];
    const float* Wa1 = (const float*)d_in[3];
    const float* Wa2 = (const float*)d_in[4];
    const float* Wgb = (const float*)d_in[5];
    const float* Wgc = (const float*)d_in[6];
    const float* Wb1 = (const float*)d_in[7];
    const float* Wb2 = (const float*)d_in[8];
    const float* Wc1 = (const float*)d_in[9];
    const float* Wc2 = (const float*)d_in[10];
    const float* Wab = (const float*)d_in[11];
    const float* Wac = (const float*)d_in[12];
    const float* Wr1 = (const float*)d_in[13];
    const float* Wr2 = (const float*)d_in[14];
    float* out = (float*)d_out;

    bf16 *eah,*eal,*ebh,*ebl,*ech,*ecl,*agh,*agl;
    float *gb,*gc;
    bf16 *WAh,*WAl,*Wa2h,*Wa2l,*Wb1h,*Wb1l,*Wb2h,*Wb2l,*Wc1h,*Wc1l,*Wc2h,*Wc2l,
         *Wr1h,*Wr1l,*Wr2h,*Wr2l;
    cudaGetSymbolAddress((void**)&eah,g_eah); cudaGetSymbolAddress((void**)&eal,g_eal);
    cudaGetSymbolAddress((void**)&gb,g_gb);   cudaGetSymbolAddress((void**)&gc,g_gc);
    cudaGetSymbolAddress((void**)&ebh,g_ebh); cudaGetSymbolAddress((void**)&ebl,g_ebl);
    cudaGetSymbolAddress((void**)&ech,g_ech); cudaGetSymbolAddress((void**)&ecl,g_ecl);
    cudaGetSymbolAddress((void**)&agh,g_agh); cudaGetSymbolAddress((void**)&agl,g_agl);
    cudaGetSymbolAddress((void**)&WAh,g_WAh); cudaGetSymbolAddress((void**)&WAl,g_WAl);
    cudaGetSymbolAddress((void**)&Wa2h,g_Wa2h); cudaGetSymbolAddress((void**)&Wa2l,g_Wa2l);
    cudaGetSymbolAddress((void**)&Wb1h,g_Wb1h); cudaGetSymbolAddress((void**)&Wb1l,g_Wb1l);
    cudaGetSymbolAddress((void**)&Wb2h,g_Wb2h); cudaGetSymbolAddress((void**)&Wb2l,g_Wb2l);
    cudaGetSymbolAddress((void**)&Wc1h,g_Wc1h); cudaGetSymbolAddress((void**)&Wc1l,g_Wc1l);
    cudaGetSymbolAddress((void**)&Wc2h,g_Wc2h); cudaGetSymbolAddress((void**)&Wc2l,g_Wc2l);
    cudaGetSymbolAddress((void**)&Wr1h,g_Wr1h); cudaGetSymbolAddress((void**)&Wr1l,g_Wr1l);
    cudaGetSymbolAddress((void**)&Wr2h,g_Wr2h); cudaGetSymbolAddress((void**)&Wr2l,g_Wr2l);

    int sA = fsz1(256, 128, 2, 128);
    int sB = fsz1(128, 128, 0, 128);
    int sR = fsz0(256, 0, 256);
    int sC = C_UNITS * 2;
    cudaFuncSetAttribute(fuse_k<256,128,2,128,1,0,1>, cudaFuncAttributeMaxDynamicSharedMemorySize, sA);
    cudaFuncSetAttribute(fuse_k<128,128,0,128,2,0,1>, cudaFuncAttributeMaxDynamicSharedMemorySize, sB);
    cudaFuncSetAttribute(fuse_k<384,256,0,256,1,2,0>, cudaFuncAttributeMaxDynamicSharedMemorySize, sR);
    cudaFuncSetAttribute(cpers_k, cudaFuncAttributeMaxDynamicSharedMemorySize, sC);

    WParams P;
    P.w[0] = {Wa1, WAh,           WAl,           32768};
    P.w[1] = {Wgb, WAh + 32768,   WAl + 32768,   32768};
    P.w[2] = {Wgc, WAh + 65536,   WAl + 65536,   32768};
    P.w[3] = {Wa2, Wa2h, Wa2l, 16384};
    P.w[4] = {Wb1, Wb1h, Wb1l, 16384};
    P.w[5] = {Wb2, Wb2h, Wb2l, 16384};
    P.w[6] = {Wc1, Wc1h, Wc1l, 8192};
    P.w[7] = {Wc2, Wc2h, Wc2l, 16384};
    P.w[8] = {Wr1, Wr1h, Wr1l, 98304};
    P.w[9] = {Wr2, Wr2h, Wr2l, 65536};
    wsplit_all<<<(335872 + 255) / 256, 256>>>(P);

    // a-stage (fp32 X direct)
    fuse_k<256,128,2,128,1,0,1><<<dim3(64, 1, NB), 256, sA>>>(
        va, nullptr, nullptr, WAh, WAl, Wa2h, Wa2l, gb, gc, eah, eal, nullptr, 4096);
    // b-stage
    fuse_k<128,128,0,128,2,0,1><<<dim3(256, 1, NB), 256, sB>>>(
        vb, nullptr, nullptr, Wb1h, Wb1l, Wb2h, Wb2l, nullptr, nullptr, ebh, ebl, nullptr, 16384);
    // c-stage (persistent weights, 16 warps)
    cpers_k<<<C_GRID, C_THREADS, sC>>>(vc, Wc1h, Wc1l, Wc2h, Wc2l, ech, ecl);

    attend_k<<<8192, 128>>>(eah, eal, gb, gc, ebh, ebl, ech, ecl, Wab, Wac, agh, agl);

    // readout (bf16 hi/lo X)
    fuse_k<384,256,0,256,1,2,0><<<dim3(64, 1, NB), 256, sR>>>(
        nullptr, agh, agl, Wr1h, Wr1l, Wr2h, Wr2l, nullptr, nullptr, nullptr, nullptr, out, 4096);
}

// round 14
// speedup vs baseline: 2.2548x; 1.1759x over previous
#include <cuda_runtime.h>
#include <cuda_bf16.h>
#include <cuda_fp16.h>
#include <cstdint>

using bf16 = __nv_bfloat16;
using h16  = __half;
#define DIB __device__ __forceinline__
#define NB 8

// ================= scratch (device globals) =================
__device__ __align__(16) bf16 g_eah[(size_t)NB*4096*128],  g_eal[(size_t)NB*4096*128];
__device__ __align__(16) float g_gb[(size_t)NB*4096*128],  g_gc[(size_t)NB*4096*128];
__device__ __align__(16) bf16 g_ebh[(size_t)NB*16384*128], g_ebl[(size_t)NB*16384*128];
__device__ __align__(16) h16  g_ec [(size_t)NB*65536*128];
__device__ __align__(16) bf16 g_agh[(size_t)NB*4096*384],  g_agl[(size_t)NB*4096*384];
__device__ __align__(16) bf16 g_WAh[384*256],  g_WAl[384*256];   // Wa1|Wgb|Wgc stacked
__device__ __align__(16) bf16 g_Wa2h[128*128], g_Wa2l[128*128];
__device__ __align__(16) bf16 g_Wb1h[128*128], g_Wb1l[128*128];
__device__ __align__(16) bf16 g_Wb2h[128*128], g_Wb2l[128*128];
__device__ __align__(16) h16  g_Wc1h[128*64],  g_Wc1l[128*64];
__device__ __align__(16) h16  g_Wc2h[128*128], g_Wc2l[128*128];
__device__ __align__(16) bf16 g_Wr1h[256*384], g_Wr1l[256*384];
__device__ __align__(16) bf16 g_Wr2h[256*256], g_Wr2l[256*256];

// ================= helpers =================
static DIB uint32_t smem_u32(const void* p) {
    uint32_t a;
    asm("{ .reg .u64 t; cvta.to.shared.u64 t, %1; cvt.u32.u64 %0, t; }" : "=r"(a) : "l"(p));
    return a;
}
static DIB void cpa16(uint32_t s, const void* g) {
    asm volatile("cp.async.ca.shared.global [%0],[%1],16;" :: "r"(s), "l"(g) : "memory");
}
#define CPA_COMMIT() asm volatile("cp.async.commit_group;" ::: "memory")
#define CPA_WAIT(N)  asm volatile("cp.async.wait_group " #N ";" ::: "memory")
static DIB void ldsm4(uint32_t* r, uint32_t a) {
    asm volatile("ldmatrix.sync.aligned.m8n8.x4.shared.b16 {%0,%1,%2,%3},[%4];"
        : "=r"(r[0]), "=r"(r[1]), "=r"(r[2]), "=r"(r[3]) : "r"(a));
}
static DIB void mma16816(float* d, const uint32_t* a, const uint32_t* b) {
    asm volatile(
        "mma.sync.aligned.m16n8k16.row.col.f32.bf16.bf16.f32 "
        "{%0,%1,%2,%3}, {%4,%5,%6,%7}, {%8,%9}, {%0,%1,%2,%3};"
        : "+f"(d[0]), "+f"(d[1]), "+f"(d[2]), "+f"(d[3])
        : "r"(a[0]), "r"(a[1]), "r"(a[2]), "r"(a[3]), "r"(b[0]), "r"(b[1]));
}
static DIB void mma16816h(float* d, const uint32_t* a, const uint32_t* b) {
    asm volatile(
        "mma.sync.aligned.m16n8k16.row.col.f32.f16.f16.f32 "
        "{%0,%1,%2,%3}, {%4,%5,%6,%7}, {%8,%9}, {%0,%1,%2,%3};"
        : "+f"(d[0]), "+f"(d[1]), "+f"(d[2]), "+f"(d[3])
        : "r"(a[0]), "r"(a[1]), "r"(a[2]), "r"(a[3]), "r"(b[0]), "r"(b[1]));
}
static DIB uint32_t pk(bf16 lo, bf16 hi) {
    return (uint32_t)__bfloat16_as_ushort(lo) | ((uint32_t)__bfloat16_as_ushort(hi) << 16);
}
static DIB uint32_t pkh2(float v0, float v1) {
    h16 a = __float2half_rn(v0), b = __float2half_rn(v1);
    return (uint32_t)__half_as_ushort(a) | ((uint32_t)__half_as_ushort(b) << 16);
}

// 3-term bf16 split: acc += Ah*(Bh+Bl) + Al*Bh
template<int STA, int STB, int MT, int NT, int CHT>
static DIB void mma_blk(float (&acc)[MT][NT][4], uint32_t aH, uint32_t aL,
                        uint32_t bH, uint32_t bL)
{
    #pragma unroll
    for (int ks = 0; ks < CHT; ks += 16) {
        uint32_t Ah[MT][4], Al[MT][4], Bh[NT/2][4], Bl[NT/2][4];
        #pragma unroll
        for (int mt = 0; mt < MT; mt++) {
            ldsm4(Ah[mt], aH + (uint32_t)(mt*16*STA + ks) * 2);
            ldsm4(Al[mt], aL + (uint32_t)(mt*16*STA + ks) * 2);
        }
        #pragma unroll
        for (int g = 0; g < NT/2; g++) {
            ldsm4(Bh[g], bH + (uint32_t)(g*16*STB + ks) * 2);
            ldsm4(Bl[g], bL + (uint32_t)(g*16*STB + ks) * 2);
        }
        #pragma unroll
        for (int nt = 0; nt < NT; nt++) {
            uint32_t bh[2] = {Bh[nt>>1][(nt&1)*2], Bh[nt>>1][(nt&1)*2+1]};
            uint32_t bl[2] = {Bl[nt>>1][(nt&1)*2], Bl[nt>>1][(nt&1)*2+1]};
            #pragma unroll
            for (int mt = 0; mt < MT; mt++) {
                mma16816(acc[mt][nt], Ah[mt], bh);
                mma16816(acc[mt][nt], Ah[mt], bl);
                mma16816(acc[mt][nt], Al[mt], bh);
            }
        }
    }
}

// 2-term fp16: acc += Ah*(Bh+Bl)   (A single plane)
template<int STA, int STB, int MT, int NT, int CHT>
static DIB void mma_blk2(float (&acc)[MT][NT][4], uint32_t aH,
                         uint32_t bH, uint32_t bL)
{
    #pragma unroll
    for (int ks = 0; ks < CHT; ks += 16) {
        uint32_t Ah[MT][4], Bh[NT/2][4], Bl[NT/2][4];
        #pragma unroll
        for (int mt = 0; mt < MT; mt++)
            ldsm4(Ah[mt], aH + (uint32_t)(mt*16*STA + ks) * 2);
        #pragma unroll
        for (int g = 0; g < NT/2; g++) {
            ldsm4(Bh[g], bH + (uint32_t)(g*16*STB + ks) * 2);
            ldsm4(Bl[g], bL + (uint32_t)(g*16*STB + ks) * 2);
        }
        #pragma unroll
        for (int nt = 0; nt < NT; nt++) {
            uint32_t bh[2] = {Bh[nt>>1][(nt&1)*2], Bh[nt>>1][(nt&1)*2+1]};
            uint32_t bl[2] = {Bl[nt>>1][(nt&1)*2], Bl[nt>>1][(nt&1)*2+1]};
            #pragma unroll
            for (int mt = 0; mt < MT; mt++) {
                mma16816h(acc[mt][nt], Ah[mt], bh);
                mma16816h(acc[mt][nt], Ah[mt], bl);
            }
        }
    }
}

// ================= unified fused 2-layer GEMM (a/b/readout; bf16 3-term) =================
template<int K1, int O1M, int NG, int O2, int OCC, int OUTM, int XMODE>
__global__ __launch_bounds__(256, OCC)
void fuse_k(const float* __restrict__ Xf,
            const bf16* __restrict__ Xh, const bf16* __restrict__ Xl,
            const bf16* __restrict__ W1h, const bf16* __restrict__ W1l,
            const bf16* __restrict__ W2h, const bf16* __restrict__ W2l,
            float* __restrict__ gate0, float* __restrict__ gate1,
            bf16* __restrict__ Oh, bf16* __restrict__ Ol, float* __restrict__ Of,
            int Mtot)
{
    constexpr int BM = 64, CH = 32, WST = 40;
    constexpr int O1T = O1M + NG * 128;
    constexpr int WR  = (O1T > O2) ? O1T : O2;
    constexpr int HST = O1M + 8;
    constexpr int WPL = WR * WST;
    constexpr int AST = K1 + 8;
    constexpr int APL = BM * AST;
    constexpr int XST = 40;
    constexpr int XPL = BM * XST;
    constexpr int STG  = (XMODE == 1) ? (2 * WPL) : (2 * XPL + 2 * WPL);
    constexpr int SOFF = (XMODE == 1) ? (2 * APL) : 0;
    constexpr int WIN  = (XMODE == 1) ? 0 : (2 * XPL);
    constexpr int HOFFn = SOFF + 2 * STG;
    constexpr int NC1 = K1 / CH, NC2 = O1M / CH;
    constexpr int NT1 = O1T / 32, NT2 = O2 / 32;

    extern __shared__ bf16 smm[];
    const int tid = threadIdx.x, lane = tid & 31, warp = tid >> 5;
    const int gid = lane >> 2, tq = (lane & 3) * 2;
    const int wm  = (warp >> 2) * 32;
    const int wn1 = (warp & 3) * (NT1 * 8);
    const int wn2 = (warp & 3) * (NT2 * 8);
    const int b = blockIdx.z, m0 = blockIdx.x * BM;
    const uint32_t su = smem_u32(smm);

    const int arow = (lane & 7) + ((lane >> 3) & 1) * 8;
    const int acol = (lane >> 4) * 8;
    const int brow = (lane & 7) + (lane >> 4) * 8;
    const int bcol = ((lane >> 3) & 1) * 8;

    auto load1 = [&](int kc, int s) {
        uint32_t wb = su + (uint32_t)(SOFF + s * STG + WIN) * 2;
        if constexpr (XMODE == 0) {
            uint32_t base = su + (uint32_t)(s * STG) * 2;
            const bf16* Xhb = Xh + ((size_t)b * Mtot + m0) * K1;
            const bf16* Xlb = Xl + ((size_t)b * Mtot + m0) * K1;
            #pragma unroll
            for (int i = tid; i < BM * 4; i += 256) {
                int r = i >> 2, c = (i & 3) * 8;
                cpa16(base + (uint32_t)(r * XST + c) * 2,       Xhb + (size_t)r * K1 + kc + c);
                cpa16(base + (uint32_t)(XPL + r * XST + c) * 2, Xlb + (size_t)r * K1 + kc + c);
            }
        }
        #pragma unroll
        for (int i = tid; i < O1T * 4; i += 256) {
            int r = i >> 2, c = (i & 3) * 8;
            cpa16(wb + (uint32_t)(r * WST + c) * 2,       W1h + (size_t)r * K1 + kc + c);
            cpa16(wb + (uint32_t)(WPL + r * WST + c) * 2, W1l + (size_t)r * K1 + kc + c);
        }
        CPA_COMMIT();
    };
    auto load2 = [&](int kc, int s) {
        uint32_t wb = su + (uint32_t)(SOFF + s * STG + WIN) * 2;
        #pragma unroll
        for (int i = tid; i < O2 * 4; i += 256) {
            int r = i >> 2, c = (i & 3) * 8;
            cpa16(wb + (uint32_t)(r * WST + c) * 2,       W2h + (size_t)r * O1M + kc + c);
            cpa16(wb + (uint32_t)(WPL + r * WST + c) * 2, W2l + (size_t)r * O1M + kc + c);
        }
        CPA_COMMIT();
    };

    if constexpr (XMODE == 1) {
        constexpr int SST_OFF = SOFF + STG;
        uint32_t sbase = su + (uint32_t)SST_OFF * 2;
        const float* Xg = Xf + (size_t)b * K1 * Mtot + m0;
        #pragma unroll
        for (int i = tid; i < K1 * 16; i += 256) {
            int r = i >> 4, c4 = (i & 15) * 4;
            cpa16(sbase + (uint32_t)(r * 68 + c4) * 4, Xg + (size_t)r * Mtot + c4);
        }
        CPA_COMMIT();
        load1(0, 0);
        CPA_WAIT(1);
        __syncthreads();
        const float* stg = (const float*)(smm + SST_OFF);
        int m = tid & 63, k0 = (tid >> 6) * (K1 / 4);
        #pragma unroll
        for (int j = 0; j < K1 / 4; j += 2) {
            int k = k0 + j;
            float v0 = stg[k * 68 + m], v1 = stg[(k + 1) * 68 + m];
            bf16 h0 = __float2bfloat16(v0), h1 = __float2bfloat16(v1);
            bf16 l0 = __float2bfloat16(v0 - __bfloat162float(h0));
            bf16 l1 = __float2bfloat16(v1 - __bfloat162float(h1));
            *(uint32_t*)&smm[(size_t)m * AST + k]       = pk(h0, h1);
            *(uint32_t*)&smm[(size_t)APL + m * AST + k] = pk(l0, l1);
        }
        __syncthreads();
    } else {
        load1(0, 0);
    }

    float acc1[2][NT1][4];
    #pragma unroll
    for (int mt = 0; mt < 2; mt++)
        #pragma unroll
        for (int nt = 0; nt < NT1; nt++)
            #pragma unroll
            for (int q = 0; q < 4; q++) acc1[mt][nt][q] = 0.f;

    for (int ki = 0; ki < NC1; ki++) {
        if (ki + 1 < NC1) { load1((ki + 1) * CH, (ki + 1) & 1); CPA_WAIT(1); }
        else              { CPA_WAIT(0); }
        __syncthreads();
        uint32_t aH, aL;
        if constexpr (XMODE == 1) {
            aH = su + (uint32_t)((wm + arow) * AST + acol + ki * CH) * 2;
            aL = aH + (uint32_t)APL * 2;
        } else {
            uint32_t base = su + (uint32_t)((ki & 1) * STG) * 2;
            aH = base + (uint32_t)((wm + arow) * XST + acol) * 2;
            aL = aH + (uint32_t)XPL * 2;
        }
        uint32_t wb = su + (uint32_t)(SOFF + (ki & 1) * STG + WIN) * 2;
        uint32_t bH = wb + (uint32_t)((wn1 + brow) * WST + bcol) * 2;
        uint32_t bL = bH + (uint32_t)WPL * 2;
        mma_blk<(XMODE == 1 ? AST : XST), WST, 2, NT1, CH>(acc1, aH, aL, bH, bL);
        __syncthreads();
    }

    load2(0, 0);

    #pragma unroll
    for (int mt = 0; mt < 2; mt++)
        #pragma unroll
        for (int h2 = 0; h2 < 2; h2++) {
            int ml = wm + mt * 16 + gid + h2 * 8;
            #pragma unroll
            for (int nt = 0; nt < NT1; nt++) {
                int oc = wn1 + nt * 8 + tq;
                float v0 = acc1[mt][nt][h2 * 2], v1 = acc1[mt][nt][h2 * 2 + 1];
                if (NG == 0 || oc < O1M) {
                    v0 = fmaxf(v0, 0.f); v1 = fmaxf(v1, 0.f);
                    bf16 h0 = __float2bfloat16(v0), h1 = __float2bfloat16(v1);
                    bf16 l0 = __float2bfloat16(v0 - __bfloat162float(h0));
                    bf16 l1 = __float2bfloat16(v1 - __bfloat162float(h1));
                    *(uint32_t*)&smm[HOFFn + ml * HST + oc]            = pk(h0, h1);
                    *(uint32_t*)&smm[HOFFn + BM * HST + ml * HST + oc] = pk(l0, l1);
                } else {
                    int g = (oc - O1M) >> 7;
                    float* gp = (g ? gate1 : gate0) + ((size_t)b * Mtot + m0 + ml) * 128 + (oc & 127);
                    *(float2*)gp = make_float2(1.0f / (1.0f + __expf(v0)),
                                               1.0f / (1.0f + __expf(v1)));
                }
            }
        }
    __syncthreads();

    float acc2[2][NT2][4];
    #pragma unroll
    for (int mt = 0; mt < 2; mt++)
        #pragma unroll
        for (int nt = 0; nt < NT2; nt++)
            #pragma unroll
            for (int q = 0; q < 4; q++) acc2[mt][nt][q] = 0.f;

    for (int ki = 0; ki < NC2; ki++) {
        if (ki + 1 < NC2) { load2((ki + 1) * CH, (ki + 1) & 1); CPA_WAIT(1); }
        else              { CPA_WAIT(0); }
        __syncthreads();
        uint32_t aH = su + (uint32_t)(HOFFn + (wm + arow) * HST + acol + ki * CH) * 2;
        uint32_t aL = aH + (uint32_t)(BM * HST) * 2;
        uint32_t wb = su + (uint32_t)(SOFF + (ki & 1) * STG + WIN) * 2;
        uint32_t bH = wb + (uint32_t)((wn2 + brow) * WST + bcol) * 2;
        uint32_t bL = bH + (uint32_t)WPL * 2;
        mma_blk<HST, WST, 2, NT2, CH>(acc2, aH, aL, bH, bL);
        __syncthreads();
    }

    #pragma unroll
    for (int mt = 0; mt < 2; mt++)
        #pragma unroll
        for (int h2 = 0; h2 < 2; h2++) {
            int m = m0 + wm + mt * 16 + gid + h2 * 8;
            #pragma unroll
            for (int nt = 0; nt < NT2; nt++) {
                int oc = wn2 + nt * 8 + tq;
                float v0 = acc2[mt][nt][h2 * 2], v1 = acc2[mt][nt][h2 * 2 + 1];
                if (OUTM == 0) {
                    bf16 h0 = __float2bfloat16(v0), h1 = __float2bfloat16(v1);
                    bf16 l0 = __float2bfloat16(v0 - __bfloat162float(h0));
                    bf16 l1 = __float2bfloat16(v1 - __bfloat162float(h1));
                    size_t go = ((size_t)b * Mtot + m) * O2 + oc;
                    *(uint32_t*)(Oh + go) = pk(h0, h1);
                    *(uint32_t*)(Ol + go) = pk(l0, l1);
                } else {
                    Of[((size_t)b * O2 + oc)     * Mtot + m] = v0;
                    Of[((size_t)b * O2 + oc + 1) * Mtot + m] = v1;
                }
            }
        }
}

// ================= persistent-weight c-stage (fp16 2-term, BM=128, 16 warps) =================
#define C_TILES 4096
#define C_GRID  1024
#define C_THREADS 512
// smem layout in h16 units
#define C_W1H 0          // 128 x 72
#define C_W1L 9216
#define C_W2H 18432      // 128 x 136
#define C_W2L 35840
#define C_A   53248      // 128 x 72 (single plane)
#define C_H   62464      // 128 x 136 (single plane)
#define C_STGO 79872     // 2 x 16384 (fp32 [64k][128m])
#define C_UNITS 112640   // 225280 bytes

__global__ __launch_bounds__(C_THREADS, 1)
void cpers_k(const float* __restrict__ Xf,
             const h16* __restrict__ W1h, const h16* __restrict__ W1l,
             const h16* __restrict__ W2h, const h16* __restrict__ W2l,
             h16* __restrict__ Oc)
{
    extern __shared__ h16 smh[];
    const int tid = threadIdx.x, lane = tid & 31, warp = tid >> 5;
    const int gid = lane >> 2, tq = (lane & 3) * 2;
    const int wm = (warp >> 2) * 32, wn = (warp & 3) * 32;   // 4m x 4n, MT=2
    const uint32_t su = smem_u32(smh);

    const int arow = (lane & 7) + ((lane >> 3) & 1) * 8;
    const int acol = (lane >> 4) * 8;
    const int brow = (lane & 7) + (lane >> 4) * 8;
    const int bcol = ((lane >> 3) & 1) * 8;

    // ---- resident weights ----
    #pragma unroll
    for (int i = tid; i < 128 * 8; i += C_THREADS) {
        int r = i >> 3, c = (i & 7) * 8;
        cpa16(su + (uint32_t)(C_W1H + r * 72 + c) * 2, W1h + (size_t)r * 64 + c);
        cpa16(su + (uint32_t)(C_W1L + r * 72 + c) * 2, W1l + (size_t)r * 64 + c);
    }
    #pragma unroll
    for (int i = tid; i < 128 * 16; i += C_THREADS) {
        int r = i >> 4, c = (i & 15) * 8;
        cpa16(su + (uint32_t)(C_W2H + r * 136 + c) * 2, W2h + (size_t)r * 128 + c);
        cpa16(su + (uint32_t)(C_W2L + r * 136 + c) * 2, W2l + (size_t)r * 128 + c);
    }
    CPA_COMMIT();

    auto stage = [&](int t, int s) {
        int b = t >> 9, mi = (t & 511) << 7;
        const float* Xg = Xf + (size_t)b * 64 * 65536 + mi;
        uint32_t sbase = su + (uint32_t)(C_STGO + s * 16384) * 2;
        #pragma unroll
        for (int i = tid; i < 64 * 32; i += C_THREADS) {
            int r = i >> 5, c4 = (i & 31) * 4;
            cpa16(sbase + (uint32_t)(r * 128 + c4) * 4, Xg + (size_t)r * 65536 + c4);
        }
        CPA_COMMIT();
    };

    stage(blockIdx.x, 0);
    CPA_WAIT(0);
    __syncthreads();

    int cur = 0;
    for (int t = blockIdx.x, it = 0; t < C_TILES; t += C_GRID, it++) {
        if (it > 0) { CPA_WAIT(0); __syncthreads(); }

        // ---- transpose + fp16 convert -> A (single plane) ----
        {
            const float* stg = (const float*)(smh + C_STGO + cur * 16384);
            int m = tid & 127, k0 = (tid >> 7) * 16;
            #pragma unroll
            for (int j = 0; j < 16; j += 2) {
                int k = k0 + j;
                float v0 = stg[k * 128 + m], v1 = stg[(k + 1) * 128 + m];
                *(uint32_t*)&smh[C_A + m * 72 + k] = pkh2(v0, v1);
            }
        }
        __syncthreads();

        if (t + C_GRID < C_TILES) stage(t + C_GRID, cur ^ 1);

        // ---- GEMM1: K=64 ----
        float acc1[2][4][4];
        #pragma unroll
        for (int mt = 0; mt < 2; mt++)
            #pragma unroll
            for (int nt = 0; nt < 4; nt++)
                #pragma unroll
                for (int q = 0; q < 4; q++) acc1[mt][nt][q] = 0.f;
        {
            uint32_t aH = su + (uint32_t)(C_A + (wm + arow) * 72 + acol) * 2;
            uint32_t bH = su + (uint32_t)(C_W1H + (wn + brow) * 72 + bcol) * 2;
            uint32_t bL = su + (uint32_t)(C_W1L + (wn + brow) * 72 + bcol) * 2;
            mma_blk2<72, 72, 2, 4, 64>(acc1, aH, bH, bL);
        }

        // ---- relu -> h (fp16 single) ----
        #pragma unroll
        for (int mt = 0; mt < 2; mt++)
            #pragma unroll
            for (int h2 = 0; h2 < 2; h2++) {
                int ml = wm + mt * 16 + gid + h2 * 8;
                #pragma unroll
                for (int nt = 0; nt < 4; nt++) {
                    int oc = wn + nt * 8 + tq;
                    float v0 = fmaxf(acc1[mt][nt][h2 * 2],     0.f);
                    float v1 = fmaxf(acc1[mt][nt][h2 * 2 + 1], 0.f);
                    *(uint32_t*)&smh[C_H + ml * 136 + oc] = pkh2(v0, v1);
                }
            }
        __syncthreads();

        // ---- GEMM2: K=128 ----
        float acc2[2][4][4];
        #pragma unroll
        for (int mt = 0; mt < 2; mt++)
            #pragma unroll
            for (int nt = 0; nt < 4; nt++)
                #pragma unroll
                for (int q = 0; q < 4; q++) acc2[mt][nt][q] = 0.f;
        {
            uint32_t aH = su + (uint32_t)(C_H + (wm + arow) * 136 + acol) * 2;
            uint32_t bH = su + (uint32_t)(C_W2H + (wn + brow) * 136 + bcol) * 2;
            uint32_t bL = su + (uint32_t)(C_W2L + (wn + brow) * 136 + bcol) * 2;
            mma_blk2<136, 136, 2, 4, 128>(acc2, aH, bH, bL);
        }

        // ---- output (fp16 single plane) ----
        {
            int b = t >> 9, mi = (t & 511) << 7;
            #pragma unroll
            for (int mt = 0; mt < 2; mt++)
                #pragma unroll
                for (int h2 = 0; h2 < 2; h2++) {
                    int m = mi + wm + mt * 16 + gid + h2 * 8;
                    #pragma unroll
                    for (int nt = 0; nt < 4; nt++) {
                        int oc = wn + nt * 8 + tq;
                        size_t go = ((size_t)b * 65536 + m) * 128 + oc;
                        *(uint32_t*)(Oc + go) = pkh2(acc2[mt][nt][h2 * 2],
                                                     acc2[mt][nt][h2 * 2 + 1]);
                    }
                }
        }
        cur ^= 1;
    }
}

// ================= merged weight split (typed) =================
struct WSeg { const float* s; unsigned short* h; unsigned short* l; int n; int f16; };
struct WParams { WSeg w[10]; };

__global__ __launch_bounds__(256)
void wsplit_all(WParams p) {
    int gi = blockIdx.x * 256 + threadIdx.x;
    #pragma unroll
    for (int s = 0; s < 10; s++) {
        int n = p.w[s].n;
        if (gi < n) {
            float v = p.w[s].s[gi];
            if (p.w[s].f16) {
                h16 hv = __float2half_rn(v);
                p.w[s].h[gi] = __half_as_ushort(hv);
                p.w[s].l[gi] = __half_as_ushort(__float2half_rn(v - __half2float(hv)));
            } else {
                bf16 hv = __float2bfloat16(v);
                p.w[s].h[gi] = __bfloat16_as_ushort(hv);
                p.w[s].l[gi] = __bfloat16_as_ushort(__float2bfloat16(v - __bfloat162float(hv)));
            }
            return;
        }
        gi -= n;
    }
}

// ================= attention =================
static DIB float wsum(float v) {
    #pragma unroll
    for (int o = 16; o > 0; o >>= 1) v += __shfl_xor_sync(0xffffffffu, v, o);
    return v;
}
static DIB float sigm(float x) { return 1.0f / (1.0f + __expf(-x)); }
static DIB float rd2(const bf16* h, const bf16* l, size_t i) {
    return __bfloat162float(h[i]) + __bfloat162float(l[i]);
}
static DIB void wr2(bf16* h, bf16* l, size_t i, float v) {
    bf16 x = __float2bfloat16(v);
    h[i] = x;
    l[i] = __float2bfloat16(v - __bfloat162float(x));
}

__global__ __launch_bounds__(128)
void attend_k(const bf16* __restrict__ eah, const bf16* __restrict__ eal,
              const float* __restrict__ gateb, const float* __restrict__ gatec,
              const bf16* __restrict__ ebh, const bf16* __restrict__ ebl,
              const h16* __restrict__ ec,
              const float* __restrict__ Wab, const float* __restrict__ Wac,
              bf16* __restrict__ agh, bf16* __restrict__ agl)
{
    int gw = (blockIdx.x * 128 + threadIdx.x) >> 5;
    int lane = threadIdx.x & 31;
    int b = gw >> 12, n = gw & 4095;
    int h = n >> 6, w = n & 63;
    size_t nb = (size_t)b * 4096 + n;

    float ea[4], gb[4], gc[4];
    float pab = 0.f, pac = 0.f;
    #pragma unroll
    for (int j = 0; j < 4; j++) {
        int cc = lane + 32 * j;
        ea[j] = rd2(eah, eal, nb * 128 + cc);
        gb[j] = gateb[nb * 128 + cc];
        gc[j] = gatec[nb * 128 + cc];
        pab += Wab[cc] * ea[j];
        pac += Wac[cc] * ea[j];
    }
    float dab = wsum(pab), dac = wsum(pac);

    { // B branch
        float eb[4][4], lb[4];
        #pragma unroll
        for (int p = 0; p < 4; p++) {
            int kh = p >> 1, kw = p & 1;
            size_t base = ((size_t)b * 16384 + (size_t)(2*h + kh) * 128 + (2*w + kw)) * 128;
            float s = 0.f;
            #pragma unroll
            for (int j = 0; j < 4; j++) {
                int cc = lane + 32 * j;
                eb[p][j] = rd2(ebh, ebl, base + cc);
                s += Wab[128 + cc] * eb[p][j];
            }
            lb[p] = fmaxf(dab + wsum(s), 0.0f);
        }
        float mx = fmaxf(fmaxf(lb[0], lb[1]), fmaxf(lb[2], lb[3]));
        float ss = 0.f;
        #pragma unroll
        for (int p = 0; p < 4; p++) { lb[p] = __expf(lb[p] - mx); ss += lb[p]; }
        float inv = 1.0f / ss;
        #pragma unroll
        for (int j = 0; j < 4; j++) {
            float a = 0.f;
            #pragma unroll
            for (int p = 0; p < 4; p++) a += eb[p][j] * lb[p];
            wr2(agh, agl, nb * 384 + lane + 32 * j, sigm(a * inv * gb[j]));
        }
    }
    { // C branch (fp16 single plane)
        float ecf[16][4], lc[16];
        #pragma unroll
        for (int p = 0; p < 16; p++) {
            int kh = p >> 2, kw = p & 3;
            size_t base = ((size_t)b * 65536 + (size_t)(4*h + kh) * 256 + (4*w + kw)) * 128;
            float s = 0.f;
            #pragma unroll
            for (int j = 0; j < 4; j++) {
                int cc = lane + 32 * j;
                ecf[p][j] = __half2float(ec[base + cc]);
                s += Wac[128 + cc] * ecf[p][j];
            }
            lc[p] = fmaxf(dac + wsum(s), 0.0f);
        }
        float mx = lc[0];
        #pragma unroll
        for (int p = 1; p < 16; p++) mx = fmaxf(mx, lc[p]);
        float ss = 0.f;
        #pragma unroll
        for (int p = 0; p < 16; p++) { lc[p] = __expf(lc[p] - mx); ss += lc[p]; }
        float inv = 1.0f / ss;
        #pragma unroll
        for (int j = 0; j < 4; j++) {
            float a = 0.f;
            #pragma unroll
            for (int p = 0; p < 16; p++) a += ecf[p][j] * lc[p];
            wr2(agh, agl, nb * 384 + 128 + lane + 32 * j, sigm(a * inv * gc[j]));
        }
    }
    #pragma unroll
    for (int j = 0; j < 4; j++)
        wr2(agh, agl, nb * 384 + 256 + lane + 32 * j, sigm(ea[j]));
}

// ================= launch =================
static inline int imax(int a, int b) { return a > b ? a : b; }
static inline int fsz1(int K1, int O1M, int NG, int O2) {
    int O1T = O1M + NG * 128, WR = imax(O1T, O2);
    int staging_units = K1 * 68 * 2;
    int units = 2*64*(K1+8) + 2*(2*WR*40) + 2*64*(O1M+8);
    int with_staging = 2*64*(K1+8) + 2*WR*40 + staging_units;
    return imax(units, with_staging) * 2;
}
static inline int fsz0(int O1M, int NG, int O2) {
    int O1T = O1M + NG * 128, WR = imax(O1T, O2);
    int XPL = 64 * 40, WPL = WR * 40;
    int STG = 2 * XPL + 2 * WPL;
    return (2 * STG + 2 * 64 * (O1M + 8)) * 2;
}

extern "C" void kernel_launch(void* const* d_in, const int* in_sizes, int n_in,
                              void* d_out, int out_size)
{
    const float* va  = (const float*)d_in[0];
    const float* vb  = (const float*)d_in[1];
    const float* vc  = (const float*)d_in[2];
    const float* Wa1 = (const float*)d_in[3];
    const float* Wa2 = (const float*)d_in[4];
    const float* Wgb = (const float*)d_in[5];
    const float* Wgc = (const float*)d_in[6];
    const float* Wb1 = (const float*)d_in[7];
    const float* Wb2 = (const float*)d_in[8];
    const float* Wc1 = (const float*)d_in[9];
    const float* Wc2 = (const float*)d_in[10];
    const float* Wab = (const float*)d_in[11];
    const float* Wac = (const float*)d_in[12];
    const float* Wr1 = (const float*)d_in[13];
    const float* Wr2 = (const float*)d_in[14];
    float* out = (float*)d_out;

    bf16 *eah,*eal,*ebh,*ebl,*agh,*agl;
    h16  *ec, *Wc1h,*Wc1l,*Wc2h,*Wc2l;
    float *gb,*gc;
    bf16 *WAh,*WAl,*Wa2h,*Wa2l,*Wb1h,*Wb1l,*Wb2h,*Wb2l,*Wr1h,*Wr1l,*Wr2h,*Wr2l;
    cudaGetSymbolAddress((void**)&eah,g_eah); cudaGetSymbolAddress((void**)&eal,g_eal);
    cudaGetSymbolAddress((void**)&gb,g_gb);   cudaGetSymbolAddress((void**)&gc,g_gc);
    cudaGetSymbolAddress((void**)&ebh,g_ebh); cudaGetSymbolAddress((void**)&ebl,g_ebl);
    cudaGetSymbolAddress((void**)&ec,g_ec);
    cudaGetSymbolAddress((void**)&agh,g_agh); cudaGetSymbolAddress((void**)&agl,g_agl);
    cudaGetSymbolAddress((void**)&WAh,g_WAh); cudaGetSymbolAddress((void**)&WAl,g_WAl);
    cudaGetSymbolAddress((void**)&Wa2h,g_Wa2h); cudaGetSymbolAddress((void**)&Wa2l,g_Wa2l);
    cudaGetSymbolAddress((void**)&Wb1h,g_Wb1h); cudaGetSymbolAddress((void**)&Wb1l,g_Wb1l);
    cudaGetSymbolAddress((void**)&Wb2h,g_Wb2h); cudaGetSymbolAddress((void**)&Wb2l,g_Wb2l);
    cudaGetSymbolAddress((void**)&Wc1h,g_Wc1h); cudaGetSymbolAddress((void**)&Wc1l,g_Wc1l);
    cudaGetSymbolAddress((void**)&Wc2h,g_Wc2h); cudaGetSymbolAddress((void**)&Wc2l,g_Wc2l);
    cudaGetSymbolAddress((void**)&Wr1h,g_Wr1h); cudaGetSymbolAddress((void**)&Wr1l,g_Wr1l);
    cudaGetSymbolAddress((void**)&Wr2h,g_Wr2h); cudaGetSymbolAddress((void**)&Wr2l,g_Wr2l);

    int sA = fsz1(256, 128, 2, 128);
    int sB = fsz1(128, 128, 0, 128);
    int sR = fsz0(256, 0, 256);
    int sC = C_UNITS * 2;
    cudaFuncSetAttribute(fuse_k<256,128,2,128,1,0,1>, cudaFuncAttributeMaxDynamicSharedMemorySize, sA);
    cudaFuncSetAttribute(fuse_k<128,128,0,128,2,0,1>, cudaFuncAttributeMaxDynamicSharedMemorySize, sB);
    cudaFuncSetAttribute(fuse_k<384,256,0,256,1,2,0>, cudaFuncAttributeMaxDynamicSharedMemorySize, sR);
    cudaFuncSetAttribute(cpers_k, cudaFuncAttributeMaxDynamicSharedMemorySize, sC);

    WParams P;
    P.w[0] = {Wa1, (unsigned short*)WAh,           (unsigned short*)WAl,           32768, 0};
    P.w[1] = {Wgb, (unsigned short*)(WAh + 32768), (unsigned short*)(WAl + 32768), 32768, 0};
    P.w[2] = {Wgc, (unsigned short*)(WAh + 65536), (unsigned short*)(WAl + 65536), 32768, 0};
    P.w[3] = {Wa2, (unsigned short*)Wa2h, (unsigned short*)Wa2l, 16384, 0};
    P.w[4] = {Wb1, (unsigned short*)Wb1h, (unsigned short*)Wb1l, 16384, 0};
    P.w[5] = {Wb2, (unsigned short*)Wb2h, (unsigned short*)Wb2l, 16384, 0};
    P.w[6] = {Wc1, (unsigned short*)Wc1h, (unsigned short*)Wc1l, 8192,  1};
    P.w[7] = {Wc2, (unsigned short*)Wc2h, (unsigned short*)Wc2l, 16384, 1};
    P.w[8] = {Wr1, (unsigned short*)Wr1h, (unsigned short*)Wr1l, 98304, 0};
    P.w[9] = {Wr2, (unsigned short*)Wr2h, (unsigned short*)Wr2l, 65536, 0};
    wsplit_all<<<(335872 + 255) / 256, 256>>>(P);

    // a-stage (fp32 X direct)
    fuse_k<256,128,2,128,1,0,1><<<dim3(64, 1, NB), 256, sA>>>(
        va, nullptr, nullptr, WAh, WAl, Wa2h, Wa2l, gb, gc, eah, eal, nullptr, 4096);
    // b-stage
    fuse_k<128,128,0,128,2,0,1><<<dim3(256, 1, NB), 256, sB>>>(
        vb, nullptr, nullptr, Wb1h, Wb1l, Wb2h, Wb2l, nullptr, nullptr, ebh, ebl, nullptr, 16384);
    // c-stage (persistent weights, fp16 2-term)
    cpers_k<<<C_GRID, C_THREADS, sC>>>(vc, Wc1h, Wc1l, Wc2h, Wc2l, ec);

    attend_k<<<8192, 128>>>(eah, eal, gb, gc, ebh, ebl, ec, Wab, Wac, agh, agl);

    // readout (bf16 hi/lo X)
    fuse_k<384,256,0,256,1,2,0><<<dim3(64, 1, NB), 256, sR>>>(
        nullptr, agh, agl, Wr1h, Wr1l, Wr2h, Wr2l, nullptr, nullptr, nullptr, nullptr, out, 4096);
}

// round 16
// speedup vs baseline: 2.4159x; 1.0714x over previous
#include <cuda_runtime.h>
#include <cuda_bf16.h>
#include <cuda_fp16.h>
#include <cstdint>

using bf16 = __nv_bfloat16;
using h16  = __half;
#define DIB __device__ __forceinline__
#define NB 8

// ================= scratch (device globals) =================
__device__ __align__(16) bf16 g_eah[(size_t)NB*4096*128],  g_eal[(size_t)NB*4096*128];
__device__ __align__(16) float g_gb[(size_t)NB*4096*128],  g_gc[(size_t)NB*4096*128];
__device__ __align__(16) h16  g_eb [(size_t)NB*16384*128];
__device__ __align__(16) h16  g_ec [(size_t)NB*65536*128];
__device__ __align__(16) bf16 g_agh[(size_t)NB*4096*384],  g_agl[(size_t)NB*4096*384];
__device__ __align__(16) bf16 g_WAh[384*256],  g_WAl[384*256];   // Wa1|Wgb|Wgc stacked
__device__ __align__(16) bf16 g_Wa2h[128*128], g_Wa2l[128*128];
__device__ __align__(16) h16  g_Wb1h[128*128], g_Wb1l[128*128];
__device__ __align__(16) h16  g_Wb2h[128*128], g_Wb2l[128*128];
__device__ __align__(16) h16  g_Wc1h[128*64],  g_Wc1l[128*64];
__device__ __align__(16) h16  g_Wc2h[128*128], g_Wc2l[128*128];
__device__ __align__(16) bf16 g_Wr1h[256*384], g_Wr1l[256*384];
__device__ __align__(16) bf16 g_Wr2h[256*256], g_Wr2l[256*256];

// ================= helpers =================
static DIB uint32_t smem_u32(const void* p) {
    uint32_t a;
    asm("{ .reg .u64 t; cvta.to.shared.u64 t, %1; cvt.u32.u64 %0, t; }" : "=r"(a) : "l"(p));
    return a;
}
static DIB void cpa16(uint32_t s, const void* g) {
    asm volatile("cp.async.ca.shared.global [%0],[%1],16;" :: "r"(s), "l"(g) : "memory");
}
#define CPA_COMMIT() asm volatile("cp.async.commit_group;" ::: "memory")
#define CPA_WAIT(N)  asm volatile("cp.async.wait_group " #N ";" ::: "memory")
static DIB void ldsm4(uint32_t* r, uint32_t a) {
    asm volatile("ldmatrix.sync.aligned.m8n8.x4.shared.b16 {%0,%1,%2,%3},[%4];"
        : "=r"(r[0]), "=r"(r[1]), "=r"(r[2]), "=r"(r[3]) : "r"(a));
}
static DIB void mma16816(float* d, const uint32_t* a, const uint32_t* b) {
    asm volatile(
        "mma.sync.aligned.m16n8k16.row.col.f32.bf16.bf16.f32 "
        "{%0,%1,%2,%3}, {%4,%5,%6,%7}, {%8,%9}, {%0,%1,%2,%3};"
        : "+f"(d[0]), "+f"(d[1]), "+f"(d[2]), "+f"(d[3])
        : "r"(a[0]), "r"(a[1]), "r"(a[2]), "r"(a[3]), "r"(b[0]), "r"(b[1]));
}
static DIB void mma16816h(float* d, const uint32_t* a, const uint32_t* b) {
    asm volatile(
        "mma.sync.aligned.m16n8k16.row.col.f32.f16.f16.f32 "
        "{%0,%1,%2,%3}, {%4,%5,%6,%7}, {%8,%9}, {%0,%1,%2,%3};"
        : "+f"(d[0]), "+f"(d[1]), "+f"(d[2]), "+f"(d[3])
        : "r"(a[0]), "r"(a[1]), "r"(a[2]), "r"(a[3]), "r"(b[0]), "r"(b[1]));
}
static DIB uint32_t pk(bf16 lo, bf16 hi) {
    return (uint32_t)__bfloat16_as_ushort(lo) | ((uint32_t)__bfloat16_as_ushort(hi) << 16);
}
static DIB uint32_t pkh2(float v0, float v1) {
    h16 a = __float2half_rn(v0), b = __float2half_rn(v1);
    return (uint32_t)__half_as_ushort(a) | ((uint32_t)__half_as_ushort(b) << 16);
}

// 3-term bf16 split: acc += Ah*(Bh+Bl) + Al*Bh
template<int STA, int STB, int MT, int NT, int CHT>
static DIB void mma_blk(float (&acc)[MT][NT][4], uint32_t aH, uint32_t aL,
                        uint32_t bH, uint32_t bL)
{
    #pragma unroll
    for (int ks = 0; ks < CHT; ks += 16) {
        uint32_t Ah[MT][4], Al[MT][4], Bh[NT/2][4], Bl[NT/2][4];
        #pragma unroll
        for (int mt = 0; mt < MT; mt++) {
            ldsm4(Ah[mt], aH + (uint32_t)(mt*16*STA + ks) * 2);
            ldsm4(Al[mt], aL + (uint32_t)(mt*16*STA + ks) * 2);
        }
        #pragma unroll
        for (int g = 0; g < NT/2; g++) {
            ldsm4(Bh[g], bH + (uint32_t)(g*16*STB + ks) * 2);
            ldsm4(Bl[g], bL + (uint32_t)(g*16*STB + ks) * 2);
        }
        #pragma unroll
        for (int nt = 0; nt < NT; nt++) {
            uint32_t bh[2] = {Bh[nt>>1][(nt&1)*2], Bh[nt>>1][(nt&1)*2+1]};
            uint32_t bl[2] = {Bl[nt>>1][(nt&1)*2], Bl[nt>>1][(nt&1)*2+1]};
            #pragma unroll
            for (int mt = 0; mt < MT; mt++) {
                mma16816(acc[mt][nt], Ah[mt], bh);
                mma16816(acc[mt][nt], Ah[mt], bl);
                mma16816(acc[mt][nt], Al[mt], bh);
            }
        }
    }
}

// 2-term fp16: acc += Ah*(Bh+Bl)   (A single plane)
template<int STA, int STB, int MT, int NT, int CHT>
static DIB void mma_blk2(float (&acc)[MT][NT][4], uint32_t aH,
                         uint32_t bH, uint32_t bL)
{
    #pragma unroll
    for (int ks = 0; ks < CHT; ks += 16) {
        uint32_t Ah[MT][4], Bh[NT/2][4], Bl[NT/2][4];
        #pragma unroll
        for (int mt = 0; mt < MT; mt++)
            ldsm4(Ah[mt], aH + (uint32_t)(mt*16*STA + ks) * 2);
        #pragma unroll
        for (int g = 0; g < NT/2; g++) {
            ldsm4(Bh[g], bH + (uint32_t)(g*16*STB + ks) * 2);
            ldsm4(Bl[g], bL + (uint32_t)(g*16*STB + ks) * 2);
        }
        #pragma unroll
        for (int nt = 0; nt < NT; nt++) {
            uint32_t bh[2] = {Bh[nt>>1][(nt&1)*2], Bh[nt>>1][(nt&1)*2+1]};
            uint32_t bl[2] = {Bl[nt>>1][(nt&1)*2], Bl[nt>>1][(nt&1)*2+1]};
            #pragma unroll
            for (int mt = 0; mt < MT; mt++) {
                mma16816h(acc[mt][nt], Ah[mt], bh);
                mma16816h(acc[mt][nt], Ah[mt], bl);
            }
        }
    }
}

// ================= unified fused 2-layer GEMM (a/readout; bf16 3-term) =================
template<int K1, int O1M, int NG, int O2, int OCC, int OUTM, int XMODE>
__global__ __launch_bounds__(256, OCC)
void fuse_k(const float* __restrict__ Xf,
            const bf16* __restrict__ Xh, const bf16* __restrict__ Xl,
            const bf16* __restrict__ W1h, const bf16* __restrict__ W1l,
            const bf16* __restrict__ W2h, const bf16* __restrict__ W2l,
            float* __restrict__ gate0, float* __restrict__ gate1,
            bf16* __restrict__ Oh, bf16* __restrict__ Ol, float* __restrict__ Of,
            int Mtot)
{
    constexpr int BM = 64, CH = 32, WST = 40;
    constexpr int O1T = O1M + NG * 128;
    constexpr int WR  = (O1T > O2) ? O1T : O2;
    constexpr int HST = O1M + 8;
    constexpr int WPL = WR * WST;
    constexpr int AST = K1 + 8;
    constexpr int APL = BM * AST;
    constexpr int XST = 40;
    constexpr int XPL = BM * XST;
    constexpr int STG  = (XMODE == 1) ? (2 * WPL) : (2 * XPL + 2 * WPL);
    constexpr int SOFF = (XMODE == 1) ? (2 * APL) : 0;
    constexpr int WIN  = (XMODE == 1) ? 0 : (2 * XPL);
    constexpr int HOFFn = SOFF + 2 * STG;
    constexpr int NC1 = K1 / CH, NC2 = O1M / CH;
    constexpr int NT1 = O1T / 32, NT2 = O2 / 32;

    extern __shared__ bf16 smm[];
    const int tid = threadIdx.x, lane = tid & 31, warp = tid >> 5;
    const int gid = lane >> 2, tq = (lane & 3) * 2;
    const int wm  = (warp >> 2) * 32;
    const int wn1 = (warp & 3) * (NT1 * 8);
    const int wn2 = (warp & 3) * (NT2 * 8);
    const int b = blockIdx.z, m0 = blockIdx.x * BM;
    const uint32_t su = smem_u32(smm);

    const int arow = (lane & 7) + ((lane >> 3) & 1) * 8;
    const int acol = (lane >> 4) * 8;
    const int brow = (lane & 7) + (lane >> 4) * 8;
    const int bcol = ((lane >> 3) & 1) * 8;

    auto load1 = [&](int kc, int s) {
        uint32_t wb = su + (uint32_t)(SOFF + s * STG + WIN) * 2;
        if constexpr (XMODE == 0) {
            uint32_t base = su + (uint32_t)(s * STG) * 2;
            const bf16* Xhb = Xh + ((size_t)b * Mtot + m0) * K1;
            const bf16* Xlb = Xl + ((size_t)b * Mtot + m0) * K1;
            #pragma unroll
            for (int i = tid; i < BM * 4; i += 256) {
                int r = i >> 2, c = (i & 3) * 8;
                cpa16(base + (uint32_t)(r * XST + c) * 2,       Xhb + (size_t)r * K1 + kc + c);
                cpa16(base + (uint32_t)(XPL + r * XST + c) * 2, Xlb + (size_t)r * K1 + kc + c);
            }
        }
        #pragma unroll
        for (int i = tid; i < O1T * 4; i += 256) {
            int r = i >> 2, c = (i & 3) * 8;
            cpa16(wb + (uint32_t)(r * WST + c) * 2,       W1h + (size_t)r * K1 + kc + c);
            cpa16(wb + (uint32_t)(WPL + r * WST + c) * 2, W1l + (size_t)r * K1 + kc + c);
        }
        CPA_COMMIT();
    };
    auto load2 = [&](int kc, int s) {
        uint32_t wb = su + (uint32_t)(SOFF + s * STG + WIN) * 2;
        #pragma unroll
        for (int i = tid; i < O2 * 4; i += 256) {
            int r = i >> 2, c = (i & 3) * 8;
            cpa16(wb + (uint32_t)(r * WST + c) * 2,       W2h + (size_t)r * O1M + kc + c);
            cpa16(wb + (uint32_t)(WPL + r * WST + c) * 2, W2l + (size_t)r * O1M + kc + c);
        }
        CPA_COMMIT();
    };

    if constexpr (XMODE == 1) {
        constexpr int SST_OFF = SOFF + STG;
        uint32_t sbase = su + (uint32_t)SST_OFF * 2;
        const float* Xg = Xf + (size_t)b * K1 * Mtot + m0;
        #pragma unroll
        for (int i = tid; i < K1 * 16; i += 256) {
            int r = i >> 4, c4 = (i & 15) * 4;
            cpa16(sbase + (uint32_t)(r * 68 + c4) * 4, Xg + (size_t)r * Mtot + c4);
        }
        CPA_COMMIT();
        load1(0, 0);
        CPA_WAIT(1);
        __syncthreads();
        const float* stg = (const float*)(smm + SST_OFF);
        int m = tid & 63, k0 = (tid >> 6) * (K1 / 4);
        #pragma unroll
        for (int j = 0; j < K1 / 4; j += 2) {
            int k = k0 + j;
            float v0 = stg[k * 68 + m], v1 = stg[(k + 1) * 68 + m];
            bf16 h0 = __float2bfloat16(v0), h1 = __float2bfloat16(v1);
            bf16 l0 = __float2bfloat16(v0 - __bfloat162float(h0));
            bf16 l1 = __float2bfloat16(v1 - __bfloat162float(h1));
            *(uint32_t*)&smm[(size_t)m * AST + k]       = pk(h0, h1);
            *(uint32_t*)&smm[(size_t)APL + m * AST + k] = pk(l0, l1);
        }
        __syncthreads();
    } else {
        load1(0, 0);
    }

    float acc1[2][NT1][4];
    #pragma unroll
    for (int mt = 0; mt < 2; mt++)
        #pragma unroll
        for (int nt = 0; nt < NT1; nt++)
            #pragma unroll
            for (int q = 0; q < 4; q++) acc1[mt][nt][q] = 0.f;

    for (int ki = 0; ki < NC1; ki++) {
        if (ki + 1 < NC1) { load1((ki + 1) * CH, (ki + 1) & 1); CPA_WAIT(1); }
        else              { CPA_WAIT(0); }
        __syncthreads();
        uint32_t aH, aL;
        if constexpr (XMODE == 1) {
            aH = su + (uint32_t)((wm + arow) * AST + acol + ki * CH) * 2;
            aL = aH + (uint32_t)APL * 2;
        } else {
            uint32_t base = su + (uint32_t)((ki & 1) * STG) * 2;
            aH = base + (uint32_t)((wm + arow) * XST + acol) * 2;
            aL = aH + (uint32_t)XPL * 2;
        }
        uint32_t wb = su + (uint32_t)(SOFF + (ki & 1) * STG + WIN) * 2;
        uint32_t bH = wb + (uint32_t)((wn1 + brow) * WST + bcol) * 2;
        uint32_t bL = bH + (uint32_t)WPL * 2;
        mma_blk<(XMODE == 1 ? AST : XST), WST, 2, NT1, CH>(acc1, aH, aL, bH, bL);
        __syncthreads();
    }

    load2(0, 0);

    #pragma unroll
    for (int mt = 0; mt < 2; mt++)
        #pragma unroll
        for (int h2 = 0; h2 < 2; h2++) {
            int ml = wm + mt * 16 + gid + h2 * 8;
            #pragma unroll
            for (int nt = 0; nt < NT1; nt++) {
                int oc = wn1 + nt * 8 + tq;
                float v0 = acc1[mt][nt][h2 * 2], v1 = acc1[mt][nt][h2 * 2 + 1];
                if (NG == 0 || oc < O1M) {
                    v0 = fmaxf(v0, 0.f); v1 = fmaxf(v1, 0.f);
                    bf16 h0 = __float2bfloat16(v0), h1 = __float2bfloat16(v1);
                    bf16 l0 = __float2bfloat16(v0 - __bfloat162float(h0));
                    bf16 l1 = __float2bfloat16(v1 - __bfloat162float(h1));
                    *(uint32_t*)&smm[HOFFn + ml * HST + oc]            = pk(h0, h1);
                    *(uint32_t*)&smm[HOFFn + BM * HST + ml * HST + oc] = pk(l0, l1);
                } else {
                    int g = (oc - O1M) >> 7;
                    float* gp = (g ? gate1 : gate0) + ((size_t)b * Mtot + m0 + ml) * 128 + (oc & 127);
                    *(float2*)gp = make_float2(1.0f / (1.0f + __expf(v0)),
                                               1.0f / (1.0f + __expf(v1)));
                }
            }
        }
    __syncthreads();

    float acc2[2][NT2][4];
    #pragma unroll
    for (int mt = 0; mt < 2; mt++)
        #pragma unroll
        for (int nt = 0; nt < NT2; nt++)
            #pragma unroll
            for (int q = 0; q < 4; q++) acc2[mt][nt][q] = 0.f;

    for (int ki = 0; ki < NC2; ki++) {
        if (ki + 1 < NC2) { load2((ki + 1) * CH, (ki + 1) & 1); CPA_WAIT(1); }
        else              { CPA_WAIT(0); }
        __syncthreads();
        uint32_t aH = su + (uint32_t)(HOFFn + (wm + arow) * HST + acol + ki * CH) * 2;
        uint32_t aL = aH + (uint32_t)(BM * HST) * 2;
        uint32_t wb = su + (uint32_t)(SOFF + (ki & 1) * STG + WIN) * 2;
        uint32_t bH = wb + (uint32_t)((wn2 + brow) * WST + bcol) * 2;
        uint32_t bL = bH + (uint32_t)WPL * 2;
        mma_blk<HST, WST, 2, NT2, CH>(acc2, aH, aL, bH, bL);
        __syncthreads();
    }

    #pragma unroll
    for (int mt = 0; mt < 2; mt++)
        #pragma unroll
        for (int h2 = 0; h2 < 2; h2++) {
            int m = m0 + wm + mt * 16 + gid + h2 * 8;
            #pragma unroll
            for (int nt = 0; nt < NT2; nt++) {
                int oc = wn2 + nt * 8 + tq;
                float v0 = acc2[mt][nt][h2 * 2], v1 = acc2[mt][nt][h2 * 2 + 1];
                if (OUTM == 0) {
                    bf16 h0 = __float2bfloat16(v0), h1 = __float2bfloat16(v1);
                    bf16 l0 = __float2bfloat16(v0 - __bfloat162float(h0));
                    bf16 l1 = __float2bfloat16(v1 - __bfloat162float(h1));
                    size_t go = ((size_t)b * Mtot + m) * O2 + oc;
                    *(uint32_t*)(Oh + go) = pk(h0, h1);
                    *(uint32_t*)(Ol + go) = pk(l0, l1);
                } else {
                    Of[((size_t)b * O2 + oc)     * Mtot + m] = v0;
                    Of[((size_t)b * O2 + oc + 1) * Mtot + m] = v1;
                }
            }
        }
}

// ================= b-stage fused kernel (fp16 2-term, XMODE1-style) =================
// K1=128, O1=128, O2=128, BM=64, CH=32. Output single fp16 plane.
#define B_AST 136
#define B_APL (64 * B_AST)           // 8704
#define B_WPL (128 * 40)             // 5120
#define B_STG (2 * B_WPL)            // 10240
#define B_SOFF B_APL                 // 8704
#define B_SST  (B_SOFF + B_STG)      // 18944 (fp32 staging overlays stage1+H head)
#define B_HOFF (B_SOFF + 2 * B_STG)  // 29184
#define B_UNITS (B_HOFF + 64 * B_AST)// 37888 units -> 75776 bytes

__global__ __launch_bounds__(256, 2)
void fuseb_k(const float* __restrict__ Xf,
             const h16* __restrict__ W1h, const h16* __restrict__ W1l,
             const h16* __restrict__ W2h, const h16* __restrict__ W2l,
             h16* __restrict__ Oc)
{
    constexpr int Mtot = 16384;
    extern __shared__ h16 smh[];
    const int tid = threadIdx.x, lane = tid & 31, warp = tid >> 5;
    const int gid = lane >> 2, tq = (lane & 3) * 2;
    const int wm = (warp >> 2) * 32, wn = (warp & 3) * 32;
    const int b = blockIdx.z, m0 = blockIdx.x * 64;
    const uint32_t su = smem_u32(smh);

    const int arow = (lane & 7) + ((lane >> 3) & 1) * 8;
    const int acol = (lane >> 4) * 8;
    const int brow = (lane & 7) + (lane >> 4) * 8;
    const int bcol = ((lane >> 3) & 1) * 8;

    auto load1 = [&](int kc, int s) {
        uint32_t wb = su + (uint32_t)(B_SOFF + s * B_STG) * 2;
        #pragma unroll
        for (int i = tid; i < 128 * 4; i += 256) {
            int r = i >> 2, c = (i & 3) * 8;
            cpa16(wb + (uint32_t)(r * 40 + c) * 2,         W1h + (size_t)r * 128 + kc + c);
            cpa16(wb + (uint32_t)(B_WPL + r * 40 + c) * 2, W1l + (size_t)r * 128 + kc + c);
        }
        CPA_COMMIT();
    };
    auto load2 = [&](int kc, int s) {
        uint32_t wb = su + (uint32_t)(B_SOFF + s * B_STG) * 2;
        #pragma unroll
        for (int i = tid; i < 128 * 4; i += 256) {
            int r = i >> 2, c = (i & 3) * 8;
            cpa16(wb + (uint32_t)(r * 40 + c) * 2,         W2h + (size_t)r * 128 + kc + c);
            cpa16(wb + (uint32_t)(B_WPL + r * 40 + c) * 2, W2l + (size_t)r * 128 + kc + c);
        }
        CPA_COMMIT();
    };

    // phase 0: fp32 X ingest -> fp16 A plane
    {
        uint32_t sbase = su + (uint32_t)B_SST * 2;
        const float* Xg = Xf + (size_t)b * 128 * Mtot + m0;
        #pragma unroll
        for (int i = tid; i < 128 * 16; i += 256) {
            int r = i >> 4, c4 = (i & 15) * 4;
            cpa16(sbase + (uint32_t)(r * 68 + c4) * 4, Xg + (size_t)r * Mtot + c4);
        }
        CPA_COMMIT();
        load1(0, 0);
        CPA_WAIT(1);
        __syncthreads();
        const float* stg = (const float*)(smh + B_SST);
        int m = tid & 63, k0 = (tid >> 6) * 32;
        #pragma unroll
        for (int j = 0; j < 32; j += 2) {
            int k = k0 + j;
            float v0 = stg[k * 68 + m], v1 = stg[(k + 1) * 68 + m];
            *(uint32_t*)&smh[m * B_AST + k] = pkh2(v0, v1);
        }
        __syncthreads();
    }

    // GEMM1: K=128, A plane x W1(fp16 h/l)
    float acc1[2][4][4];
    #pragma unroll
    for (int mt = 0; mt < 2; mt++)
        #pragma unroll
        for (int nt = 0; nt < 4; nt++)
            #pragma unroll
            for (int q = 0; q < 4; q++) acc1[mt][nt][q] = 0.f;

    for (int ki = 0; ki < 4; ki++) {
        if (ki + 1 < 4) { load1((ki + 1) * 32, (ki + 1) & 1); CPA_WAIT(1); }
        else            { CPA_WAIT(0); }
        __syncthreads();
        uint32_t aH = su + (uint32_t)((wm + arow) * B_AST + acol + ki * 32) * 2;
        uint32_t wb = su + (uint32_t)(B_SOFF + (ki & 1) * B_STG) * 2;
        uint32_t bH = wb + (uint32_t)((wn + brow) * 40 + bcol) * 2;
        uint32_t bL = bH + (uint32_t)B_WPL * 2;
        mma_blk2<B_AST, 40, 2, 4, 32>(acc1, aH, bH, bL);
        __syncthreads();
    }

    load2(0, 0);

    // relu -> h fp16 plane
    #pragma unroll
    for (int mt = 0; mt < 2; mt++)
        #pragma unroll
        for (int h2 = 0; h2 < 2; h2++) {
            int ml = wm + mt * 16 + gid + h2 * 8;
            #pragma unroll
            for (int nt = 0; nt < 4; nt++) {
                int oc = wn + nt * 8 + tq;
                float v0 = fmaxf(acc1[mt][nt][h2 * 2],     0.f);
                float v1 = fmaxf(acc1[mt][nt][h2 * 2 + 1], 0.f);
                *(uint32_t*)&smh[B_HOFF + ml * B_AST + oc] = pkh2(v0, v1);
            }
        }
    __syncthreads();

    // GEMM2: K=128
    float acc2[2][4][4];
    #pragma unroll
    for (int mt = 0; mt < 2; mt++)
        #pragma unroll
        for (int nt = 0; nt < 4; nt++)
            #pragma unroll
            for (int q = 0; q < 4; q++) acc2[mt][nt][q] = 0.f;

    for (int ki = 0; ki < 4; ki++) {
        if (ki + 1 < 4) { load2((ki + 1) * 32, (ki + 1) & 1); CPA_WAIT(1); }
        else            { CPA_WAIT(0); }
        __syncthreads();
        uint32_t aH = su + (uint32_t)(B_HOFF + (wm + arow) * B_AST + acol + ki * 32) * 2;
        uint32_t wb = su + (uint32_t)(B_SOFF + (ki & 1) * B_STG) * 2;
        uint32_t bH = wb + (uint32_t)((wn + brow) * 40 + bcol) * 2;
        uint32_t bL = bH + (uint32_t)B_WPL * 2;
        mma_blk2<B_AST, 40, 2, 4, 32>(acc2, aH, bH, bL);
        __syncthreads();
    }

    // output (fp16 single plane)
    #pragma unroll
    for (int mt = 0; mt < 2; mt++)
        #pragma unroll
        for (int h2 = 0; h2 < 2; h2++) {
            int m = m0 + wm + mt * 16 + gid + h2 * 8;
            #pragma unroll
            for (int nt = 0; nt < 4; nt++) {
                int oc = wn + nt * 8 + tq;
                size_t go = ((size_t)b * Mtot + m) * 128 + oc;
                *(uint32_t*)(Oc + go) = pkh2(acc2[mt][nt][h2 * 2], acc2[mt][nt][h2 * 2 + 1]);
            }
        }
}

// ================= persistent-weight c-stage (fp16 2-term, BM=128, 16 warps) =================
#define C_TILES 4096
#define C_GRID  1024
#define C_THREADS 512
#define C_W1H 0
#define C_W1L 9216
#define C_W2H 18432
#define C_W2L 35840
#define C_A   53248
#define C_H   62464
#define C_STGO 79872
#define C_UNITS 112640

__global__ __launch_bounds__(C_THREADS, 1)
void cpers_k(const float* __restrict__ Xf,
             const h16* __restrict__ W1h, const h16* __restrict__ W1l,
             const h16* __restrict__ W2h, const h16* __restrict__ W2l,
             h16* __restrict__ Oc)
{
    extern __shared__ h16 smh[];
    const int tid = threadIdx.x, lane = tid & 31, warp = tid >> 5;
    const int gid = lane >> 2, tq = (lane & 3) * 2;
    const int wm = (warp >> 2) * 32, wn = (warp & 3) * 32;
    const uint32_t su = smem_u32(smh);

    const int arow = (lane & 7) + ((lane >> 3) & 1) * 8;
    const int acol = (lane >> 4) * 8;
    const int brow = (lane & 7) + (lane >> 4) * 8;
    const int bcol = ((lane >> 3) & 1) * 8;

    #pragma unroll
    for (int i = tid; i < 128 * 8; i += C_THREADS) {
        int r = i >> 3, c = (i & 7) * 8;
        cpa16(su + (uint32_t)(C_W1H + r * 72 + c) * 2, W1h + (size_t)r * 64 + c);
        cpa16(su + (uint32_t)(C_W1L + r * 72 + c) * 2, W1l + (size_t)r * 64 + c);
    }
    #pragma unroll
    for (int i = tid; i < 128 * 16; i += C_THREADS) {
        int r = i >> 4, c = (i & 15) * 8;
        cpa16(su + (uint32_t)(C_W2H + r * 136 + c) * 2, W2h + (size_t)r * 128 + c);
        cpa16(su + (uint32_t)(C_W2L + r * 136 + c) * 2, W2l + (size_t)r * 128 + c);
    }
    CPA_COMMIT();

    auto stage = [&](int t, int s) {
        int b = t >> 9, mi = (t & 511) << 7;
        const float* Xg = Xf + (size_t)b * 64 * 65536 + mi;
        uint32_t sbase = su + (uint32_t)(C_STGO + s * 16384) * 2;
        #pragma unroll
        for (int i = tid; i < 64 * 32; i += C_THREADS) {
            int r = i >> 5, c4 = (i & 31) * 4;
            cpa16(sbase + (uint32_t)(r * 128 + c4) * 4, Xg + (size_t)r * 65536 + c4);
        }
        CPA_COMMIT();
    };

    stage(blockIdx.x, 0);
    CPA_WAIT(0);
    __syncthreads();

    int cur = 0;
    for (int t = blockIdx.x, it = 0; t < C_TILES; t += C_GRID, it++) {
        if (it > 0) { CPA_WAIT(0); __syncthreads(); }

        {
            const float* stg = (const float*)(smh + C_STGO + cur * 16384);
            int m = tid & 127, k0 = (tid >> 7) * 16;
            #pragma unroll
            for (int j = 0; j < 16; j += 2) {
                int k = k0 + j;
                float v0 = stg[k * 128 + m], v1 = stg[(k + 1) * 128 + m];
                *(uint32_t*)&smh[C_A + m * 72 + k] = pkh2(v0, v1);
            }
        }
        __syncthreads();

        if (t + C_GRID < C_TILES) stage(t + C_GRID, cur ^ 1);

        float acc1[2][4][4];
        #pragma unroll
        for (int mt = 0; mt < 2; mt++)
            #pragma unroll
            for (int nt = 0; nt < 4; nt++)
                #pragma unroll
                for (int q = 0; q < 4; q++) acc1[mt][nt][q] = 0.f;
        {
            uint32_t aH = su + (uint32_t)(C_A + (wm + arow) * 72 + acol) * 2;
            uint32_t bH = su + (uint32_t)(C_W1H + (wn + brow) * 72 + bcol) * 2;
            uint32_t bL = su + (uint32_t)(C_W1L + (wn + brow) * 72 + bcol) * 2;
            mma_blk2<72, 72, 2, 4, 64>(acc1, aH, bH, bL);
        }

        #pragma unroll
        for (int mt = 0; mt < 2; mt++)
            #pragma unroll
            for (int h2 = 0; h2 < 2; h2++) {
                int ml = wm + mt * 16 + gid + h2 * 8;
                #pragma unroll
                for (int nt = 0; nt < 4; nt++) {
                    int oc = wn + nt * 8 + tq;
                    float v0 = fmaxf(acc1[mt][nt][h2 * 2],     0.f);
                    float v1 = fmaxf(acc1[mt][nt][h2 * 2 + 1], 0.f);
                    *(uint32_t*)&smh[C_H + ml * 136 + oc] = pkh2(v0, v1);
                }
            }
        __syncthreads();

        float acc2[2][4][4];
        #pragma unroll
        for (int mt = 0; mt < 2; mt++)
            #pragma unroll
            for (int nt = 0; nt < 4; nt++)
                #pragma unroll
                for (int q = 0; q < 4; q++) acc2[mt][nt][q] = 0.f;
        {
            uint32_t aH = su + (uint32_t)(C_H + (wm + arow) * 136 + acol) * 2;
            uint32_t bH = su + (uint32_t)(C_W2H + (wn + brow) * 136 + bcol) * 2;
            uint32_t bL = su + (uint32_t)(C_W2L + (wn + brow) * 136 + bcol) * 2;
            mma_blk2<136, 136, 2, 4, 128>(acc2, aH, bH, bL);
        }

        {
            int b = t >> 9, mi = (t & 511) << 7;
            #pragma unroll
            for (int mt = 0; mt < 2; mt++)
                #pragma unroll
                for (int h2 = 0; h2 < 2; h2++) {
                    int m = mi + wm + mt * 16 + gid + h2 * 8;
                    #pragma unroll
                    for (int nt = 0; nt < 4; nt++) {
                        int oc = wn + nt * 8 + tq;
                        size_t go = ((size_t)b * 65536 + m) * 128 + oc;
                        *(uint32_t*)(Oc + go) = pkh2(acc2[mt][nt][h2 * 2],
                                                     acc2[mt][nt][h2 * 2 + 1]);
                    }
                }
        }
        cur ^= 1;
    }
}

// ================= merged weight split (typed) =================
struct WSeg { const float* s; unsigned short* h; unsigned short* l; int n; int f16; };
struct WParams { WSeg w[10]; };

__global__ __launch_bounds__(256)
void wsplit_all(WParams p) {
    int gi = blockIdx.x * 256 + threadIdx.x;
    #pragma unroll
    for (int s = 0; s < 10; s++) {
        int n = p.w[s].n;
        if (gi < n) {
            float v = p.w[s].s[gi];
            if (p.w[s].f16) {
                h16 hv = __float2half_rn(v);
                p.w[s].h[gi] = __half_as_ushort(hv);
                p.w[s].l[gi] = __half_as_ushort(__float2half_rn(v - __half2float(hv)));
            } else {
                bf16 hv = __float2bfloat16(v);
                p.w[s].h[gi] = __bfloat16_as_ushort(hv);
                p.w[s].l[gi] = __bfloat16_as_ushort(__float2bfloat16(v - __bfloat162float(hv)));
            }
            return;
        }
        gi -= n;
    }
}

// ================= attention =================
static DIB float wsum(float v) {
    #pragma unroll
    for (int o = 16; o > 0; o >>= 1) v += __shfl_xor_sync(0xffffffffu, v, o);
    return v;
}
static DIB float sigm(float x) { return 1.0f / (1.0f + __expf(-x)); }
static DIB float rd2(const bf16* h, const bf16* l, size_t i) {
    return __bfloat162float(h[i]) + __bfloat162float(l[i]);
}
static DIB void wr2(bf16* h, bf16* l, size_t i, float v) {
    bf16 x = __float2bfloat16(v);
    h[i] = x;
    l[i] = __float2bfloat16(v - __bfloat162float(x));
}

__global__ __launch_bounds__(128)
void attend_k(const bf16* __restrict__ eah, const bf16* __restrict__ eal,
              const float* __restrict__ gateb, const float* __restrict__ gatec,
              const h16* __restrict__ eb, const h16* __restrict__ ec,
              const float* __restrict__ Wab, const float* __restrict__ Wac,
              bf16* __restrict__ agh, bf16* __restrict__ agl)
{
    int gw = (blockIdx.x * 128 + threadIdx.x) >> 5;
    int lane = threadIdx.x & 31;
    int b = gw >> 12, n = gw & 4095;
    int h = n >> 6, w = n & 63;
    size_t nb = (size_t)b * 4096 + n;

    float ea[4], gb[4], gc[4];
    float pab = 0.f, pac = 0.f;
    #pragma unroll
    for (int j = 0; j < 4; j++) {
        int cc = lane + 32 * j;
        ea[j] = rd2(eah, eal, nb * 128 + cc);
        gb[j] = gateb[nb * 128 + cc];
        gc[j] = gatec[nb * 128 + cc];
        pab += Wab[cc] * ea[j];
        pac += Wac[cc] * ea[j];
    }
    float dab = wsum(pab), dac = wsum(pac);

    { // B branch (fp16 single plane)
        float ebf[4][4], lb[4];
        #pragma unroll
        for (int p = 0; p < 4; p++) {
            int kh = p >> 1, kw = p & 1;
            size_t base = ((size_t)b * 16384 + (size_t)(2*h + kh) * 128 + (2*w + kw)) * 128;
            float s = 0.f;
            #pragma unroll
            for (int j = 0; j < 4; j++) {
                int cc = lane + 32 * j;
                ebf[p][j] = __half2float(eb[base + cc]);
                s += Wab[128 + cc] * ebf[p][j];
            }
            lb[p] = fmaxf(dab + wsum(s), 0.0f);
        }
        float mx = fmaxf(fmaxf(lb[0], lb[1]), fmaxf(lb[2], lb[3]));
        float ss = 0.f;
        #pragma unroll
        for (int p = 0; p < 4; p++) { lb[p] = __expf(lb[p] - mx); ss += lb[p]; }
        float inv = 1.0f / ss;
        #pragma unroll
        for (int j = 0; j < 4; j++) {
            float a = 0.f;
            #pragma unroll
            for (int p = 0; p < 4; p++) a += ebf[p][j] * lb[p];
            wr2(agh, agl, nb * 384 + lane + 32 * j, sigm(a * inv * gb[j]));
        }
    }
    { // C branch (fp16 single plane)
        float ecf[16][4], lc[16];
        #pragma unroll
        for (int p = 0; p < 16; p++) {
            int kh = p >> 2, kw = p & 3;
            size_t base = ((size_t)b * 65536 + (size_t)(4*h + kh) * 256 + (4*w + kw)) * 128;
            float s = 0.f;
            #pragma unroll
            for (int j = 0; j < 4; j++) {
                int cc = lane + 32 * j;
                ecf[p][j] = __half2float(ec[base + cc]);
                s += Wac[128 + cc] * ecf[p][j];
            }
            lc[p] = fmaxf(dac + wsum(s), 0.0f);
        }
        float mx = lc[0];
        #pragma unroll
        for (int p = 1; p < 16; p++) mx = fmaxf(mx, lc[p]);
        float ss = 0.f;
        #pragma unroll
        for (int p = 0; p < 16; p++) { lc[p] = __expf(lc[p] - mx); ss += lc[p]; }
        float inv = 1.0f / ss;
        #pragma unroll
        for (int j = 0; j < 4; j++) {
            float a = 0.f;
            #pragma unroll
            for (int p = 0; p < 16; p++) a += ecf[p][j] * lc[p];
            wr2(agh, agl, nb * 384 + 128 + lane + 32 * j, sigm(a * inv * gc[j]));
        }
    }
    #pragma unroll
    for (int j = 0; j < 4; j++)
        wr2(agh, agl, nb * 384 + 256 + lane + 32 * j, sigm(ea[j]));
}

// ================= launch =================
static inline int imax(int a, int b) { return a > b ? a : b; }
static inline int fsz1(int K1, int O1M, int NG, int O2) {
    int O1T = O1M + NG * 128, WR = imax(O1T, O2);
    int staging_units = K1 * 68 * 2;
    int units = 2*64*(K1+8) + 2*(2*WR*40) + 2*64*(O1M+8);
    int with_staging = 2*64*(K1+8) + 2*WR*40 + staging_units;
    return imax(units, with_staging) * 2;
}
static inline int fsz0(int O1M, int NG, int O2) {
    int O1T = O1M + NG * 128, WR = imax(O1T, O2);
    int XPL = 64 * 40, WPL = WR * 40;
    int STG = 2 * XPL + 2 * WPL;
    return (2 * STG + 2 * 64 * (O1M + 8)) * 2;
}

extern "C" void kernel_launch(void* const* d_in, const int* in_sizes, int n_in,
                              void* d_out, int out_size)
{
    const float* va  = (const float*)d_in[0];
    const float* vb  = (const float*)d_in[1];
    const float* vc  = (const float*)d_in[2];
    const float* Wa1 = (const float*)d_in[3];
    const float* Wa2 = (const float*)d_in[4];
    const float* Wgb = (const float*)d_in[5];
    const float* Wgc = (const float*)d_in[6];
    const float* Wb1 = (const float*)d_in[7];
    const float* Wb2 = (const float*)d_in[8];
    const float* Wc1 = (const float*)d_in[9];
    const float* Wc2 = (const float*)d_in[10];
    const float* Wab = (const float*)d_in[11];
    const float* Wac = (const float*)d_in[12];
    const float* Wr1 = (const float*)d_in[13];
    const float* Wr2 = (const float*)d_in[14];
    float* out = (float*)d_out;

    bf16 *eah,*eal,*agh,*agl;
    h16  *eb,*ec, *Wb1h,*Wb1l,*Wb2h,*Wb2l, *Wc1h,*Wc1l,*Wc2h,*Wc2l;
    float *gb,*gc;
    bf16 *WAh,*WAl,*Wa2h,*Wa2l,*Wr1h,*Wr1l,*Wr2h,*Wr2l;
    cudaGetSymbolAddress((void**)&eah,g_eah); cudaGetSymbolAddress((void**)&eal,g_eal);
    cudaGetSymbolAddress((void**)&gb,g_gb);   cudaGetSymbolAddress((void**)&gc,g_gc);
    cudaGetSymbolAddress((void**)&eb,g_eb);   cudaGetSymbolAddress((void**)&ec,g_ec);
    cudaGetSymbolAddress((void**)&agh,g_agh); cudaGetSymbolAddress((void**)&agl,g_agl);
    cudaGetSymbolAddress((void**)&WAh,g_WAh); cudaGetSymbolAddress((void**)&WAl,g_WAl);
    cudaGetSymbolAddress((void**)&Wa2h,g_Wa2h); cudaGetSymbolAddress((void**)&Wa2l,g_Wa2l);
    cudaGetSymbolAddress((void**)&Wb1h,g_Wb1h); cudaGetSymbolAddress((void**)&Wb1l,g_Wb1l);
    cudaGetSymbolAddress((void**)&Wb2h,g_Wb2h); cudaGetSymbolAddress((void**)&Wb2l,g_Wb2l);
    cudaGetSymbolAddress((void**)&Wc1h,g_Wc1h); cudaGetSymbolAddress((void**)&Wc1l,g_Wc1l);
    cudaGetSymbolAddress((void**)&Wc2h,g_Wc2h); cudaGetSymbolAddress((void**)&Wc2l,g_Wc2l);
    cudaGetSymbolAddress((void**)&Wr1h,g_Wr1h); cudaGetSymbolAddress((void**)&Wr1l,g_Wr1l);
    cudaGetSymbolAddress((void**)&Wr2h,g_Wr2h); cudaGetSymbolAddress((void**)&Wr2l,g_Wr2l);

    int sA = fsz1(256, 128, 2, 128);
    int sR = fsz0(256, 0, 256);
    int sB = B_UNITS * 2;
    int sC = C_UNITS * 2;
    cudaFuncSetAttribute(fuse_k<256,128,2,128,1,0,1>, cudaFuncAttributeMaxDynamicSharedMemorySize, sA);
    cudaFuncSetAttribute(fuse_k<384,256,0,256,1,2,0>, cudaFuncAttributeMaxDynamicSharedMemorySize, sR);
    cudaFuncSetAttribute(fuseb_k, cudaFuncAttributeMaxDynamicSharedMemorySize, sB);
    cudaFuncSetAttribute(cpers_k, cudaFuncAttributeMaxDynamicSharedMemorySize, sC);

    WParams P;
    P.w[0] = {Wa1, (unsigned short*)WAh,           (unsigned short*)WAl,           32768, 0};
    P.w[1] = {Wgb, (unsigned short*)(WAh + 32768), (unsigned short*)(WAl + 32768), 32768, 0};
    P.w[2] = {Wgc, (unsigned short*)(WAh + 65536), (unsigned short*)(WAl + 65536), 32768, 0};
    P.w[3] = {Wa2, (unsigned short*)Wa2h, (unsigned short*)Wa2l, 16384, 0};
    P.w[4] = {Wb1, (unsigned short*)Wb1h, (unsigned short*)Wb1l, 16384, 1};
    P.w[5] = {Wb2, (unsigned short*)Wb2h, (unsigned short*)Wb2l, 16384, 1};
    P.w[6] = {Wc1, (unsigned short*)Wc1h, (unsigned short*)Wc1l, 8192,  1};
    P.w[7] = {Wc2, (unsigned short*)Wc2h, (unsigned short*)Wc2l, 16384, 1};
    P.w[8] = {Wr1, (unsigned short*)Wr1h, (unsigned short*)Wr1l, 98304, 0};
    P.w[9] = {Wr2, (unsigned short*)Wr2h, (unsigned short*)Wr2l, 65536, 0};
    wsplit_all<<<(335872 + 255) / 256, 256>>>(P);

    // a-stage (bf16 3-term)
    fuse_k<256,128,2,128,1,0,1><<<dim3(64, 1, NB), 256, sA>>>(
        va, nullptr, nullptr, WAh, WAl, Wa2h, Wa2l, gb, gc, eah, eal, nullptr, 4096);
    // b-stage (fp16 2-term)
    fuseb_k<<<dim3(256, 1, NB), 256, sB>>>(vb, Wb1h, Wb1l, Wb2h, Wb2l, eb);
    // c-stage (persistent, fp16 2-term)
    cpers_k<<<C_GRID, C_THREADS, sC>>>(vc, Wc1h, Wc1l, Wc2h, Wc2l, ec);

    attend_k<<<8192, 128>>>(eah, eal, gb, gc, eb, ec, Wab, Wac, agh, agl);

    // readout (bf16 3-term)
    fuse_k<384,256,0,256,1,2,0><<<dim3(64, 1, NB), 256, sR>>>(
        nullptr, agh, agl, Wr1h, Wr1l, Wr2h, Wr2l, nullptr, nullptr, nullptr, nullptr, out, 4096);
}

// round 17
// speedup vs baseline: 2.7862x; 1.1533x over previous
#include <cuda_runtime.h>
#include <cuda_bf16.h>
#include <cuda_fp16.h>
#include <cstdint>

using bf16 = __nv_bfloat16;
using h16  = __half;
#define DIB __device__ __forceinline__
#define NB 8

// ================= scratch (device globals) =================
__device__ __align__(16) bf16 g_eah[(size_t)NB*4096*128],  g_eal[(size_t)NB*4096*128];
__device__ __align__(16) float g_gb[(size_t)NB*4096*128],  g_gc[(size_t)NB*4096*128];
__device__ __align__(16) h16  g_eb [(size_t)NB*16384*128];
__device__ __align__(16) h16  g_ec [(size_t)NB*65536*128];
__device__ __align__(16) bf16 g_agh[(size_t)NB*4096*384],  g_agl[(size_t)NB*4096*384];
__device__ __align__(16) bf16 g_WAh[384*256],  g_WAl[384*256];   // Wa1|Wgb|Wgc stacked
__device__ __align__(16) bf16 g_Wa2h[128*128], g_Wa2l[128*128];
__device__ __align__(16) h16  g_Wb1h[128*128];
__device__ __align__(16) h16  g_Wb2h[128*128];
__device__ __align__(16) h16  g_Wc1h[128*64];
__device__ __align__(16) h16  g_Wc2h[128*128];
__device__ __align__(16) bf16 g_Wr1h[256*384], g_Wr1l[256*384];
__device__ __align__(16) bf16 g_Wr2h[256*256], g_Wr2l[256*256];

// ================= helpers =================
static DIB uint32_t smem_u32(const void* p) {
    uint32_t a;
    asm("{ .reg .u64 t; cvta.to.shared.u64 t, %1; cvt.u32.u64 %0, t; }" : "=r"(a) : "l"(p));
    return a;
}
static DIB void cpa16(uint32_t s, const void* g) {
    asm volatile("cp.async.ca.shared.global [%0],[%1],16;" :: "r"(s), "l"(g) : "memory");
}
#define CPA_COMMIT() asm volatile("cp.async.commit_group;" ::: "memory")
#define CPA_WAIT(N)  asm volatile("cp.async.wait_group " #N ";" ::: "memory")
static DIB void ldsm4(uint32_t* r, uint32_t a) {
    asm volatile("ldmatrix.sync.aligned.m8n8.x4.shared.b16 {%0,%1,%2,%3},[%4];"
        : "=r"(r[0]), "=r"(r[1]), "=r"(r[2]), "=r"(r[3]) : "r"(a));
}
static DIB void mma16816(float* d, const uint32_t* a, const uint32_t* b) {
    asm volatile(
        "mma.sync.aligned.m16n8k16.row.col.f32.bf16.bf16.f32 "
        "{%0,%1,%2,%3}, {%4,%5,%6,%7}, {%8,%9}, {%0,%1,%2,%3};"
        : "+f"(d[0]), "+f"(d[1]), "+f"(d[2]), "+f"(d[3])
        : "r"(a[0]), "r"(a[1]), "r"(a[2]), "r"(a[3]), "r"(b[0]), "r"(b[1]));
}
static DIB void mma16816h(float* d, const uint32_t* a, const uint32_t* b) {
    asm volatile(
        "mma.sync.aligned.m16n8k16.row.col.f32.f16.f16.f32 "
        "{%0,%1,%2,%3}, {%4,%5,%6,%7}, {%8,%9}, {%0,%1,%2,%3};"
        : "+f"(d[0]), "+f"(d[1]), "+f"(d[2]), "+f"(d[3])
        : "r"(a[0]), "r"(a[1]), "r"(a[2]), "r"(a[3]), "r"(b[0]), "r"(b[1]));
}
static DIB uint32_t pk(bf16 lo, bf16 hi) {
    return (uint32_t)__bfloat16_as_ushort(lo) | ((uint32_t)__bfloat16_as_ushort(hi) << 16);
}
static DIB uint32_t pkh2(float v0, float v1) {
    h16 a = __float2half_rn(v0), b = __float2half_rn(v1);
    return (uint32_t)__half_as_ushort(a) | ((uint32_t)__half_as_ushort(b) << 16);
}

// 3-term bf16 split: acc += Ah*(Bh+Bl) + Al*Bh
template<int STA, int STB, int MT, int NT, int CHT>
static DIB void mma_blk(float (&acc)[MT][NT][4], uint32_t aH, uint32_t aL,
                        uint32_t bH, uint32_t bL)
{
    #pragma unroll
    for (int ks = 0; ks < CHT; ks += 16) {
        uint32_t Ah[MT][4], Al[MT][4], Bh[NT/2][4], Bl[NT/2][4];
        #pragma unroll
        for (int mt = 0; mt < MT; mt++) {
            ldsm4(Ah[mt], aH + (uint32_t)(mt*16*STA + ks) * 2);
            ldsm4(Al[mt], aL + (uint32_t)(mt*16*STA + ks) * 2);
        }
        #pragma unroll
        for (int g = 0; g < NT/2; g++) {
            ldsm4(Bh[g], bH + (uint32_t)(g*16*STB + ks) * 2);
            ldsm4(Bl[g], bL + (uint32_t)(g*16*STB + ks) * 2);
        }
        #pragma unroll
        for (int nt = 0; nt < NT; nt++) {
            uint32_t bh[2] = {Bh[nt>>1][(nt&1)*2], Bh[nt>>1][(nt&1)*2+1]};
            uint32_t bl[2] = {Bl[nt>>1][(nt&1)*2], Bl[nt>>1][(nt&1)*2+1]};
            #pragma unroll
            for (int mt = 0; mt < MT; mt++) {
                mma16816(acc[mt][nt], Ah[mt], bh);
                mma16816(acc[mt][nt], Ah[mt], bl);
                mma16816(acc[mt][nt], Al[mt], bh);
            }
        }
    }
}

// single-plane fp16: acc += A*B
template<int STA, int STB, int MT, int NT, int CHT>
static DIB void mma_blk1(float (&acc)[MT][NT][4], uint32_t aH, uint32_t bH)
{
    #pragma unroll
    for (int ks = 0; ks < CHT; ks += 16) {
        uint32_t Ah[MT][4], Bh[NT/2][4];
        #pragma unroll
        for (int mt = 0; mt < MT; mt++)
            ldsm4(Ah[mt], aH + (uint32_t)(mt*16*STA + ks) * 2);
        #pragma unroll
        for (int g = 0; g < NT/2; g++)
            ldsm4(Bh[g], bH + (uint32_t)(g*16*STB + ks) * 2);
        #pragma unroll
        for (int nt = 0; nt < NT; nt++) {
            uint32_t bh[2] = {Bh[nt>>1][(nt&1)*2], Bh[nt>>1][(nt&1)*2+1]};
            #pragma unroll
            for (int mt = 0; mt < MT; mt++)
                mma16816h(acc[mt][nt], Ah[mt], bh);
        }
    }
}

// ================= unified fused 2-layer GEMM (a/readout; bf16 3-term) =================
template<int K1, int O1M, int NG, int O2, int OCC, int OUTM, int XMODE>
__global__ __launch_bounds__(256, OCC)
void fuse_k(const float* __restrict__ Xf,
            const bf16* __restrict__ Xh, const bf16* __restrict__ Xl,
            const bf16* __restrict__ W1h, const bf16* __restrict__ W1l,
            const bf16* __restrict__ W2h, const bf16* __restrict__ W2l,
            float* __restrict__ gate0, float* __restrict__ gate1,
            bf16* __restrict__ Oh, bf16* __restrict__ Ol, float* __restrict__ Of,
            int Mtot)
{
    constexpr int BM = 64, CH = 32, WST = 40;
    constexpr int O1T = O1M + NG * 128;
    constexpr int WR  = (O1T > O2) ? O1T : O2;
    constexpr int HST = O1M + 8;
    constexpr int WPL = WR * WST;
    constexpr int AST = K1 + 8;
    constexpr int APL = BM * AST;
    constexpr int XST = 40;
    constexpr int XPL = BM * XST;
    constexpr int STG  = (XMODE == 1) ? (2 * WPL) : (2 * XPL + 2 * WPL);
    constexpr int SOFF = (XMODE == 1) ? (2 * APL) : 0;
    constexpr int WIN  = (XMODE == 1) ? 0 : (2 * XPL);
    constexpr int HOFFn = SOFF + 2 * STG;
    constexpr int NC1 = K1 / CH, NC2 = O1M / CH;
    constexpr int NT1 = O1T / 32, NT2 = O2 / 32;

    extern __shared__ bf16 smm[];
    const int tid = threadIdx.x, lane = tid & 31, warp = tid >> 5;
    const int gid = lane >> 2, tq = (lane & 3) * 2;
    const int wm  = (warp >> 2) * 32;
    const int wn1 = (warp & 3) * (NT1 * 8);
    const int wn2 = (warp & 3) * (NT2 * 8);
    const int b = blockIdx.z, m0 = blockIdx.x * BM;
    const uint32_t su = smem_u32(smm);

    const int arow = (lane & 7) + ((lane >> 3) & 1) * 8;
    const int acol = (lane >> 4) * 8;
    const int brow = (lane & 7) + (lane >> 4) * 8;
    const int bcol = ((lane >> 3) & 1) * 8;

    auto load1 = [&](int kc, int s) {
        uint32_t wb = su + (uint32_t)(SOFF + s * STG + WIN) * 2;
        if constexpr (XMODE == 0) {
            uint32_t base = su + (uint32_t)(s * STG) * 2;
            const bf16* Xhb = Xh + ((size_t)b * Mtot + m0) * K1;
            const bf16* Xlb = Xl + ((size_t)b * Mtot + m0) * K1;
            #pragma unroll
            for (int i = tid; i < BM * 4; i += 256) {
                int r = i >> 2, c = (i & 3) * 8;
                cpa16(base + (uint32_t)(r * XST + c) * 2,       Xhb + (size_t)r * K1 + kc + c);
                cpa16(base + (uint32_t)(XPL + r * XST + c) * 2, Xlb + (size_t)r * K1 + kc + c);
            }
        }
        #pragma unroll
        for (int i = tid; i < O1T * 4; i += 256) {
            int r = i >> 2, c = (i & 3) * 8;
            cpa16(wb + (uint32_t)(r * WST + c) * 2,       W1h + (size_t)r * K1 + kc + c);
            cpa16(wb + (uint32_t)(WPL + r * WST + c) * 2, W1l + (size_t)r * K1 + kc + c);
        }
        CPA_COMMIT();
    };
    auto load2 = [&](int kc, int s) {
        uint32_t wb = su + (uint32_t)(SOFF + s * STG + WIN) * 2;
        #pragma unroll
        for (int i = tid; i < O2 * 4; i += 256) {
            int r = i >> 2, c = (i & 3) * 8;
            cpa16(wb + (uint32_t)(r * WST + c) * 2,       W2h + (size_t)r * O1M + kc + c);
            cpa16(wb + (uint32_t)(WPL + r * WST + c) * 2, W2l + (size_t)r * O1M + kc + c);
        }
        CPA_COMMIT();
    };

    if constexpr (XMODE == 1) {
        constexpr int SST_OFF = SOFF + STG;
        uint32_t sbase = su + (uint32_t)SST_OFF * 2;
        const float* Xg = Xf + (size_t)b * K1 * Mtot + m0;
        #pragma unroll
        for (int i = tid; i < K1 * 16; i += 256) {
            int r = i >> 4, c4 = (i & 15) * 4;
            cpa16(sbase + (uint32_t)(r * 68 + c4) * 4, Xg + (size_t)r * Mtot + c4);
        }
        CPA_COMMIT();
        load1(0, 0);
        CPA_WAIT(1);
        __syncthreads();
        const float* stg = (const float*)(smm + SST_OFF);
        int m = tid & 63, k0 = (tid >> 6) * (K1 / 4);
        #pragma unroll
        for (int j = 0; j < K1 / 4; j += 2) {
            int k = k0 + j;
            float v0 = stg[k * 68 + m], v1 = stg[(k + 1) * 68 + m];
            bf16 h0 = __float2bfloat16(v0), h1 = __float2bfloat16(v1);
            bf16 l0 = __float2bfloat16(v0 - __bfloat162float(h0));
            bf16 l1 = __float2bfloat16(v1 - __bfloat162float(h1));
            *(uint32_t*)&smm[(size_t)m * AST + k]       = pk(h0, h1);
            *(uint32_t*)&smm[(size_t)APL + m * AST + k] = pk(l0, l1);
        }
        __syncthreads();
    } else {
        load1(0, 0);
    }

    float acc1[2][NT1][4];
    #pragma unroll
    for (int mt = 0; mt < 2; mt++)
        #pragma unroll
        for (int nt = 0; nt < NT1; nt++)
            #pragma unroll
            for (int q = 0; q < 4; q++) acc1[mt][nt][q] = 0.f;

    for (int ki = 0; ki < NC1; ki++) {
        if (ki + 1 < NC1) { load1((ki + 1) * CH, (ki + 1) & 1); CPA_WAIT(1); }
        else              { CPA_WAIT(0); }
        __syncthreads();
        uint32_t aH, aL;
        if constexpr (XMODE == 1) {
            aH = su + (uint32_t)((wm + arow) * AST + acol + ki * CH) * 2;
            aL = aH + (uint32_t)APL * 2;
        } else {
            uint32_t base = su + (uint32_t)((ki & 1) * STG) * 2;
            aH = base + (uint32_t)((wm + arow) * XST + acol) * 2;
            aL = aH + (uint32_t)XPL * 2;
        }
        uint32_t wb = su + (uint32_t)(SOFF + (ki & 1) * STG + WIN) * 2;
        uint32_t bH = wb + (uint32_t)((wn1 + brow) * WST + bcol) * 2;
        uint32_t bL = bH + (uint32_t)WPL * 2;
        mma_blk<(XMODE == 1 ? AST : XST), WST, 2, NT1, CH>(acc1, aH, aL, bH, bL);
        __syncthreads();
    }

    load2(0, 0);

    #pragma unroll
    for (int mt = 0; mt < 2; mt++)
        #pragma unroll
        for (int h2 = 0; h2 < 2; h2++) {
            int ml = wm + mt * 16 + gid + h2 * 8;
            #pragma unroll
            for (int nt = 0; nt < NT1; nt++) {
                int oc = wn1 + nt * 8 + tq;
                float v0 = acc1[mt][nt][h2 * 2], v1 = acc1[mt][nt][h2 * 2 + 1];
                if (NG == 0 || oc < O1M) {
                    v0 = fmaxf(v0, 0.f); v1 = fmaxf(v1, 0.f);
                    bf16 h0 = __float2bfloat16(v0), h1 = __float2bfloat16(v1);
                    bf16 l0 = __float2bfloat16(v0 - __bfloat162float(h0));
                    bf16 l1 = __float2bfloat16(v1 - __bfloat162float(h1));
                    *(uint32_t*)&smm[HOFFn + ml * HST + oc]            = pk(h0, h1);
                    *(uint32_t*)&smm[HOFFn + BM * HST + ml * HST + oc] = pk(l0, l1);
                } else {
                    int g = (oc - O1M) >> 7;
                    float* gp = (g ? gate1 : gate0) + ((size_t)b * Mtot + m0 + ml) * 128 + (oc & 127);
                    *(float2*)gp = make_float2(1.0f / (1.0f + __expf(v0)),
                                               1.0f / (1.0f + __expf(v1)));
                }
            }
        }
    __syncthreads();

    float acc2[2][NT2][4];
    #pragma unroll
    for (int mt = 0; mt < 2; mt++)
        #pragma unroll
        for (int nt = 0; nt < NT2; nt++)
            #pragma unroll
            for (int q = 0; q < 4; q++) acc2[mt][nt][q] = 0.f;

    for (int ki = 0; ki < NC2; ki++) {
        if (ki + 1 < NC2) { load2((ki + 1) * CH, (ki + 1) & 1); CPA_WAIT(1); }
        else              { CPA_WAIT(0); }
        __syncthreads();
        uint32_t aH = su + (uint32_t)(HOFFn + (wm + arow) * HST + acol + ki * CH) * 2;
        uint32_t aL = aH + (uint32_t)(BM * HST) * 2;
        uint32_t wb = su + (uint32_t)(SOFF + (ki & 1) * STG + WIN) * 2;
        uint32_t bH = wb + (uint32_t)((wn2 + brow) * WST + bcol) * 2;
        uint32_t bL = bH + (uint32_t)WPL * 2;
        mma_blk<HST, WST, 2, NT2, CH>(acc2, aH, aL, bH, bL);
        __syncthreads();
    }

    #pragma unroll
    for (int mt = 0; mt < 2; mt++)
        #pragma unroll
        for (int h2 = 0; h2 < 2; h2++) {
            int m = m0 + wm + mt * 16 + gid + h2 * 8;
            #pragma unroll
            for (int nt = 0; nt < NT2; nt++) {
                int oc = wn2 + nt * 8 + tq;
                float v0 = acc2[mt][nt][h2 * 2], v1 = acc2[mt][nt][h2 * 2 + 1];
                if (OUTM == 0) {
                    bf16 h0 = __float2bfloat16(v0), h1 = __float2bfloat16(v1);
                    bf16 l0 = __float2bfloat16(v0 - __bfloat162float(h0));
                    bf16 l1 = __float2bfloat16(v1 - __bfloat162float(h1));
                    size_t go = ((size_t)b * Mtot + m) * O2 + oc;
                    *(uint32_t*)(Oh + go) = pk(h0, h1);
                    *(uint32_t*)(Ol + go) = pk(l0, l1);
                } else {
                    Of[((size_t)b * O2 + oc)     * Mtot + m] = v0;
                    Of[((size_t)b * O2 + oc + 1) * Mtot + m] = v1;
                }
            }
        }
}

// ================= b-stage fused kernel (fp16 single-plane W) =================
#define B_AST 136
#define B_APL (64 * B_AST)            // 8704
#define B_WPL (128 * 40)              // 5120 (single plane)
#define B_STG B_WPL
#define B_SOFF B_APL                  // 8704
#define B_SST  (B_SOFF + 2 * B_STG)   // 18944 (staging overlays H region)
#define B_HOFF (B_SOFF + 2 * B_STG)   // 18944
#define B_UNITS 36352                 // max(18944+8704, 18944+17408) = 36352 -> 72704 B

__global__ __launch_bounds__(256, 2)
void fuseb_k(const float* __restrict__ Xf,
             const h16* __restrict__ W1h, const h16* __restrict__ W2h,
             h16* __restrict__ Oc)
{
    constexpr int Mtot = 16384;
    extern __shared__ h16 smh[];
    const int tid = threadIdx.x, lane = tid & 31, warp = tid >> 5;
    const int gid = lane >> 2, tq = (lane & 3) * 2;
    const int wm = (warp >> 2) * 32, wn = (warp & 3) * 32;
    const int b = blockIdx.z, m0 = blockIdx.x * 64;
    const uint32_t su = smem_u32(smh);

    const int arow = (lane & 7) + ((lane >> 3) & 1) * 8;
    const int acol = (lane >> 4) * 8;
    const int brow = (lane & 7) + (lane >> 4) * 8;
    const int bcol = ((lane >> 3) & 1) * 8;

    auto load1 = [&](int kc, int s) {
        uint32_t wb = su + (uint32_t)(B_SOFF + s * B_STG) * 2;
        #pragma unroll
        for (int i = tid; i < 128 * 4; i += 256) {
            int r = i >> 2, c = (i & 3) * 8;
            cpa16(wb + (uint32_t)(r * 40 + c) * 2, W1h + (size_t)r * 128 + kc + c);
        }
        CPA_COMMIT();
    };
    auto load2 = [&](int kc, int s) {
        uint32_t wb = su + (uint32_t)(B_SOFF + s * B_STG) * 2;
        #pragma unroll
        for (int i = tid; i < 128 * 4; i += 256) {
            int r = i >> 2, c = (i & 3) * 8;
            cpa16(wb + (uint32_t)(r * 40 + c) * 2, W2h + (size_t)r * 128 + kc + c);
        }
        CPA_COMMIT();
    };

    // phase 0: fp32 X ingest -> fp16 A plane
    {
        uint32_t sbase = su + (uint32_t)B_SST * 2;
        const float* Xg = Xf + (size_t)b * 128 * Mtot + m0;
        #pragma unroll
        for (int i = tid; i < 128 * 16; i += 256) {
            int r = i >> 4, c4 = (i & 15) * 4;
            cpa16(sbase + (uint32_t)(r * 68 + c4) * 4, Xg + (size_t)r * Mtot + c4);
        }
        CPA_COMMIT();
        load1(0, 0);
        CPA_WAIT(1);
        __syncthreads();
        const float* stg = (const float*)(smh + B_SST);
        int m = tid & 63, k0 = (tid >> 6) * 32;
        #pragma unroll
        for (int j = 0; j < 32; j += 2) {
            int k = k0 + j;
            float v0 = stg[k * 68 + m], v1 = stg[(k + 1) * 68 + m];
            *(uint32_t*)&smh[m * B_AST + k] = pkh2(v0, v1);
        }
        __syncthreads();
    }

    // GEMM1: K=128
    float acc1[2][4][4];
    #pragma unroll
    for (int mt = 0; mt < 2; mt++)
        #pragma unroll
        for (int nt = 0; nt < 4; nt++)
            #pragma unroll
            for (int q = 0; q < 4; q++) acc1[mt][nt][q] = 0.f;

    for (int ki = 0; ki < 4; ki++) {
        if (ki + 1 < 4) { load1((ki + 1) * 32, (ki + 1) & 1); CPA_WAIT(1); }
        else            { CPA_WAIT(0); }
        __syncthreads();
        uint32_t aH = su + (uint32_t)((wm + arow) * B_AST + acol + ki * 32) * 2;
        uint32_t wb = su + (uint32_t)(B_SOFF + (ki & 1) * B_STG) * 2;
        uint32_t bH = wb + (uint32_t)((wn + brow) * 40 + bcol) * 2;
        mma_blk1<B_AST, 40, 2, 4, 32>(acc1, aH, bH);
        __syncthreads();
    }

    load2(0, 0);

    // relu -> h fp16 plane
    #pragma unroll
    for (int mt = 0; mt < 2; mt++)
        #pragma unroll
        for (int h2 = 0; h2 < 2; h2++) {
            int ml = wm + mt * 16 + gid + h2 * 8;
            #pragma unroll
            for (int nt = 0; nt < 4; nt++) {
                int oc = wn + nt * 8 + tq;
                float v0 = fmaxf(acc1[mt][nt][h2 * 2],     0.f);
                float v1 = fmaxf(acc1[mt][nt][h2 * 2 + 1], 0.f);
                *(uint32_t*)&smh[B_HOFF + ml * B_AST + oc] = pkh2(v0, v1);
            }
        }
    __syncthreads();

    // GEMM2: K=128
    float acc2[2][4][4];
    #pragma unroll
    for (int mt = 0; mt < 2; mt++)
        #pragma unroll
        for (int nt = 0; nt < 4; nt++)
            #pragma unroll
            for (int q = 0; q < 4; q++) acc2[mt][nt][q] = 0.f;

    for (int ki = 0; ki < 4; ki++) {
        if (ki + 1 < 4) { load2((ki + 1) * 32, (ki + 1) & 1); CPA_WAIT(1); }
        else            { CPA_WAIT(0); }
        __syncthreads();
        uint32_t aH = su + (uint32_t)(B_HOFF + (wm + arow) * B_AST + acol + ki * 32) * 2;
        uint32_t wb = su + (uint32_t)(B_SOFF + (ki & 1) * B_STG) * 2;
        uint32_t bH = wb + (uint32_t)((wn + brow) * 40 + bcol) * 2;
        mma_blk1<B_AST, 40, 2, 4, 32>(acc2, aH, bH);
        __syncthreads();
    }

    // output (fp16 single plane)
    #pragma unroll
    for (int mt = 0; mt < 2; mt++)
        #pragma unroll
        for (int h2 = 0; h2 < 2; h2++) {
            int m = m0 + wm + mt * 16 + gid + h2 * 8;
            #pragma unroll
            for (int nt = 0; nt < 4; nt++) {
                int oc = wn + nt * 8 + tq;
                size_t go = ((size_t)b * Mtot + m) * 128 + oc;
                *(uint32_t*)(Oc + go) = pkh2(acc2[mt][nt][h2 * 2], acc2[mt][nt][h2 * 2 + 1]);
            }
        }
}

// ================= persistent-weight c-stage (fp16 single-plane W, BM=128) =================
#define C_TILES 4096
#define C_GRID  1024
#define C_THREADS 512
#define C_W1  0          // 128 x 72
#define C_W2  9216       // 128 x 136
#define C_A   26624      // 128 x 72
#define C_H   35840      // 128 x 136
#define C_STGO 53248     // 2 x 16384 fp32 staging (64k x 128m)
#define C_UNITS 86016    // 172032 bytes

__global__ __launch_bounds__(C_THREADS, 1)
void cpers_k(const float* __restrict__ Xf,
             const h16* __restrict__ W1h, const h16* __restrict__ W2h,
             h16* __restrict__ Oc)
{
    extern __shared__ h16 smh[];
    const int tid = threadIdx.x, lane = tid & 31, warp = tid >> 5;
    const int gid = lane >> 2, tq = (lane & 3) * 2;
    const int wm = (warp >> 2) * 32, wn = (warp & 3) * 32;
    const uint32_t su = smem_u32(smh);

    const int arow = (lane & 7) + ((lane >> 3) & 1) * 8;
    const int acol = (lane >> 4) * 8;
    const int brow = (lane & 7) + (lane >> 4) * 8;
    const int bcol = ((lane >> 3) & 1) * 8;

    #pragma unroll
    for (int i = tid; i < 128 * 8; i += C_THREADS) {
        int r = i >> 3, c = (i & 7) * 8;
        cpa16(su + (uint32_t)(C_W1 + r * 72 + c) * 2, W1h + (size_t)r * 64 + c);
    }
    #pragma unroll
    for (int i = tid; i < 128 * 16; i += C_THREADS) {
        int r = i >> 4, c = (i & 15) * 8;
        cpa16(su + (uint32_t)(C_W2 + r * 136 + c) * 2, W2h + (size_t)r * 128 + c);
    }
    CPA_COMMIT();

    auto stage = [&](int t, int s) {
        int b = t >> 9, mi = (t & 511) << 7;
        const float* Xg = Xf + (size_t)b * 64 * 65536 + mi;
        uint32_t sbase = su + (uint32_t)(C_STGO + s * 16384) * 2;
        #pragma unroll
        for (int i = tid; i < 64 * 32; i += C_THREADS) {
            int r = i >> 5, c4 = (i & 31) * 4;
            cpa16(sbase + (uint32_t)(r * 128 + c4) * 4, Xg + (size_t)r * 65536 + c4);
        }
        CPA_COMMIT();
    };

    stage(blockIdx.x, 0);
    CPA_WAIT(0);
    __syncthreads();

    int cur = 0;
    for (int t = blockIdx.x, it = 0; t < C_TILES; t += C_GRID, it++) {
        if (it > 0) { CPA_WAIT(0); __syncthreads(); }

        {
            const float* stg = (const float*)(smh + C_STGO + cur * 16384);
            int m = tid & 127, k0 = (tid >> 7) * 16;
            #pragma unroll
            for (int j = 0; j < 16; j += 2) {
                int k = k0 + j;
                float v0 = stg[k * 128 + m], v1 = stg[(k + 1) * 128 + m];
                *(uint32_t*)&smh[C_A + m * 72 + k] = pkh2(v0, v1);
            }
        }
        __syncthreads();

        if (t + C_GRID < C_TILES) stage(t + C_GRID, cur ^ 1);

        float acc1[2][4][4];
        #pragma unroll
        for (int mt = 0; mt < 2; mt++)
            #pragma unroll
            for (int nt = 0; nt < 4; nt++)
                #pragma unroll
                for (int q = 0; q < 4; q++) acc1[mt][nt][q] = 0.f;
        {
            uint32_t aH = su + (uint32_t)(C_A + (wm + arow) * 72 + acol) * 2;
            uint32_t bH = su + (uint32_t)(C_W1 + (wn + brow) * 72 + bcol) * 2;
            mma_blk1<72, 72, 2, 4, 64>(acc1, aH, bH);
        }

        #pragma unroll
        for (int mt = 0; mt < 2; mt++)
            #pragma unroll
            for (int h2 = 0; h2 < 2; h2++) {
                int ml = wm + mt * 16 + gid + h2 * 8;
                #pragma unroll
                for (int nt = 0; nt < 4; nt++) {
                    int oc = wn + nt * 8 + tq;
                    float v0 = fmaxf(acc1[mt][nt][h2 * 2],     0.f);
                    float v1 = fmaxf(acc1[mt][nt][h2 * 2 + 1], 0.f);
                    *(uint32_t*)&smh[C_H + ml * 136 + oc] = pkh2(v0, v1);
                }
            }
        __syncthreads();

        float acc2[2][4][4];
        #pragma unroll
        for (int mt = 0; mt < 2; mt++)
            #pragma unroll
            for (int nt = 0; nt < 4; nt++)
                #pragma unroll
                for (int q = 0; q < 4; q++) acc2[mt][nt][q] = 0.f;
        {
            uint32_t aH = su + (uint32_t)(C_H + (wm + arow) * 136 + acol) * 2;
            uint32_t bH = su + (uint32_t)(C_W2 + (wn + brow) * 136 + bcol) * 2;
            mma_blk1<136, 136, 2, 4, 128>(acc2, aH, bH);
        }

        {
            int b = t >> 9, mi = (t & 511) << 7;
            #pragma unroll
            for (int mt = 0; mt < 2; mt++)
                #pragma unroll
                for (int h2 = 0; h2 < 2; h2++) {
                    int m = mi + wm + mt * 16 + gid + h2 * 8;
                    #pragma unroll
                    for (int nt = 0; nt < 4; nt++) {
                        int oc = wn + nt * 8 + tq;
                        size_t go = ((size_t)b * 65536 + m) * 128 + oc;
                        *(uint32_t*)(Oc + go) = pkh2(acc2[mt][nt][h2 * 2],
                                                     acc2[mt][nt][h2 * 2 + 1]);
                    }
                }
        }
        cur ^= 1;
    }
}

// ================= merged weight split (typed) =================
struct WSeg { const float* s; unsigned short* h; unsigned short* l; int n; int f16; };
struct WParams { WSeg w[10]; };

__global__ __launch_bounds__(256)
void wsplit_all(WParams p) {
    int gi = blockIdx.x * 256 + threadIdx.x;
    #pragma unroll
    for (int s = 0; s < 10; s++) {
        int n = p.w[s].n;
        if (gi < n) {
            float v = p.w[s].s[gi];
            if (p.w[s].f16) {
                p.w[s].h[gi] = __half_as_ushort(__float2half_rn(v));
            } else {
                bf16 hv = __float2bfloat16(v);
                p.w[s].h[gi] = __bfloat16_as_ushort(hv);
                p.w[s].l[gi] = __bfloat16_as_ushort(__float2bfloat16(v - __bfloat162float(hv)));
            }
            return;
        }
        gi -= n;
    }
}

// ================= attention =================
static DIB float wsum(float v) {
    #pragma unroll
    for (int o = 16; o > 0; o >>= 1) v += __shfl_xor_sync(0xffffffffu, v, o);
    return v;
}
static DIB float sigm(float x) { return 1.0f / (1.0f + __expf(-x)); }
static DIB float rd2(const bf16* h, const bf16* l, size_t i) {
    return __bfloat162float(h[i]) + __bfloat162float(l[i]);
}
static DIB void wr2(bf16* h, bf16* l, size_t i, float v) {
    bf16 x = __float2bfloat16(v);
    h[i] = x;
    l[i] = __float2bfloat16(v - __bfloat162float(x));
}

__global__ __launch_bounds__(128)
void attend_k(const bf16* __restrict__ eah, const bf16* __restrict__ eal,
              const float* __restrict__ gateb, const float* __restrict__ gatec,
              const h16* __restrict__ eb, const h16* __restrict__ ec,
              const float* __restrict__ Wab, const float* __restrict__ Wac,
              bf16* __restrict__ agh, bf16* __restrict__ agl)
{
    int gw = (blockIdx.x * 128 + threadIdx.x) >> 5;
    int lane = threadIdx.x & 31;
    int b = gw >> 12, n = gw & 4095;
    int h = n >> 6, w = n & 63;
    size_t nb = (size_t)b * 4096 + n;

    float ea[4], gb[4], gc[4];
    float pab = 0.f, pac = 0.f;
    #pragma unroll
    for (int j = 0; j < 4; j++) {
        int cc = lane + 32 * j;
        ea[j] = rd2(eah, eal, nb * 128 + cc);
        gb[j] = gateb[nb * 128 + cc];
        gc[j] = gatec[nb * 128 + cc];
        pab += Wab[cc] * ea[j];
        pac += Wac[cc] * ea[j];
    }
    float dab = wsum(pab), dac = wsum(pac);

    { // B branch (fp16 single plane)
        float ebf[4][4], lb[4];
        #pragma unroll
        for (int p = 0; p < 4; p++) {
            int kh = p >> 1, kw = p & 1;
            size_t base = ((size_t)b * 16384 + (size_t)(2*h + kh) * 128 + (2*w + kw)) * 128;
            float s = 0.f;
            #pragma unroll
            for (int j = 0; j < 4; j++) {
                int cc = lane + 32 * j;
                ebf[p][j] = __half2float(eb[base + cc]);
                s += Wab[128 + cc] * ebf[p][j];
            }
            lb[p] = fmaxf(dab + wsum(s), 0.0f);
        }
        float mx = fmaxf(fmaxf(lb[0], lb[1]), fmaxf(lb[2], lb[3]));
        float ss = 0.f;
        #pragma unroll
        for (int p = 0; p < 4; p++) { lb[p] = __expf(lb[p] - mx); ss += lb[p]; }
        float inv = 1.0f / ss;
        #pragma unroll
        for (int j = 0; j < 4; j++) {
            float a = 0.f;
            #pragma unroll
            for (int p = 0; p < 4; p++) a += ebf[p][j] * lb[p];
            wr2(agh, agl, nb * 384 + lane + 32 * j, sigm(a * inv * gb[j]));
        }
    }
    { // C branch (fp16 single plane)
        float ecf[16][4], lc[16];
        #pragma unroll
        for (int p = 0; p < 16; p++) {
            int kh = p >> 2, kw = p & 3;
            size_t base = ((size_t)b * 65536 + (size_t)(4*h + kh) * 256 + (4*w + kw)) * 128;
            float s = 0.f;
            #pragma unroll
            for (int j = 0; j < 4; j++) {
                int cc = lane + 32 * j;
                ecf[p][j] = __half2float(ec[base + cc]);
                s += Wac[128 + cc] * ecf[p][j];
            }
            lc[p] = fmaxf(dac + wsum(s), 0.0f);
        }
        float mx = lc[0];
        #pragma unroll
        for (int p = 1; p < 16; p++) mx = fmaxf(mx, lc[p]);
        float ss = 0.f;
        #pragma unroll
        for (int p = 0; p < 16; p++) { lc[p] = __expf(lc[p] - mx); ss += lc[p]; }
        float inv = 1.0f / ss;
        #pragma unroll
        for (int j = 0; j < 4; j++) {
            float a = 0.f;
            #pragma unroll
            for (int p = 0; p < 16; p++) a += ecf[p][j] * lc[p];
            wr2(agh, agl, nb * 384 + 128 + lane + 32 * j, sigm(a * inv * gc[j]));
        }
    }
    #pragma unroll
    for (int j = 0; j < 4; j++)
        wr2(agh, agl, nb * 384 + 256 + lane + 32 * j, sigm(ea[j]));
}

// ================= launch =================
static inline int imax(int a, int b) { return a > b ? a : b; }
static inline int fsz1(int K1, int O1M, int NG, int O2) {
    int O1T = O1M + NG * 128, WR = imax(O1T, O2);
    int staging_units = K1 * 68 * 2;
    int units = 2*64*(K1+8) + 2*(2*WR*40) + 2*64*(O1M+8);
    int with_staging = 2*64*(K1+8) + 2*WR*40 + staging_units;
    return imax(units, with_staging) * 2;
}
static inline int fsz0(int O1M, int NG, int O2) {
    int O1T = O1M + NG * 128, WR = imax(O1T, O2);
    int XPL = 64 * 40, WPL = WR * 40;
    int STG = 2 * XPL + 2 * WPL;
    return (2 * STG + 2 * 64 * (O1M + 8)) * 2;
}

extern "C" void kernel_launch(void* const* d_in, const int* in_sizes, int n_in,
                              void* d_out, int out_size)
{
    const float* va  = (const float*)d_in[0];
    const float* vb  = (const float*)d_in[1];
    const float* vc  = (const float*)d_in[2];
    const float* Wa1 = (const float*)d_in[3];
    const float* Wa2 = (const float*)d_in[4];
    const float* Wgb = (const float*)d_in[5];
    const float* Wgc = (const float*)d_in[6];
    const float* Wb1 = (const float*)d_in[7];
    const float* Wb2 = (const float*)d_in[8];
    const float* Wc1 = (const float*)d_in[9];
    const float* Wc2 = (const float*)d_in[10];
    const float* Wab = (const float*)d_in[11];
    const float* Wac = (const float*)d_in[12];
    const float* Wr1 = (const float*)d_in[13];
    const float* Wr2 = (const float*)d_in[14];
    float* out = (float*)d_out;

    bf16 *eah,*eal,*agh,*agl;
    h16  *eb,*ec, *Wb1h,*Wb2h, *Wc1h,*Wc2h;
    float *gb,*gc;
    bf16 *WAh,*WAl,*Wa2h,*Wa2l,*Wr1h,*Wr1l,*Wr2h,*Wr2l;
    cudaGetSymbolAddress((void**)&eah,g_eah); cudaGetSymbolAddress((void**)&eal,g_eal);
    cudaGetSymbolAddress((void**)&gb,g_gb);   cudaGetSymbolAddress((void**)&gc,g_gc);
    cudaGetSymbolAddress((void**)&eb,g_eb);   cudaGetSymbolAddress((void**)&ec,g_ec);
    cudaGetSymbolAddress((void**)&agh,g_agh); cudaGetSymbolAddress((void**)&agl,g_agl);
    cudaGetSymbolAddress((void**)&WAh,g_WAh); cudaGetSymbolAddress((void**)&WAl,g_WAl);
    cudaGetSymbolAddress((void**)&Wa2h,g_Wa2h); cudaGetSymbolAddress((void**)&Wa2l,g_Wa2l);
    cudaGetSymbolAddress((void**)&Wb1h,g_Wb1h); cudaGetSymbolAddress((void**)&Wb2h,g_Wb2h);
    cudaGetSymbolAddress((void**)&Wc1h,g_Wc1h); cudaGetSymbolAddress((void**)&Wc2h,g_Wc2h);
    cudaGetSymbolAddress((void**)&Wr1h,g_Wr1h); cudaGetSymbolAddress((void**)&Wr1l,g_Wr1l);
    cudaGetSymbolAddress((void**)&Wr2h,g_Wr2h); cudaGetSymbolAddress((void**)&Wr2l,g_Wr2l);

    int sA = fsz1(256, 128, 2, 128);
    int sR = fsz0(256, 0, 256);
    int sB = B_UNITS * 2;
    int sC = C_UNITS * 2;
    cudaFuncSetAttribute(fuse_k<256,128,2,128,1,0,1>, cudaFuncAttributeMaxDynamicSharedMemorySize, sA);
    cudaFuncSetAttribute(fuse_k<384,256,0,256,1,2,0>, cudaFuncAttributeMaxDynamicSharedMemorySize, sR);
    cudaFuncSetAttribute(fuseb_k, cudaFuncAttributeMaxDynamicSharedMemorySize, sB);
    cudaFuncSetAttribute(cpers_k, cudaFuncAttributeMaxDynamicSharedMemorySize, sC);

    WParams P;
    P.w[0] = {Wa1, (unsigned short*)WAh,           (unsigned short*)WAl,           32768, 0};
    P.w[1] = {Wgb, (unsigned short*)(WAh + 32768), (unsigned short*)(WAl + 32768), 32768, 0};
    P.w[2] = {Wgc, (unsigned short*)(WAh + 65536), (unsigned short*)(WAl + 65536), 32768, 0};
    P.w[3] = {Wa2, (unsigned short*)Wa2h, (unsigned short*)Wa2l, 16384, 0};
    P.w[4] = {Wb1, (unsigned short*)Wb1h, nullptr, 16384, 1};
    P.w[5] = {Wb2, (unsigned short*)Wb2h, nullptr, 16384, 1};
    P.w[6] = {Wc1, (unsigned short*)Wc1h, nullptr, 8192,  1};
    P.w[7] = {Wc2, (unsigned short*)Wc2h, nullptr, 16384, 1};
    P.w[8] = {Wr1, (unsigned short*)Wr1h, (unsigned short*)Wr1l, 98304, 0};
    P.w[9] = {Wr2, (unsigned short*)Wr2h, (unsigned short*)Wr2l, 65536, 0};
    wsplit_all<<<(335872 + 255) / 256, 256>>>(P);

    // a-stage (bf16 3-term)
    fuse_k<256,128,2,128,1,0,1><<<dim3(64, 1, NB), 256, sA>>>(
        va, nullptr, nullptr, WAh, WAl, Wa2h, Wa2l, gb, gc, eah, eal, nullptr, 4096);
    // b-stage (fp16 single-plane W)
    fuseb_k<<<dim3(256, 1, NB), 256, sB>>>(vb, Wb1h, Wb2h, eb);
    // c-stage (persistent, fp16 single-plane W)
    cpers_k<<<C_GRID, C_THREADS, sC>>>(vc, Wc1h, Wc2h, ec);

    attend_k<<<8192, 128>>>(eah, eal, gb, gc, eb, ec, Wab, Wac, agh, agl);

    // readout (bf16 3-term)
    fuse_k<384,256,0,256,1,2,0><<<dim3(64, 1, NB), 256, sR>>>(
        nullptr, agh, agl, Wr1h, Wr1l, Wr2h, Wr2l, nullptr, nullptr, nullptr, nullptr, out, 4096);
}